// round 11
// baseline (speedup 1.0000x reference)
#include <cuda_runtime.h>
#include <cuda_bf16.h>
#include <cstdint>
#include <math.h>

#define BBv 2
#define Tv 2048
#define Mv 512
#define Cv 512
#define Hv 8
#define Dv 64
#define BHv 16
#define SCL 0.125f
typedef __nv_bfloat16 bf;

// ---------- bf16 pair pool offsets ----------
constexpr long oWQX  = 0;
constexpr long oWQY  = oWQX  + (long)Cv*3*Cv;
constexpr long oWGS  = oWQY  + (long)Cv*3*Cv;
constexpr long oWGC  = oWGS  + (long)Cv*Cv;
constexpr long oWP   = oWGC  + (long)Cv*Cv;
constexpr long oQKVX = oWP   + (long)Cv*Cv;
constexpr long oQKVY = oQKVX + (long)BBv*Tv*3*Cv;
constexpr long oQXG  = oQKVY + (long)BBv*Mv*3*Cv;
constexpr long oGT   = oQXG  + (long)BHv*Tv*Dv;
constexpr long NBF   = oGT   + (long)BHv*Dv*Dv;
// ---------- fp32 pool ----------
constexpr long nTCe = (long)BBv*Tv*Cv;
constexpr long fSV = 0;
constexpr long fCV = fSV + nTCe;
constexpr long fT1 = fCV + nTCe;
constexpr long fT2 = fT1 + nTCe;
constexpr long fT3 = fT2 + nTCe;
constexpr long NF_ = fT3 + nTCe;

__device__ bf    g_h[NBF];
__device__ bf    g_l[NBF];
__device__ float g_f[NF_];

// ---------- helpers ----------
__device__ __forceinline__ uint32_t smem_u32(const void* p) {
    uint32_t a;
    asm("{ .reg .u64 t; cvta.to.shared.u64 t, %1; cvt.u32.u64 %0, t; }" : "=r"(a) : "l"(p));
    return a;
}
#define LDM4(r, addr) asm volatile( \
    "ldmatrix.sync.aligned.m8n8.x4.shared.b16 {%0,%1,%2,%3}, [%4];" \
    : "=r"((r)[0]), "=r"((r)[1]), "=r"((r)[2]), "=r"((r)[3]) : "r"(addr))
#define LDM4T(r, addr) asm volatile( \
    "ldmatrix.sync.aligned.m8n8.x4.trans.shared.b16 {%0,%1,%2,%3}, [%4];" \
    : "=r"((r)[0]), "=r"((r)[1]), "=r"((r)[2]), "=r"((r)[3]) : "r"(addr))
#define MMA(c, a, b) asm volatile( \
    "mma.sync.aligned.m16n8k16.row.col.f32.bf16.bf16.f32 " \
    "{%0,%1,%2,%3}, {%4,%5,%6,%7}, {%8,%9}, {%0,%1,%2,%3};" \
    : "+f"((c)[0]), "+f"((c)[1]), "+f"((c)[2]), "+f"((c)[3]) \
    : "r"((a)[0]), "r"((a)[1]), "r"((a)[2]), "r"((a)[3]), "r"((b)[0]), "r"((b)[1]))
#define CPA(sa, ga) asm volatile("cp.async.cg.shared.global [%0], [%1], 16;" :: "r"(sa), "l"(ga))
#define CPA_COMMIT() asm volatile("cp.async.commit_group;")

__device__ __forceinline__ uint32_t packbf(float a, float b) {
    __nv_bfloat162 t; t.x = __float2bfloat16(a); t.y = __float2bfloat16(b);
    return *reinterpret_cast<uint32_t*>(&t);
}

// ---------- HMMA split-bf16 GEMM: C = alpha*(A@B^T) (+bias) -------------------
// AF32: A is fp32 in gmem, split to hi/lo on the fly (identical numerics to
// pre-split pairs). Otherwise A is a hi/lo bf16 pair.
template<int TN, bool AF32, bool F32O, bool PO, bool BIAS>
__global__ void __launch_bounds__(256) hg(
    const bf* __restrict__ Ah, const bf* __restrict__ Al, const float* __restrict__ Af,
    int lda, long sAb, long sAh_,
    const bf* __restrict__ Bh, const bf* __restrict__ Bl, int ldb, long sBb, long sBh_,
    float* __restrict__ C, bf* __restrict__ Ch, bf* __restrict__ Cl, int ldc, long sCb, long sCh_,
    const float* __restrict__ bias, int K, int Hn, float alpha)
{
    constexpr int NFRAG = TN / 16;
    int m0 = blockIdx.y * 128, n0 = blockIdx.x * TN;
    int z = blockIdx.z, bb = z / Hn, hh = z - bb * Hn;
    const bf* pAh; const bf* pAl; const float* pAf;
    if (AF32) pAf = Af + bb * sAb + hh * sAh_;
    else { pAh = Ah + bb * sAb + hh * sAh_; pAl = Al + bb * sAb + hh * sAh_; }
    const bf* pBh = Bh + bb * sBb + hh * sBh_;
    const bf* pBl = Bl + bb * sBb + hh * sBh_;
    long co = bb * sCb + hh * sCh_;

    __shared__ bf sA[2][128][40];
    __shared__ bf sB[2][TN][40];
    uint32_t baseA = smem_u32(&sA[0][0][0]);
    uint32_t baseB = smem_u32(&sB[0][0][0]);

    int tid = threadIdx.x, lane = tid & 31, wid = tid >> 5;
    int wm = (wid & 3) * 32, wn = (wid >> 2) * (TN / 2);

    float acc[2][NFRAG][4];
    #pragma unroll
    for (int i = 0; i < 2; ++i)
        #pragma unroll
        for (int j = 0; j < NFRAG; ++j)
            #pragma unroll
            for (int q = 0; q < 4; ++q) acc[i][j][q] = 0.f;

    int kst = K >> 5;
    int aRow = (lane & 15), aK = (lane >> 4) * 8;
    int bRow = (lane & 7) + ((lane >> 4) & 1) * 8, bK = ((lane >> 3) & 1) * 8;

    for (int s = 0; s < kst; ++s) {
        int k0 = s << 5;
        if (AF32) {
            #pragma unroll
            for (int i = 0; i < 4; ++i) {
                int q = tid + i * 256, r = q >> 3, g = q & 7;
                float4 v = *(const float4*)(pAf + (long)(m0 + r) * lda + k0 + g * 4);
                bf h0 = __float2bfloat16(v.x), h1 = __float2bfloat16(v.y);
                bf h2 = __float2bfloat16(v.z), h3 = __float2bfloat16(v.w);
                uint2 hi, lo;
                hi.x = packbf(__bfloat162float(h0), __bfloat162float(h1));
                hi.y = packbf(__bfloat162float(h2), __bfloat162float(h3));
                lo.x = packbf(v.x - __bfloat162float(h0), v.y - __bfloat162float(h1));
                lo.y = packbf(v.z - __bfloat162float(h2), v.w - __bfloat162float(h3));
                *(uint2*)&sA[0][r][g * 4] = hi;
                *(uint2*)&sA[1][r][g * 4] = lo;
            }
        } else {
            #pragma unroll
            for (int i = 0; i < 2; ++i) {
                int q = tid + i * 256, r = q >> 2, sg = (q & 3) * 8;
                long go = (long)(m0 + r) * lda + k0 + sg;
                *(uint4*)&sA[0][r][sg] = *(const uint4*)(pAh + go);
                *(uint4*)&sA[1][r][sg] = *(const uint4*)(pAl + go);
            }
        }
        #pragma unroll
        for (int i = 0; i < TN / 64; ++i) {
            int q = tid + i * 256, r = q >> 2, sg = (q & 3) * 8;
            long go = (long)(n0 + r) * ldb + k0 + sg;
            *(uint4*)&sB[0][r][sg] = *(const uint4*)(pBh + go);
            *(uint4*)&sB[1][r][sg] = *(const uint4*)(pBl + go);
        }
        __syncthreads();

        #pragma unroll
        for (int kk = 0; kk < 2; ++kk) {
            uint32_t ah[2][4], al[2][4];
            #pragma unroll
            for (int mf = 0; mf < 2; ++mf) {
                uint32_t off = (uint32_t)((wm + mf * 16 + aRow) * 40 + kk * 16 + aK) * 2;
                LDM4(ah[mf], baseA + off);
                LDM4(al[mf], baseA + 128 * 40 * 2 + off);
            }
            uint32_t bh[NFRAG][2], bl[NFRAG][2];
            #pragma unroll
            for (int np = 0; np < NFRAG / 2; ++np) {
                uint32_t off = (uint32_t)((wn + np * 16 + bRow) * 40 + kk * 16 + bK) * 2;
                uint32_t t[4];
                LDM4(t, baseB + off);
                bh[np*2][0] = t[0]; bh[np*2][1] = t[1]; bh[np*2+1][0] = t[2]; bh[np*2+1][1] = t[3];
                LDM4(t, baseB + TN * 40 * 2 + off);
                bl[np*2][0] = t[0]; bl[np*2][1] = t[1]; bl[np*2+1][0] = t[2]; bl[np*2+1][1] = t[3];
            }
            #pragma unroll
            for (int mf = 0; mf < 2; ++mf)
                #pragma unroll
                for (int nf = 0; nf < NFRAG; ++nf) {
                    MMA(acc[mf][nf], ah[mf], bh[nf]);
                    MMA(acc[mf][nf], ah[mf], bl[nf]);
                    MMA(acc[mf][nf], al[mf], bh[nf]);
                }
        }
        __syncthreads();
    }

    int rb = m0 + wm + (lane >> 2);
    int cb = n0 + wn + (lane & 3) * 2;
    #pragma unroll
    for (int mf = 0; mf < 2; ++mf)
        #pragma unroll
        for (int half = 0; half < 2; ++half) {
            long row = rb + mf * 16 + half * 8;
            #pragma unroll
            for (int nf = 0; nf < NFRAG; ++nf) {
                int cc = cb + nf * 8;
                float v0 = alpha * acc[mf][nf][half * 2 + 0];
                float v1 = alpha * acc[mf][nf][half * 2 + 1];
                if (BIAS) { v0 += bias[cc]; v1 += bias[cc + 1]; }
                long base = co + row * (long)ldc + cc;
                if (F32O) { C[base] = v0; C[base + 1] = v1; }
                if (PO) {
                    bf h0 = __float2bfloat16(v0), h1 = __float2bfloat16(v1);
                    *reinterpret_cast<uint32_t*>(Ch + base) = packbf(__bfloat162float(h0), __bfloat162float(h1));
                    *reinterpret_cast<uint32_t*>(Cl + base) = packbf(v0 - __bfloat162float(h0), v1 - __bfloat162float(h1));
                }
            }
        }
}

// ---------- shared attention tile step (scores -> online softmax -> PV) -------
template<bool CAUSAL>
__device__ __forceinline__ void attn_tile(
    uint32_t sbase, uint32_t bo,
    uint32_t (&qh)[4][4], uint32_t (&ql)[4][4],
    float (&o)[8][4], float& mr0, float& mr1, float& l0, float& l1,
    int c0, int row0, int diagRow, float scale, int lane)
{
    int bRow = (lane & 7) + ((lane >> 4) & 1) * 8, bK = ((lane >> 3) & 1) * 8;
    int vRow = (lane & 7) + ((lane >> 3) & 1) * 8, vN = ((lane >> 4) & 1) * 8;

    float s[8][4];
    #pragma unroll
    for (int i = 0; i < 8; ++i)
        #pragma unroll
        for (int q = 0; q < 4; ++q) s[i][q] = 0.f;

    #pragma unroll
    for (int kk = 0; kk < 4; ++kk) {
        uint32_t kh[8][2], kl[8][2];
        #pragma unroll
        for (int np = 0; np < 4; ++np) {
            uint32_t off = bo + (uint32_t)((np * 16 + bRow) * 72 + kk * 16 + bK) * 2;
            uint32_t t[4];
            LDM4(t, sbase + off);
            kh[np*2][0] = t[0]; kh[np*2][1] = t[1]; kh[np*2+1][0] = t[2]; kh[np*2+1][1] = t[3];
            LDM4(t, sbase + 4608 * 2 + off);
            kl[np*2][0] = t[0]; kl[np*2][1] = t[1]; kl[np*2+1][0] = t[2]; kl[np*2+1][1] = t[3];
        }
        #pragma unroll
        for (int nf = 0; nf < 8; ++nf) {
            MMA(s[nf], qh[kk], kh[nf]);
            MMA(s[nf], qh[kk], kl[nf]);
            MMA(s[nf], ql[kk], kh[nf]);
        }
    }
    #pragma unroll
    for (int nf = 0; nf < 8; ++nf) {
        #pragma unroll
        for (int q = 0; q < 4; ++q) s[nf][q] *= scale;
    }
    if (CAUSAL && (c0 + 63 > diagRow)) {
        #pragma unroll
        for (int nf = 0; nf < 8; ++nf) {
            int col = c0 + nf * 8 + (lane & 3) * 2;
            if (col     > row0)     s[nf][0] = -1e30f;
            if (col + 1 > row0)     s[nf][1] = -1e30f;
            if (col     > row0 + 8) s[nf][2] = -1e30f;
            if (col + 1 > row0 + 8) s[nf][3] = -1e30f;
        }
    }
    float t0 = -INFINITY, t1 = -INFINITY;
    #pragma unroll
    for (int nf = 0; nf < 8; ++nf) {
        t0 = fmaxf(t0, fmaxf(s[nf][0], s[nf][1]));
        t1 = fmaxf(t1, fmaxf(s[nf][2], s[nf][3]));
    }
    t0 = fmaxf(t0, __shfl_xor_sync(0xffffffffu, t0, 1));
    t0 = fmaxf(t0, __shfl_xor_sync(0xffffffffu, t0, 2));
    t1 = fmaxf(t1, __shfl_xor_sync(0xffffffffu, t1, 1));
    t1 = fmaxf(t1, __shfl_xor_sync(0xffffffffu, t1, 2));
    float mn0 = fmaxf(mr0, t0), mn1 = fmaxf(mr1, t1);
    float cr0 = __expf(mr0 - mn0), cr1 = __expf(mr1 - mn1);
    float sum0 = 0.f, sum1 = 0.f;
    #pragma unroll
    for (int nf = 0; nf < 8; ++nf) {
        s[nf][0] = __expf(s[nf][0] - mn0);
        s[nf][1] = __expf(s[nf][1] - mn0);
        s[nf][2] = __expf(s[nf][2] - mn1);
        s[nf][3] = __expf(s[nf][3] - mn1);
        sum0 += s[nf][0] + s[nf][1];
        sum1 += s[nf][2] + s[nf][3];
    }
    sum0 += __shfl_xor_sync(0xffffffffu, sum0, 1);
    sum0 += __shfl_xor_sync(0xffffffffu, sum0, 2);
    sum1 += __shfl_xor_sync(0xffffffffu, sum1, 1);
    sum1 += __shfl_xor_sync(0xffffffffu, sum1, 2);
    l0 = l0 * cr0 + sum0; l1 = l1 * cr1 + sum1;
    mr0 = mn0; mr1 = mn1;
    #pragma unroll
    for (int nf = 0; nf < 8; ++nf) {
        o[nf][0] *= cr0; o[nf][1] *= cr0; o[nf][2] *= cr1; o[nf][3] *= cr1;
    }
    #pragma unroll
    for (int kk2 = 0; kk2 < 4; ++kk2) {
        uint32_t Ph[4], Pl[4];
        {
            float a0 = s[2*kk2][0],   a1 = s[2*kk2][1];
            float a2 = s[2*kk2][2],   a3 = s[2*kk2][3];
            float a4 = s[2*kk2+1][0], a5 = s[2*kk2+1][1];
            float a6 = s[2*kk2+1][2], a7 = s[2*kk2+1][3];
            bf h0 = __float2bfloat16(a0), h1 = __float2bfloat16(a1);
            bf h2 = __float2bfloat16(a2), h3 = __float2bfloat16(a3);
            bf h4 = __float2bfloat16(a4), h5 = __float2bfloat16(a5);
            bf h6 = __float2bfloat16(a6), h7 = __float2bfloat16(a7);
            Ph[0] = packbf(__bfloat162float(h0), __bfloat162float(h1));
            Ph[1] = packbf(__bfloat162float(h2), __bfloat162float(h3));
            Ph[2] = packbf(__bfloat162float(h4), __bfloat162float(h5));
            Ph[3] = packbf(__bfloat162float(h6), __bfloat162float(h7));
            Pl[0] = packbf(a0 - __bfloat162float(h0), a1 - __bfloat162float(h1));
            Pl[1] = packbf(a2 - __bfloat162float(h2), a3 - __bfloat162float(h3));
            Pl[2] = packbf(a4 - __bfloat162float(h4), a5 - __bfloat162float(h5));
            Pl[3] = packbf(a6 - __bfloat162float(h6), a7 - __bfloat162float(h7));
        }
        uint32_t vh[8][2], vl[8][2];
        #pragma unroll
        for (int np = 0; np < 4; ++np) {
            uint32_t off = bo + (uint32_t)((kk2 * 16 + vRow) * 72 + np * 16 + vN) * 2;
            uint32_t t[4];
            LDM4T(t, sbase + 9216 * 2 + off);
            vh[np*2][0] = t[0]; vh[np*2][1] = t[1]; vh[np*2+1][0] = t[2]; vh[np*2+1][1] = t[3];
            LDM4T(t, sbase + 13824 * 2 + off);
            vl[np*2][0] = t[0]; vl[np*2][1] = t[1]; vl[np*2+1][0] = t[2]; vl[np*2+1][1] = t[3];
        }
        #pragma unroll
        for (int nf = 0; nf < 8; ++nf) {
            MMA(o[nf], Ph, vh[nf]);
            MMA(o[nf], Ph, vl[nf]);
            MMA(o[nf], Pl, vh[nf]);
        }
    }
}

// prefetch one K/V tile (V loaded directly from qkv row-major [s][d])
__device__ __forceinline__ void kv_prefetch(
    uint32_t sbase, uint32_t bn, int c0,
    const bf* pKh, const bf* pKl, int ldk,
    const bf* pVh, const bf* pVl, int ldv, int tid)
{
    int pr = tid >> 3, pch = tid & 7;
    #pragma unroll
    for (int i = 0; i < 2; ++i) {
        int r = pr + i * 32;
        long gk = (long)(c0 + r) * ldk + pch * 8;
        long gv = (long)(c0 + r) * ldv + pch * 8;
        uint32_t so = bn + (uint32_t)(r * 72 + pch * 8) * 2;
        CPA(sbase + so,             pKh + gk);
        CPA(sbase + 4608*2  + so,   pKl + gk);
        CPA(sbase + 9216*2  + so,   pVh + gv);
        CPA(sbase + 13824*2 + so,   pVl + gv);
    }
    CPA_COMMIT();
}

// ---------- single-Q flash (non-causal; cval1), f32 out -----------------------
__global__ void __launch_bounds__(256) fa_k(
    const bf* __restrict__ Ah, const bf* __restrict__ Al, int lda, long sAb, long sAh_,
    const bf* __restrict__ Kh, const bf* __restrict__ Kl, int ldk, long sKb, long sKh_,
    const bf* __restrict__ Vh, const bf* __restrict__ Vl, int ldv, long sVb, long sVh_,
    int S_, float* __restrict__ O, int ldo, long sOb, long sOh_, float scale)
{
    extern __shared__ __align__(16) bf dsm[];
    uint32_t sbase = smem_u32(dsm);

    int z = blockIdx.y, bb = z >> 3, hh = z & 7;
    int m0 = (int)blockIdx.x * 128;
    const bf* pAh = Ah + bb * sAb + hh * sAh_;
    const bf* pAl = Al + bb * sAb + hh * sAh_;
    const bf* pKh = Kh + bb * sKb + hh * sKh_;
    const bf* pKl = Kl + bb * sKb + hh * sKh_;
    const bf* pVh = Vh + bb * sVb + hh * sVh_;
    const bf* pVl = Vl + bb * sVb + hh * sVh_;
    long co = (long)bb * sOb + (long)hh * sOh_;

    int tid = threadIdx.x, lane = tid & 31, wid = tid >> 5;
    int wrow = wid * 16;

    #pragma unroll
    for (int i = 0; i < 4; ++i) {
        int q = tid + i * 256, r = q >> 3, ch = q & 7;
        long go = (long)(m0 + r) * lda + ch * 8;
        *(uint4*)&dsm[r * 72 + ch * 8]        = *(const uint4*)(pAh + go);
        *(uint4*)&dsm[9216 + r * 72 + ch * 8] = *(const uint4*)(pAl + go);
    }
    __syncthreads();
    int aRow = lane & 15, aK = (lane >> 4) * 8;
    uint32_t qh[4][4], ql[4][4];
    #pragma unroll
    for (int kk = 0; kk < 4; ++kk) {
        uint32_t off = (uint32_t)((wrow + aRow) * 72 + kk * 16 + aK) * 2;
        LDM4(qh[kk], sbase + off);
        LDM4(ql[kk], sbase + 9216 * 2 + off);
    }
    __syncthreads();

    float o[8][4];
    #pragma unroll
    for (int i = 0; i < 8; ++i)
        #pragma unroll
        for (int q = 0; q < 4; ++q) o[i][q] = 0.f;
    float mr0 = -INFINITY, mr1 = -INFINITY, l0 = 0.f, l1 = 0.f;

    int nt = S_ >> 6;
    int row0 = m0 + wrow + (lane >> 2);

    kv_prefetch(sbase, 0, 0, pKh, pKl, ldk, pVh, pVl, ldv, tid);

    for (int ct = 0; ct < nt; ++ct) {
        uint32_t bo = (uint32_t)(ct & 1) * 18432u * 2u;
        if (ct + 1 < nt) {
            kv_prefetch(sbase, (uint32_t)((ct + 1) & 1) * 18432u * 2u, (ct + 1) << 6,
                        pKh, pKl, ldk, pVh, pVl, ldv, tid);
            asm volatile("cp.async.wait_group 1;");
        } else {
            asm volatile("cp.async.wait_group 0;");
        }
        __syncthreads();
        attn_tile<false>(sbase, bo, qh, ql, o, mr0, mr1, l0, l1,
                         ct << 6, row0, 0, scale, lane);
        __syncthreads();
    }

    float inv0 = 1.f / l0, inv1 = 1.f / l1;
    #pragma unroll
    for (int nf = 0; nf < 8; ++nf) {
        int col = nf * 8 + (lane & 3) * 2;
        long b0 = co + (long)row0 * ldo + col;
        long b1 = co + (long)(row0 + 8) * ldo + col;
        O[b0] = o[nf][0] * inv0; O[b0 + 1] = o[nf][1] * inv0;
        O[b1] = o[nf][2] * inv1; O[b1 + 1] = o[nf][3] * inv1;
    }
}

// ---------- dual-Q causal flash: cval2 (ACC into O1) + sval; fp32 outs --------
__global__ void __launch_bounds__(256) fa2_k(
    const bf* __restrict__ A1h, const bf* __restrict__ A1l, int lda1, long sA1b, long sA1h,
    const bf* __restrict__ A2h, const bf* __restrict__ A2l, int lda2, long sA2b, long sA2h,
    const bf* __restrict__ Kh, const bf* __restrict__ Kl, int ldk, long sKb, long sKh_,
    const bf* __restrict__ Vh, const bf* __restrict__ Vl, int ldv, long sVb, long sVh_,
    float* __restrict__ O1, float* __restrict__ O2,
    int ldo, long sOb, long sOh_, float scale)
{
    extern __shared__ __align__(16) bf dsm[];
    uint32_t sbase = smem_u32(dsm);

    int z = blockIdx.y, bb = z >> 3, hh = z & 7;
    int m0 = (int)(gridDim.x - 1 - blockIdx.x) * 128;   // heavy blocks first
    const bf* pKh = Kh + bb * sKb + hh * sKh_;
    const bf* pKl = Kl + bb * sKb + hh * sKh_;
    const bf* pVh = Vh + bb * sVb + hh * sVh_;
    const bf* pVl = Vl + bb * sVb + hh * sVh_;
    long co = (long)bb * sOb + (long)hh * sOh_;

    int tid = threadIdx.x, lane = tid & 31, wid = tid >> 5;
    int wrow = wid * 16;
    int aRow = lane & 15, aK = (lane >> 4) * 8;
    uint32_t q1h[4][4], q1l[4][4], q2h[4][4], q2l[4][4];

    {
        const bf* p1h = A1h + bb * sA1b + hh * sA1h;
        const bf* p1l = A1l + bb * sA1b + hh * sA1h;
        #pragma unroll
        for (int i = 0; i < 4; ++i) {
            int q = tid + i * 256, r = q >> 3, ch = q & 7;
            long go = (long)(m0 + r) * lda1 + ch * 8;
            *(uint4*)&dsm[r * 72 + ch * 8]        = *(const uint4*)(p1h + go);
            *(uint4*)&dsm[9216 + r * 72 + ch * 8] = *(const uint4*)(p1l + go);
        }
        __syncthreads();
        #pragma unroll
        for (int kk = 0; kk < 4; ++kk) {
            uint32_t off = (uint32_t)((wrow + aRow) * 72 + kk * 16 + aK) * 2;
            LDM4(q1h[kk], sbase + off);
            LDM4(q1l[kk], sbase + 9216 * 2 + off);
        }
        __syncthreads();
        const bf* p2h = A2h + bb * sA2b + hh * sA2h;
        const bf* p2l = A2l + bb * sA2b + hh * sA2h;
        #pragma unroll
        for (int i = 0; i < 4; ++i) {
            int q = tid + i * 256, r = q >> 3, ch = q & 7;
            long go = (long)(m0 + r) * lda2 + ch * 8;
            *(uint4*)&dsm[r * 72 + ch * 8]        = *(const uint4*)(p2h + go);
            *(uint4*)&dsm[9216 + r * 72 + ch * 8] = *(const uint4*)(p2l + go);
        }
        __syncthreads();
        #pragma unroll
        for (int kk = 0; kk < 4; ++kk) {
            uint32_t off = (uint32_t)((wrow + aRow) * 72 + kk * 16 + aK) * 2;
            LDM4(q2h[kk], sbase + off);
            LDM4(q2l[kk], sbase + 9216 * 2 + off);
        }
        __syncthreads();
    }

    float o1[8][4], o2[8][4];
    #pragma unroll
    for (int i = 0; i < 8; ++i)
        #pragma unroll
        for (int q = 0; q < 4; ++q) { o1[i][q] = 0.f; o2[i][q] = 0.f; }
    float m10 = -INFINITY, m11 = -INFINITY, l10 = 0.f, l11 = 0.f;
    float m20 = -INFINITY, m21 = -INFINITY, l20 = 0.f, l21 = 0.f;

    int nt = (m0 >> 6) + 2;
    int row0 = m0 + wrow + (lane >> 2);
    int diagRow = m0 + wrow;

    kv_prefetch(sbase, 0, 0, pKh, pKl, ldk, pVh, pVl, ldv, tid);

    for (int ct = 0; ct < nt; ++ct) {
        uint32_t bo = (uint32_t)(ct & 1) * 18432u * 2u;
        if (ct + 1 < nt) {
            kv_prefetch(sbase, (uint32_t)((ct + 1) & 1) * 18432u * 2u, (ct + 1) << 6,
                        pKh, pKl, ldk, pVh, pVl, ldv, tid);
            asm volatile("cp.async.wait_group 1;");
        } else {
            asm volatile("cp.async.wait_group 0;");
        }
        __syncthreads();
        int c0 = ct << 6;
        attn_tile<true>(sbase, bo, q1h, q1l, o1, m10, m11, l10, l11, c0, row0, diagRow, scale, lane);
        attn_tile<true>(sbase, bo, q2h, q2l, o2, m20, m21, l20, l21, c0, row0, diagRow, scale, lane);
        __syncthreads();
    }

    float i10 = 1.f / l10, i11 = 1.f / l11, i20 = 1.f / l20, i21 = 1.f / l21;
    #pragma unroll
    for (int nf = 0; nf < 8; ++nf) {
        int col = nf * 8 + (lane & 3) * 2;
        long b0 = co + (long)row0 * ldo + col;
        long b1 = co + (long)(row0 + 8) * ldo + col;
        O1[b0]     = o1[nf][0] * i10 + O1[b0];
        O1[b0 + 1] = o1[nf][1] * i10 + O1[b0 + 1];
        O1[b1]     = o1[nf][2] * i11 + O1[b1];
        O1[b1 + 1] = o1[nf][3] * i11 + O1[b1 + 1];
        O2[b0]     = o2[nf][0] * i20;
        O2[b0 + 1] = o2[nf][1] * i20;
        O2[b1]     = o2[nf][2] * i21;
        O2[b1 + 1] = o2[nf][3] * i21;
    }
}

// ---------- G^T = SCL^2 * (k_y^T q_y)^T per head ----------
__global__ void __launch_bounds__(256) g_k(const bf* __restrict__ qh, const bf* __restrict__ ql,
                                           bf* __restrict__ goh, bf* __restrict__ gol)
{
    int z = blockIdx.x, b = z >> 3, h = z & 7;
    long kyo = (long)b * Mv * 3 * Cv + (long)h * Dv + Cv;
    long qyo = (long)b * Mv * 3 * Cv + (long)h * Dv;
    __shared__ float sky[64][65], sqy[64][65];
    int tid = threadIdx.x;
    int d2 = tid & 63, gg = tid >> 6;
    float acc[16];
    #pragma unroll
    for (int i = 0; i < 16; ++i) acc[i] = 0.f;
    for (int m0 = 0; m0 < Mv; m0 += 64) {
        #pragma unroll
        for (int i = 0; i < 16; ++i) {
            int q = tid + i * 256;
            int mm = q >> 6, dd = q & 63;
            long ik = kyo + (long)(m0 + mm) * 3 * Cv + dd;
            long iq = qyo + (long)(m0 + mm) * 3 * Cv + dd;
            sky[mm][dd] = __bfloat162float(qh[ik]) + __bfloat162float(ql[ik]);
            sqy[mm][dd] = __bfloat162float(qh[iq]) + __bfloat162float(ql[iq]);
        }
        __syncthreads();
        for (int mm = 0; mm < 64; ++mm) {
            float qv = sqy[mm][d2];
            #pragma unroll
            for (int i = 0; i < 16; ++i)
                acc[i] += sky[mm][gg * 16 + i] * qv;
        }
        __syncthreads();
    }
    long base = (long)z * 4096 + (long)d2 * 64 + gg * 16;
    #pragma unroll
    for (int i = 0; i < 16; ++i) {
        float v = acc[i] * (SCL * SCL);
        bf hh = __float2bfloat16(v);
        goh[base + i] = hh;
        gol[base + i] = __float2bfloat16(v - __bfloat162float(hh));
    }
}

// ---------- merged weight transpose-splits (5 jobs via blockIdx.y) ------------
__global__ void __launch_bounds__(256) splitW_k(
    const float* __restrict__ w0, const float* __restrict__ w1,
    const float* __restrict__ w2, const float* __restrict__ w3,
    const float* __restrict__ w4, bf* __restrict__ oh, bf* __restrict__ ol)
{
    int job = blockIdx.y;
    const float* src; long off; int Nd;
    switch (job) {
        case 0:  src = w0; off = oWQX; Nd = 3 * Cv; break;
        case 1:  src = w1; off = oWQY; Nd = 3 * Cv; break;
        case 2:  src = w2; off = oWGS; Nd = Cv; break;
        case 3:  src = w3; off = oWGC; Nd = Cv; break;
        default: src = w4; off = oWP;  Nd = Cv; break;
    }
    long n = (long)Cv * Nd;
    long i = (long)blockIdx.x * 256 + threadIdx.x;
    if (i >= n) return;
    int nn = (int)(i / Cv), k = (int)(i % Cv);
    float v = src[(long)k * Nd + nn];
    bf h = __float2bfloat16(v);
    oh[off + i] = h;
    ol[off + i] = __float2bfloat16(v - __bfloat162float(h));
}

// ---------- gate combine (fp32 out) ----------
__global__ void __launch_bounds__(256) gate_k(
    const float* __restrict__ t1, const float* __restrict__ t2,
    const float* __restrict__ bgs, const float* __restrict__ bgc,
    const float* __restrict__ cv, const float* __restrict__ sv,
    float* __restrict__ t3, long n)
{
    long i = (long)blockIdx.x * 256 + threadIdx.x;
    if (i < n) {
        int c = (int)(i & (Cv - 1));
        float g1 = 1.f / (1.f + __expf(-(t1[i] + bgs[c])));
        float g2 = 1.f / (1.f + __expf(-(t2[i] + bgc[c])));
        t3[i] = g1 * cv[i] + g2 * sv[i];
    }
}

// ------------------------------------------------------------------------------
extern "C" void kernel_launch(void* const* d_in, const int* in_sizes, int n_in,
                              void* d_out, int out_size)
{
    const float* x      = (const float*)d_in[0];
    const float* y      = (const float*)d_in[1];
    const float* Wqkv_x = (const float*)d_in[3];
    const float* bqkv_x = (const float*)d_in[4];
    const float* Wqkv_y = (const float*)d_in[5];
    const float* bqkv_y = (const float*)d_in[6];
    const float* Wgs    = (const float*)d_in[7];
    const float* bgs    = (const float*)d_in[8];
    const float* Wgc    = (const float*)d_in[9];
    const float* bgc    = (const float*)d_in[10];
    const float* Wp     = (const float*)d_in[11];
    const float* bp     = (const float*)d_in[12];
    float* out = (float*)d_out;

    bf *gh, *gl; float* gf;
    cudaGetSymbolAddress((void**)&gh, g_h);
    cudaGetSymbolAddress((void**)&gl, g_l);
    cudaGetSymbolAddress((void**)&gf, g_f);

    const int FASM = 2 * 18432 * 2;   // 73728 B dynamic smem
    cudaFuncSetAttribute((const void*)fa_k,  cudaFuncAttributeMaxDynamicSharedMemorySize, FASM);
    cudaFuncSetAttribute((const void*)fa2_k, cudaFuncAttributeMaxDynamicSharedMemorySize, FASM);

    dim3 blk(256);
    long nTC = nTCe;

    // all weight transpose-splits in one launch
    splitW_k<<<dim3(3072, 5), blk>>>(Wqkv_x, Wqkv_y, Wgs, Wgc, Wp, gh, gl);

    // qkv projections: A = x / y fp32 directly (AF32), pair out
    hg<128,true,false,true,true><<<dim3(12,32,1), blk>>>(
        nullptr, nullptr, x, Cv, 0,0, gh+oWQX, gl+oWQX, Cv, 0,0,
        nullptr, gh+oQKVX, gl+oQKVX, 3*Cv, 0,0, bqkv_x, Cv, 1, 1.0f);
    hg<128,true,false,true,true><<<dim3(12,8,1), blk>>>(
        nullptr, nullptr, y, Cv, 0,0, gh+oWQY, gl+oWQY, Cv, 0,0,
        nullptr, gh+oQKVY, gl+oQKVY, 3*Cv, 0,0, bqkv_y, Cv, 1, 1.0f);

    // G^T then qxG (pair path)
    g_k<<<BHv, blk>>>(gh+oQKVY, gl+oQKVY, gh+oGT, gl+oGT);
    hg<64,false,false,true,false><<<dim3(1,16,16), blk>>>(
        gh+oQKVX, gl+oQKVX, nullptr, 3*Cv, (long)Tv*3*Cv, (long)Dv,
        gh+oGT, gl+oGT, 64, (long)Hv*Dv*Dv, (long)Dv*Dv,
        nullptr, gh+oQXG, gl+oQXG, Dv, (long)Hv*Tv*Dv, (long)Tv*Dv, nullptr, Dv, Hv, 1.0f);

    // cval1 = softmax(q_x k_y^T) v_y  (fused, non-causal)
    fa_k<<<dim3(16,16), blk, FASM>>>(
        gh+oQKVX, gl+oQKVX, 3*Cv, (long)Tv*3*Cv, (long)Dv,
        gh+oQKVY+Cv, gl+oQKVY+Cv, 3*Cv, (long)Mv*3*Cv, (long)Dv,
        gh+oQKVY+2*Cv, gl+oQKVY+2*Cv, 3*Cv, (long)Mv*3*Cv, (long)Dv,
        Mv, gf+fCV, Cv, (long)Tv*Cv, (long)Dv, SCL);

    // dual-Q causal: cval += softmax(qxG k_x^T) v_x ; sval = softmax(q_x k_x^T) v_x
    fa2_k<<<dim3(16,16), blk, FASM>>>(
        gh+oQXG, gl+oQXG, Dv, (long)Hv*Tv*Dv, (long)Tv*Dv,
        gh+oQKVX, gl+oQKVX, 3*Cv, (long)Tv*3*Cv, (long)Dv,
        gh+oQKVX+Cv, gl+oQKVX+Cv, 3*Cv, (long)Tv*3*Cv, (long)Dv,
        gh+oQKVX+2*Cv, gl+oQKVX+2*Cv, 3*Cv, (long)Tv*3*Cv, (long)Dv,
        gf+fCV, gf+fSV, Cv, (long)Tv*Cv, (long)Dv, SCL);

    // gates: batched z=2 (t1 = sval@Wgs, t2 = cval@Wgc), A = fp32 (AF32)
    hg<128,true,true,false,false><<<dim3(4,32,2), blk>>>(
        nullptr, nullptr, gf+fSV, Cv, 0, nTC,
        gh+oWGS, gl+oWGS, Cv, 0, (long)Cv*Cv,
        gf+fT1, nullptr, nullptr, Cv, 0, nTC, nullptr, Cv, 2, 1.0f);

    gate_k<<<(unsigned)((nTC + 255) / 256), blk>>>(
        gf+fT1, gf+fT2, bgs, bgc, gf+fCV, gf+fSV, gf+fT3, nTC);

    // out = t3 @ Wp + bp  (A = fp32)
    hg<128,true,true,false,true><<<dim3(4,32,1), blk>>>(
        nullptr, nullptr, gf+fT3, Cv, 0,0, gh+oWP, gl+oWP, Cv, 0,0,
        out, nullptr, nullptr, Cv, 0,0, bp, Cv, 1, 1.0f);
}

// round 12
// speedup vs baseline: 1.1209x; 1.1209x over previous
#include <cuda_runtime.h>
#include <cuda_bf16.h>
#include <cstdint>
#include <math.h>

#define BBv 2
#define Tv 2048
#define Mv 512
#define Cv 512
#define Hv 8
#define Dv 64
#define BHv 16
#define SCL 0.125f
typedef __nv_bfloat16 bf;

// ---------- bf16 pair pool offsets ----------
constexpr long oWQX  = 0;
constexpr long oWQY  = oWQX  + (long)Cv*3*Cv;
constexpr long oWGS  = oWQY  + (long)Cv*3*Cv;
constexpr long oWGC  = oWGS  + (long)Cv*Cv;
constexpr long oWP   = oWGC  + (long)Cv*Cv;
constexpr long oQKVX = oWP   + (long)Cv*Cv;
constexpr long oQKVY = oQKVX + (long)BBv*Tv*3*Cv;
constexpr long oQXG  = oQKVY + (long)BBv*Mv*3*Cv;
constexpr long oGT   = oQXG  + (long)BHv*Tv*Dv;
constexpr long NBF   = oGT   + (long)BHv*Dv*Dv;
// ---------- fp32 pool ----------
constexpr long nTCe = (long)BBv*Tv*Cv;
constexpr long fSV = 0;
constexpr long fCV = fSV + nTCe;
constexpr long fT1 = fCV + nTCe;      // also reused as G partial scratch early
constexpr long fT2 = fT1 + nTCe;
constexpr long fT3 = fT2 + nTCe;
constexpr long NF_ = fT3 + nTCe;

__device__ bf    g_h[NBF];
__device__ bf    g_l[NBF];
__device__ float g_f[NF_];

// ---------- helpers ----------
__device__ __forceinline__ uint32_t smem_u32(const void* p) {
    uint32_t a;
    asm("{ .reg .u64 t; cvta.to.shared.u64 t, %1; cvt.u32.u64 %0, t; }" : "=r"(a) : "l"(p));
    return a;
}
#define LDM4(r, addr) asm volatile( \
    "ldmatrix.sync.aligned.m8n8.x4.shared.b16 {%0,%1,%2,%3}, [%4];" \
    : "=r"((r)[0]), "=r"((r)[1]), "=r"((r)[2]), "=r"((r)[3]) : "r"(addr))
#define LDM4T(r, addr) asm volatile( \
    "ldmatrix.sync.aligned.m8n8.x4.trans.shared.b16 {%0,%1,%2,%3}, [%4];" \
    : "=r"((r)[0]), "=r"((r)[1]), "=r"((r)[2]), "=r"((r)[3]) : "r"(addr))
#define MMA(c, a, b) asm volatile( \
    "mma.sync.aligned.m16n8k16.row.col.f32.bf16.bf16.f32 " \
    "{%0,%1,%2,%3}, {%4,%5,%6,%7}, {%8,%9}, {%0,%1,%2,%3};" \
    : "+f"((c)[0]), "+f"((c)[1]), "+f"((c)[2]), "+f"((c)[3]) \
    : "r"((a)[0]), "r"((a)[1]), "r"((a)[2]), "r"((a)[3]), "r"((b)[0]), "r"((b)[1]))
#define CPA(sa, ga) asm volatile("cp.async.cg.shared.global [%0], [%1], 16;" :: "r"(sa), "l"(ga))
#define CPA_COMMIT() asm volatile("cp.async.commit_group;")

__device__ __forceinline__ uint32_t packbf(float a, float b) {
    __nv_bfloat162 t; t.x = __float2bfloat16(a); t.y = __float2bfloat16(b);
    return *reinterpret_cast<uint32_t*>(&t);
}

// ---------- HMMA split-bf16 GEMM: C = alpha*(A@B^T) (+bias) -------------------
template<int TN, bool AF32, bool F32O, bool PO, bool BIAS>
__global__ void __launch_bounds__(256) hg(
    const bf* __restrict__ Ah, const bf* __restrict__ Al, const float* __restrict__ Af,
    int lda, long sAb, long sAh_,
    const bf* __restrict__ Bh, const bf* __restrict__ Bl, int ldb, long sBb, long sBh_,
    float* __restrict__ C, bf* __restrict__ Ch, bf* __restrict__ Cl, int ldc, long sCb, long sCh_,
    const float* __restrict__ bias, int K, int Hn, float alpha)
{
    constexpr int NFRAG = TN / 16;
    int m0 = blockIdx.y * 128, n0 = blockIdx.x * TN;
    int z = blockIdx.z, bb = z / Hn, hh = z - bb * Hn;
    const bf* pAh; const bf* pAl; const float* pAf;
    if (AF32) pAf = Af + bb * sAb + hh * sAh_;
    else { pAh = Ah + bb * sAb + hh * sAh_; pAl = Al + bb * sAb + hh * sAh_; }
    const bf* pBh = Bh + bb * sBb + hh * sBh_;
    const bf* pBl = Bl + bb * sBb + hh * sBh_;
    long co = bb * sCb + hh * sCh_;

    __shared__ bf sA[2][128][40];
    __shared__ bf sB[2][TN][40];
    uint32_t baseA = smem_u32(&sA[0][0][0]);
    uint32_t baseB = smem_u32(&sB[0][0][0]);

    int tid = threadIdx.x, lane = tid & 31, wid = tid >> 5;
    int wm = (wid & 3) * 32, wn = (wid >> 2) * (TN / 2);

    float acc[2][NFRAG][4];
    #pragma unroll
    for (int i = 0; i < 2; ++i)
        #pragma unroll
        for (int j = 0; j < NFRAG; ++j)
            #pragma unroll
            for (int q = 0; q < 4; ++q) acc[i][j][q] = 0.f;

    int kst = K >> 5;
    int aRow = (lane & 15), aK = (lane >> 4) * 8;
    int bRow = (lane & 7) + ((lane >> 4) & 1) * 8, bK = ((lane >> 3) & 1) * 8;

    for (int s = 0; s < kst; ++s) {
        int k0 = s << 5;
        if (AF32) {
            #pragma unroll
            for (int i = 0; i < 4; ++i) {
                int q = tid + i * 256, r = q >> 3, g = q & 7;
                float4 v = *(const float4*)(pAf + (long)(m0 + r) * lda + k0 + g * 4);
                bf h0 = __float2bfloat16(v.x), h1 = __float2bfloat16(v.y);
                bf h2 = __float2bfloat16(v.z), h3 = __float2bfloat16(v.w);
                uint2 hi, lo;
                hi.x = packbf(__bfloat162float(h0), __bfloat162float(h1));
                hi.y = packbf(__bfloat162float(h2), __bfloat162float(h3));
                lo.x = packbf(v.x - __bfloat162float(h0), v.y - __bfloat162float(h1));
                lo.y = packbf(v.z - __bfloat162float(h2), v.w - __bfloat162float(h3));
                *(uint2*)&sA[0][r][g * 4] = hi;
                *(uint2*)&sA[1][r][g * 4] = lo;
            }
        } else {
            #pragma unroll
            for (int i = 0; i < 2; ++i) {
                int q = tid + i * 256, r = q >> 2, sg = (q & 3) * 8;
                long go = (long)(m0 + r) * lda + k0 + sg;
                *(uint4*)&sA[0][r][sg] = *(const uint4*)(pAh + go);
                *(uint4*)&sA[1][r][sg] = *(const uint4*)(pAl + go);
            }
        }
        #pragma unroll
        for (int i = 0; i < TN / 64; ++i) {
            int q = tid + i * 256, r = q >> 2, sg = (q & 3) * 8;
            long go = (long)(n0 + r) * ldb + k0 + sg;
            *(uint4*)&sB[0][r][sg] = *(const uint4*)(pBh + go);
            *(uint4*)&sB[1][r][sg] = *(const uint4*)(pBl + go);
        }
        __syncthreads();

        #pragma unroll
        for (int kk = 0; kk < 2; ++kk) {
            uint32_t ah[2][4], al[2][4];
            #pragma unroll
            for (int mf = 0; mf < 2; ++mf) {
                uint32_t off = (uint32_t)((wm + mf * 16 + aRow) * 40 + kk * 16 + aK) * 2;
                LDM4(ah[mf], baseA + off);
                LDM4(al[mf], baseA + 128 * 40 * 2 + off);
            }
            uint32_t bh[NFRAG][2], bl[NFRAG][2];
            #pragma unroll
            for (int np = 0; np < NFRAG / 2; ++np) {
                uint32_t off = (uint32_t)((wn + np * 16 + bRow) * 40 + kk * 16 + bK) * 2;
                uint32_t t[4];
                LDM4(t, baseB + off);
                bh[np*2][0] = t[0]; bh[np*2][1] = t[1]; bh[np*2+1][0] = t[2]; bh[np*2+1][1] = t[3];
                LDM4(t, baseB + TN * 40 * 2 + off);
                bl[np*2][0] = t[0]; bl[np*2][1] = t[1]; bl[np*2+1][0] = t[2]; bl[np*2+1][1] = t[3];
            }
            #pragma unroll
            for (int mf = 0; mf < 2; ++mf)
                #pragma unroll
                for (int nf = 0; nf < NFRAG; ++nf) {
                    MMA(acc[mf][nf], ah[mf], bh[nf]);
                    MMA(acc[mf][nf], ah[mf], bl[nf]);
                    MMA(acc[mf][nf], al[mf], bh[nf]);
                }
        }
        __syncthreads();
    }

    int rb = m0 + wm + (lane >> 2);
    int cb = n0 + wn + (lane & 3) * 2;
    #pragma unroll
    for (int mf = 0; mf < 2; ++mf)
        #pragma unroll
        for (int half = 0; half < 2; ++half) {
            long row = rb + mf * 16 + half * 8;
            #pragma unroll
            for (int nf = 0; nf < NFRAG; ++nf) {
                int cc = cb + nf * 8;
                float v0 = alpha * acc[mf][nf][half * 2 + 0];
                float v1 = alpha * acc[mf][nf][half * 2 + 1];
                if (BIAS) { v0 += bias[cc]; v1 += bias[cc + 1]; }
                long base = co + row * (long)ldc + cc;
                if (F32O) { C[base] = v0; C[base + 1] = v1; }
                if (PO) {
                    bf h0 = __float2bfloat16(v0), h1 = __float2bfloat16(v1);
                    *reinterpret_cast<uint32_t*>(Ch + base) = packbf(__bfloat162float(h0), __bfloat162float(h1));
                    *reinterpret_cast<uint32_t*>(Cl + base) = packbf(v0 - __bfloat162float(h0), v1 - __bfloat162float(h1));
                }
            }
        }
}

// ---------- shared attention tile step (scores -> online softmax -> PV) -------
template<bool CAUSAL>
__device__ __forceinline__ void attn_tile(
    uint32_t sbase, uint32_t bo,
    uint32_t (&qh)[4][4], uint32_t (&ql)[4][4],
    float (&o)[8][4], float& mr0, float& mr1, float& l0, float& l1,
    int c0, int row0, int diagRow, float scale, int lane)
{
    int bRow = (lane & 7) + ((lane >> 4) & 1) * 8, bK = ((lane >> 3) & 1) * 8;
    int vRow = (lane & 7) + ((lane >> 3) & 1) * 8, vN = ((lane >> 4) & 1) * 8;

    float s[8][4];
    #pragma unroll
    for (int i = 0; i < 8; ++i)
        #pragma unroll
        for (int q = 0; q < 4; ++q) s[i][q] = 0.f;

    #pragma unroll
    for (int kk = 0; kk < 4; ++kk) {
        uint32_t kh[8][2], kl[8][2];
        #pragma unroll
        for (int np = 0; np < 4; ++np) {
            uint32_t off = bo + (uint32_t)((np * 16 + bRow) * 72 + kk * 16 + bK) * 2;
            uint32_t t[4];
            LDM4(t, sbase + off);
            kh[np*2][0] = t[0]; kh[np*2][1] = t[1]; kh[np*2+1][0] = t[2]; kh[np*2+1][1] = t[3];
            LDM4(t, sbase + 4608 * 2 + off);
            kl[np*2][0] = t[0]; kl[np*2][1] = t[1]; kl[np*2+1][0] = t[2]; kl[np*2+1][1] = t[3];
        }
        #pragma unroll
        for (int nf = 0; nf < 8; ++nf) {
            MMA(s[nf], qh[kk], kh[nf]);
            MMA(s[nf], qh[kk], kl[nf]);
            MMA(s[nf], ql[kk], kh[nf]);
        }
    }
    #pragma unroll
    for (int nf = 0; nf < 8; ++nf) {
        #pragma unroll
        for (int q = 0; q < 4; ++q) s[nf][q] *= scale;
    }
    if (CAUSAL && (c0 + 63 > diagRow)) {
        #pragma unroll
        for (int nf = 0; nf < 8; ++nf) {
            int col = c0 + nf * 8 + (lane & 3) * 2;
            if (col     > row0)     s[nf][0] = -1e30f;
            if (col + 1 > row0)     s[nf][1] = -1e30f;
            if (col     > row0 + 8) s[nf][2] = -1e30f;
            if (col + 1 > row0 + 8) s[nf][3] = -1e30f;
        }
    }
    float t0 = -INFINITY, t1 = -INFINITY;
    #pragma unroll
    for (int nf = 0; nf < 8; ++nf) {
        t0 = fmaxf(t0, fmaxf(s[nf][0], s[nf][1]));
        t1 = fmaxf(t1, fmaxf(s[nf][2], s[nf][3]));
    }
    t0 = fmaxf(t0, __shfl_xor_sync(0xffffffffu, t0, 1));
    t0 = fmaxf(t0, __shfl_xor_sync(0xffffffffu, t0, 2));
    t1 = fmaxf(t1, __shfl_xor_sync(0xffffffffu, t1, 1));
    t1 = fmaxf(t1, __shfl_xor_sync(0xffffffffu, t1, 2));
    float mn0 = fmaxf(mr0, t0), mn1 = fmaxf(mr1, t1);
    float cr0 = __expf(mr0 - mn0), cr1 = __expf(mr1 - mn1);
    float sum0 = 0.f, sum1 = 0.f;
    #pragma unroll
    for (int nf = 0; nf < 8; ++nf) {
        s[nf][0] = __expf(s[nf][0] - mn0);
        s[nf][1] = __expf(s[nf][1] - mn0);
        s[nf][2] = __expf(s[nf][2] - mn1);
        s[nf][3] = __expf(s[nf][3] - mn1);
        sum0 += s[nf][0] + s[nf][1];
        sum1 += s[nf][2] + s[nf][3];
    }
    sum0 += __shfl_xor_sync(0xffffffffu, sum0, 1);
    sum0 += __shfl_xor_sync(0xffffffffu, sum0, 2);
    sum1 += __shfl_xor_sync(0xffffffffu, sum1, 1);
    sum1 += __shfl_xor_sync(0xffffffffu, sum1, 2);
    l0 = l0 * cr0 + sum0; l1 = l1 * cr1 + sum1;
    mr0 = mn0; mr1 = mn1;
    #pragma unroll
    for (int nf = 0; nf < 8; ++nf) {
        o[nf][0] *= cr0; o[nf][1] *= cr0; o[nf][2] *= cr1; o[nf][3] *= cr1;
    }
    #pragma unroll
    for (int kk2 = 0; kk2 < 4; ++kk2) {
        uint32_t Ph[4], Pl[4];
        {
            float a0 = s[2*kk2][0],   a1 = s[2*kk2][1];
            float a2 = s[2*kk2][2],   a3 = s[2*kk2][3];
            float a4 = s[2*kk2+1][0], a5 = s[2*kk2+1][1];
            float a6 = s[2*kk2+1][2], a7 = s[2*kk2+1][3];
            bf h0 = __float2bfloat16(a0), h1 = __float2bfloat16(a1);
            bf h2 = __float2bfloat16(a2), h3 = __float2bfloat16(a3);
            bf h4 = __float2bfloat16(a4), h5 = __float2bfloat16(a5);
            bf h6 = __float2bfloat16(a6), h7 = __float2bfloat16(a7);
            Ph[0] = packbf(__bfloat162float(h0), __bfloat162float(h1));
            Ph[1] = packbf(__bfloat162float(h2), __bfloat162float(h3));
            Ph[2] = packbf(__bfloat162float(h4), __bfloat162float(h5));
            Ph[3] = packbf(__bfloat162float(h6), __bfloat162float(h7));
            Pl[0] = packbf(a0 - __bfloat162float(h0), a1 - __bfloat162float(h1));
            Pl[1] = packbf(a2 - __bfloat162float(h2), a3 - __bfloat162float(h3));
            Pl[2] = packbf(a4 - __bfloat162float(h4), a5 - __bfloat162float(h5));
            Pl[3] = packbf(a6 - __bfloat162float(h6), a7 - __bfloat162float(h7));
        }
        uint32_t vh[8][2], vl[8][2];
        #pragma unroll
        for (int np = 0; np < 4; ++np) {
            uint32_t off = bo + (uint32_t)((kk2 * 16 + vRow) * 72 + np * 16 + vN) * 2;
            uint32_t t[4];
            LDM4T(t, sbase + 9216 * 2 + off);
            vh[np*2][0] = t[0]; vh[np*2][1] = t[1]; vh[np*2+1][0] = t[2]; vh[np*2+1][1] = t[3];
            LDM4T(t, sbase + 13824 * 2 + off);
            vl[np*2][0] = t[0]; vl[np*2][1] = t[1]; vl[np*2+1][0] = t[2]; vl[np*2+1][1] = t[3];
        }
        #pragma unroll
        for (int nf = 0; nf < 8; ++nf) {
            MMA(o[nf], Ph, vh[nf]);
            MMA(o[nf], Ph, vl[nf]);
            MMA(o[nf], Pl, vh[nf]);
        }
    }
}

// prefetch one K/V tile
__device__ __forceinline__ void kv_prefetch(
    uint32_t sbase, uint32_t bn, int c0,
    const bf* pKh, const bf* pKl, int ldk,
    const bf* pVh, const bf* pVl, int ldv, int tid)
{
    int pr = tid >> 3, pch = tid & 7;
    #pragma unroll
    for (int i = 0; i < 2; ++i) {
        int r = pr + i * 32;
        long gk = (long)(c0 + r) * ldk + pch * 8;
        long gv = (long)(c0 + r) * ldv + pch * 8;
        uint32_t so = bn + (uint32_t)(r * 72 + pch * 8) * 2;
        CPA(sbase + so,             pKh + gk);
        CPA(sbase + 4608*2  + so,   pKl + gk);
        CPA(sbase + 9216*2  + so,   pVh + gv);
        CPA(sbase + 13824*2 + so,   pVl + gv);
    }
    CPA_COMMIT();
}

// ---------- single-Q flash (non-causal; cval1), f32 out -----------------------
__global__ void __launch_bounds__(256) fa_k(
    const bf* __restrict__ Ah, const bf* __restrict__ Al, int lda, long sAb, long sAh_,
    const bf* __restrict__ Kh, const bf* __restrict__ Kl, int ldk, long sKb, long sKh_,
    const bf* __restrict__ Vh, const bf* __restrict__ Vl, int ldv, long sVb, long sVh_,
    int S_, float* __restrict__ O, int ldo, long sOb, long sOh_, float scale)
{
    extern __shared__ __align__(16) bf dsm[];
    uint32_t sbase = smem_u32(dsm);

    int z = blockIdx.y, bb = z >> 3, hh = z & 7;
    int m0 = (int)blockIdx.x * 128;
    const bf* pAh = Ah + bb * sAb + hh * sAh_;
    const bf* pAl = Al + bb * sAb + hh * sAh_;
    const bf* pKh = Kh + bb * sKb + hh * sKh_;
    const bf* pKl = Kl + bb * sKb + hh * sKh_;
    const bf* pVh = Vh + bb * sVb + hh * sVh_;
    const bf* pVl = Vl + bb * sVb + hh * sVh_;
    long co = (long)bb * sOb + (long)hh * sOh_;

    int tid = threadIdx.x, lane = tid & 31, wid = tid >> 5;
    int wrow = wid * 16;

    #pragma unroll
    for (int i = 0; i < 4; ++i) {
        int q = tid + i * 256, r = q >> 3, ch = q & 7;
        long go = (long)(m0 + r) * lda + ch * 8;
        *(uint4*)&dsm[r * 72 + ch * 8]        = *(const uint4*)(pAh + go);
        *(uint4*)&dsm[9216 + r * 72 + ch * 8] = *(const uint4*)(pAl + go);
    }
    __syncthreads();
    int aRow = lane & 15, aK = (lane >> 4) * 8;
    uint32_t qh[4][4], ql[4][4];
    #pragma unroll
    for (int kk = 0; kk < 4; ++kk) {
        uint32_t off = (uint32_t)((wrow + aRow) * 72 + kk * 16 + aK) * 2;
        LDM4(qh[kk], sbase + off);
        LDM4(ql[kk], sbase + 9216 * 2 + off);
    }
    __syncthreads();

    float o[8][4];
    #pragma unroll
    for (int i = 0; i < 8; ++i)
        #pragma unroll
        for (int q = 0; q < 4; ++q) o[i][q] = 0.f;
    float mr0 = -INFINITY, mr1 = -INFINITY, l0 = 0.f, l1 = 0.f;

    int nt = S_ >> 6;
    int row0 = m0 + wrow + (lane >> 2);

    kv_prefetch(sbase, 0, 0, pKh, pKl, ldk, pVh, pVl, ldv, tid);

    for (int ct = 0; ct < nt; ++ct) {
        uint32_t bo = (uint32_t)(ct & 1) * 18432u * 2u;
        if (ct + 1 < nt) {
            kv_prefetch(sbase, (uint32_t)((ct + 1) & 1) * 18432u * 2u, (ct + 1) << 6,
                        pKh, pKl, ldk, pVh, pVl, ldv, tid);
            asm volatile("cp.async.wait_group 1;");
        } else {
            asm volatile("cp.async.wait_group 0;");
        }
        __syncthreads();
        attn_tile<false>(sbase, bo, qh, ql, o, mr0, mr1, l0, l1,
                         ct << 6, row0, 0, scale, lane);
        __syncthreads();
    }

    float inv0 = 1.f / l0, inv1 = 1.f / l1;
    #pragma unroll
    for (int nf = 0; nf < 8; ++nf) {
        int col = nf * 8 + (lane & 3) * 2;
        long b0 = co + (long)row0 * ldo + col;
        long b1 = co + (long)(row0 + 8) * ldo + col;
        O[b0] = o[nf][0] * inv0; O[b0 + 1] = o[nf][1] * inv0;
        O[b1] = o[nf][2] * inv1; O[b1 + 1] = o[nf][3] * inv1;
    }
}

// ---------- dual-Q causal flash: cval2 (ACC into O1) + sval; fp32 outs --------
__global__ void __launch_bounds__(256) fa2_k(
    const bf* __restrict__ A1h, const bf* __restrict__ A1l, int lda1, long sA1b, long sA1h,
    const bf* __restrict__ A2h, const bf* __restrict__ A2l, int lda2, long sA2b, long sA2h,
    const bf* __restrict__ Kh, const bf* __restrict__ Kl, int ldk, long sKb, long sKh_,
    const bf* __restrict__ Vh, const bf* __restrict__ Vl, int ldv, long sVb, long sVh_,
    float* __restrict__ O1, float* __restrict__ O2,
    int ldo, long sOb, long sOh_, float scale)
{
    extern __shared__ __align__(16) bf dsm[];
    uint32_t sbase = smem_u32(dsm);

    int z = blockIdx.y, bb = z >> 3, hh = z & 7;
    int m0 = (int)(gridDim.x - 1 - blockIdx.x) * 128;
    const bf* pKh = Kh + bb * sKb + hh * sKh_;
    const bf* pKl = Kl + bb * sKb + hh * sKh_;
    const bf* pVh = Vh + bb * sVb + hh * sVh_;
    const bf* pVl = Vl + bb * sVb + hh * sVh_;
    long co = (long)bb * sOb + (long)hh * sOh_;

    int tid = threadIdx.x, lane = tid & 31, wid = tid >> 5;
    int wrow = wid * 16;
    int aRow = lane & 15, aK = (lane >> 4) * 8;
    uint32_t q1h[4][4], q1l[4][4], q2h[4][4], q2l[4][4];

    {
        const bf* p1h = A1h + bb * sA1b + hh * sA1h;
        const bf* p1l = A1l + bb * sA1b + hh * sA1h;
        #pragma unroll
        for (int i = 0; i < 4; ++i) {
            int q = tid + i * 256, r = q >> 3, ch = q & 7;
            long go = (long)(m0 + r) * lda1 + ch * 8;
            *(uint4*)&dsm[r * 72 + ch * 8]        = *(const uint4*)(p1h + go);
            *(uint4*)&dsm[9216 + r * 72 + ch * 8] = *(const uint4*)(p1l + go);
        }
        __syncthreads();
        #pragma unroll
        for (int kk = 0; kk < 4; ++kk) {
            uint32_t off = (uint32_t)((wrow + aRow) * 72 + kk * 16 + aK) * 2;
            LDM4(q1h[kk], sbase + off);
            LDM4(q1l[kk], sbase + 9216 * 2 + off);
        }
        __syncthreads();
        const bf* p2h = A2h + bb * sA2b + hh * sA2h;
        const bf* p2l = A2l + bb * sA2b + hh * sA2h;
        #pragma unroll
        for (int i = 0; i < 4; ++i) {
            int q = tid + i * 256, r = q >> 3, ch = q & 7;
            long go = (long)(m0 + r) * lda2 + ch * 8;
            *(uint4*)&dsm[r * 72 + ch * 8]        = *(const uint4*)(p2h + go);
            *(uint4*)&dsm[9216 + r * 72 + ch * 8] = *(const uint4*)(p2l + go);
        }
        __syncthreads();
        #pragma unroll
        for (int kk = 0; kk < 4; ++kk) {
            uint32_t off = (uint32_t)((wrow + aRow) * 72 + kk * 16 + aK) * 2;
            LDM4(q2h[kk], sbase + off);
            LDM4(q2l[kk], sbase + 9216 * 2 + off);
        }
        __syncthreads();
    }

    float o1[8][4], o2[8][4];
    #pragma unroll
    for (int i = 0; i < 8; ++i)
        #pragma unroll
        for (int q = 0; q < 4; ++q) { o1[i][q] = 0.f; o2[i][q] = 0.f; }
    float m10 = -INFINITY, m11 = -INFINITY, l10 = 0.f, l11 = 0.f;
    float m20 = -INFINITY, m21 = -INFINITY, l20 = 0.f, l21 = 0.f;

    int nt = (m0 >> 6) + 2;
    int row0 = m0 + wrow + (lane >> 2);
    int diagRow = m0 + wrow;

    kv_prefetch(sbase, 0, 0, pKh, pKl, ldk, pVh, pVl, ldv, tid);

    for (int ct = 0; ct < nt; ++ct) {
        uint32_t bo = (uint32_t)(ct & 1) * 18432u * 2u;
        if (ct + 1 < nt) {
            kv_prefetch(sbase, (uint32_t)((ct + 1) & 1) * 18432u * 2u, (ct + 1) << 6,
                        pKh, pKl, ldk, pVh, pVl, ldv, tid);
            asm volatile("cp.async.wait_group 1;");
        } else {
            asm volatile("cp.async.wait_group 0;");
        }
        __syncthreads();
        int c0 = ct << 6;
        attn_tile<true>(sbase, bo, q1h, q1l, o1, m10, m11, l10, l11, c0, row0, diagRow, scale, lane);
        attn_tile<true>(sbase, bo, q2h, q2l, o2, m20, m21, l20, l21, c0, row0, diagRow, scale, lane);
        __syncthreads();
    }

    float i10 = 1.f / l10, i11 = 1.f / l11, i20 = 1.f / l20, i21 = 1.f / l21;
    #pragma unroll
    for (int nf = 0; nf < 8; ++nf) {
        int col = nf * 8 + (lane & 3) * 2;
        long b0 = co + (long)row0 * ldo + col;
        long b1 = co + (long)(row0 + 8) * ldo + col;
        O1[b0]     = o1[nf][0] * i10 + O1[b0];
        O1[b0 + 1] = o1[nf][1] * i10 + O1[b0 + 1];
        O1[b1]     = o1[nf][2] * i11 + O1[b1];
        O1[b1 + 1] = o1[nf][3] * i11 + O1[b1 + 1];
        O2[b0]     = o2[nf][0] * i20;
        O2[b0 + 1] = o2[nf][1] * i20;
        O2[b1]     = o2[nf][2] * i21;
        O2[b1 + 1] = o2[nf][3] * i21;
    }
}

// ---------- G partials: per (head, 64-row chunk) -> fp32 scratch --------------
// part[(z*8+ck)*4096 + d2*64 + d1] = sum_{m in chunk} k_y[m][d1] * q_y[m][d2]
__global__ void __launch_bounds__(256) g1_k(const bf* __restrict__ qh, const bf* __restrict__ ql,
                                            float* __restrict__ part)
{
    int z = blockIdx.x, ck = blockIdx.y;
    int b = z >> 3, h = z & 7;
    int m0 = ck * 64;
    long kyo = (long)b * Mv * 3 * Cv + (long)h * Dv + Cv;
    long qyo = (long)b * Mv * 3 * Cv + (long)h * Dv;
    __shared__ float sky[64][65], sqy[64][65];
    int tid = threadIdx.x;
    int d2 = tid & 63, gg = tid >> 6;
    float acc[16];
    #pragma unroll
    for (int i = 0; i < 16; ++i) acc[i] = 0.f;
    #pragma unroll
    for (int i = 0; i < 16; ++i) {
        int q = tid + i * 256;
        int mm = q >> 6, dd = q & 63;
        long ik = kyo + (long)(m0 + mm) * 3 * Cv + dd;
        long iq = qyo + (long)(m0 + mm) * 3 * Cv + dd;
        sky[mm][dd] = __bfloat162float(qh[ik]) + __bfloat162float(ql[ik]);
        sqy[mm][dd] = __bfloat162float(qh[iq]) + __bfloat162float(ql[iq]);
    }
    __syncthreads();
    for (int mm = 0; mm < 64; ++mm) {
        float qv = sqy[mm][d2];
        #pragma unroll
        for (int i = 0; i < 16; ++i)
            acc[i] += sky[mm][gg * 16 + i] * qv;
    }
    long base = ((long)z * 8 + ck) * 4096 + (long)d2 * 64 + gg * 16;
    #pragma unroll
    for (int i = 0; i < 16; ++i) part[base + i] = acc[i];
}

// ---------- G reduce: sum 8 chunk partials, scale, emit pair ------------------
__global__ void __launch_bounds__(256) g2_k(const float* __restrict__ part,
                                            bf* __restrict__ goh, bf* __restrict__ gol)
{
    int z = blockIdx.x, tid = threadIdx.x;
    #pragma unroll
    for (int i = 0; i < 16; ++i) {
        int idx = tid + i * 256;
        float s = 0.f;
        #pragma unroll
        for (int ck = 0; ck < 8; ++ck)
            s += part[((long)z * 8 + ck) * 4096 + idx];
        float v = s * (SCL * SCL);
        bf hh = __float2bfloat16(v);
        long o = (long)z * 4096 + idx;
        goh[o] = hh;
        gol[o] = __float2bfloat16(v - __bfloat162float(hh));
    }
}

// ---------- merged weight transpose-splits (5 jobs via blockIdx.y) ------------
__global__ void __launch_bounds__(256) splitW_k(
    const float* __restrict__ w0, const float* __restrict__ w1,
    const float* __restrict__ w2, const float* __restrict__ w3,
    const float* __restrict__ w4, bf* __restrict__ oh, bf* __restrict__ ol)
{
    int job = blockIdx.y;
    const float* src; long off; int Nd;
    switch (job) {
        case 0:  src = w0; off = oWQX; Nd = 3 * Cv; break;
        case 1:  src = w1; off = oWQY; Nd = 3 * Cv; break;
        case 2:  src = w2; off = oWGS; Nd = Cv; break;
        case 3:  src = w3; off = oWGC; Nd = Cv; break;
        default: src = w4; off = oWP;  Nd = Cv; break;
    }
    long n = (long)Cv * Nd;
    long i = (long)blockIdx.x * 256 + threadIdx.x;
    if (i >= n) return;
    int nn = (int)(i / Cv), k = (int)(i % Cv);
    float v = src[(long)k * Nd + nn];
    bf h = __float2bfloat16(v);
    oh[off + i] = h;
    ol[off + i] = __float2bfloat16(v - __bfloat162float(h));
}

// ---------- gate combine (fp32 out) ----------
__global__ void __launch_bounds__(256) gate_k(
    const float* __restrict__ t1, const float* __restrict__ t2,
    const float* __restrict__ bgs, const float* __restrict__ bgc,
    const float* __restrict__ cv, const float* __restrict__ sv,
    float* __restrict__ t3, long n)
{
    long i = (long)blockIdx.x * 256 + threadIdx.x;
    if (i < n) {
        int c = (int)(i & (Cv - 1));
        float g1 = 1.f / (1.f + __expf(-(t1[i] + bgs[c])));
        float g2 = 1.f / (1.f + __expf(-(t2[i] + bgc[c])));
        t3[i] = g1 * cv[i] + g2 * sv[i];
    }
}

// ------------------------------------------------------------------------------
extern "C" void kernel_launch(void* const* d_in, const int* in_sizes, int n_in,
                              void* d_out, int out_size)
{
    const float* x      = (const float*)d_in[0];
    const float* y      = (const float*)d_in[1];
    const float* Wqkv_x = (const float*)d_in[3];
    const float* bqkv_x = (const float*)d_in[4];
    const float* Wqkv_y = (const float*)d_in[5];
    const float* bqkv_y = (const float*)d_in[6];
    const float* Wgs    = (const float*)d_in[7];
    const float* bgs    = (const float*)d_in[8];
    const float* Wgc    = (const float*)d_in[9];
    const float* bgc    = (const float*)d_in[10];
    const float* Wp     = (const float*)d_in[11];
    const float* bp     = (const float*)d_in[12];
    float* out = (float*)d_out;

    bf *gh, *gl; float* gf;
    cudaGetSymbolAddress((void**)&gh, g_h);
    cudaGetSymbolAddress((void**)&gl, g_l);
    cudaGetSymbolAddress((void**)&gf, g_f);

    const int FASM = 2 * 18432 * 2;
    cudaFuncSetAttribute((const void*)fa_k,  cudaFuncAttributeMaxDynamicSharedMemorySize, FASM);
    cudaFuncSetAttribute((const void*)fa2_k, cudaFuncAttributeMaxDynamicSharedMemorySize, FASM);

    dim3 blk(256);
    long nTC = nTCe;

    // all weight transpose-splits in one launch
    splitW_k<<<dim3(3072, 5), blk>>>(Wqkv_x, Wqkv_y, Wgs, Wgc, Wp, gh, gl);

    // qkv projections: A = x / y fp32 directly
    hg<128,true,false,true,true><<<dim3(12,32,1), blk>>>(
        nullptr, nullptr, x, Cv, 0,0, gh+oWQX, gl+oWQX, Cv, 0,0,
        nullptr, gh+oQKVX, gl+oQKVX, 3*Cv, 0,0, bqkv_x, Cv, 1, 1.0f);
    hg<128,true,false,true,true><<<dim3(12,8,1), blk>>>(
        nullptr, nullptr, y, Cv, 0,0, gh+oWQY, gl+oWQY, Cv, 0,0,
        nullptr, gh+oQKVY, gl+oQKVY, 3*Cv, 0,0, bqkv_y, Cv, 1, 1.0f);

    // G: split-K partials then reduce (uses fT1 region as scratch; free here)
    g1_k<<<dim3(BHv, 8), blk>>>(gh+oQKVY, gl+oQKVY, gf+fT1);
    g2_k<<<BHv, blk>>>(gf+fT1, gh+oGT, gl+oGT);

    // qxG = q_x @ G
    hg<64,false,false,true,false><<<dim3(1,16,16), blk>>>(
        gh+oQKVX, gl+oQKVX, nullptr, 3*Cv, (long)Tv*3*Cv, (long)Dv,
        gh+oGT, gl+oGT, 64, (long)Hv*Dv*Dv, (long)Dv*Dv,
        nullptr, gh+oQXG, gl+oQXG, Dv, (long)Hv*Tv*Dv, (long)Tv*Dv, nullptr, Dv, Hv, 1.0f);

    // cval1 = softmax(q_x k_y^T) v_y  (fused, non-causal)
    fa_k<<<dim3(16,16), blk, FASM>>>(
        gh+oQKVX, gl+oQKVX, 3*Cv, (long)Tv*3*Cv, (long)Dv,
        gh+oQKVY+Cv, gl+oQKVY+Cv, 3*Cv, (long)Mv*3*Cv, (long)Dv,
        gh+oQKVY+2*Cv, gl+oQKVY+2*Cv, 3*Cv, (long)Mv*3*Cv, (long)Dv,
        Mv, gf+fCV, Cv, (long)Tv*Cv, (long)Dv, SCL);

    // dual-Q causal: cval += softmax(qxG k_x^T) v_x ; sval = softmax(q_x k_x^T) v_x
    fa2_k<<<dim3(16,16), blk, FASM>>>(
        gh+oQXG, gl+oQXG, Dv, (long)Hv*Tv*Dv, (long)Tv*Dv,
        gh+oQKVX, gl+oQKVX, 3*Cv, (long)Tv*3*Cv, (long)Dv,
        gh+oQKVX+Cv, gl+oQKVX+Cv, 3*Cv, (long)Tv*3*Cv, (long)Dv,
        gh+oQKVX+2*Cv, gl+oQKVX+2*Cv, 3*Cv, (long)Tv*3*Cv, (long)Dv,
        gf+fCV, gf+fSV, Cv, (long)Tv*Cv, (long)Dv, SCL);

    // gates: batched z=2 (t1 = sval@Wgs, t2 = cval@Wgc)
    hg<128,true,true,false,false><<<dim3(4,32,2), blk>>>(
        nullptr, nullptr, gf+fSV, Cv, 0, nTC,
        gh+oWGS, gl+oWGS, Cv, 0, (long)Cv*Cv,
        gf+fT1, nullptr, nullptr, Cv, 0, nTC, nullptr, Cv, 2, 1.0f);

    gate_k<<<(unsigned)((nTC + 255) / 256), blk>>>(
        gf+fT1, gf+fT2, bgs, bgc, gf+fCV, gf+fSV, gf+fT3, nTC);

    // out = t3 @ Wp + bp
    hg<128,true,true,false,true><<<dim3(4,32,1), blk>>>(
        nullptr, nullptr, gf+fT3, Cv, 0,0, gh+oWP, gl+oWP, Cv, 0,0,
        out, nullptr, nullptr, Cv, 0,0, bp, Cv, 1, 1.0f);
}

// round 13
// speedup vs baseline: 1.1408x; 1.0177x over previous
#include <cuda_runtime.h>
#include <cuda_bf16.h>
#include <cstdint>
#include <math.h>

#define BBv 2
#define Tv 2048
#define Mv 512
#define Cv 512
#define Hv 8
#define Dv 64
#define BHv 16
#define SCL 0.125f
#define LOG2E 1.4426950408889634f
typedef __nv_bfloat16 bf;

// ---------- bf16 pair pool offsets ----------
constexpr long oXB   = 0;
constexpr long oYB   = oXB   + (long)BBv*Tv*Cv;
constexpr long oWQX  = oYB   + (long)BBv*Mv*Cv;
constexpr long oWQY  = oWQX  + (long)Cv*3*Cv;
constexpr long oWGS  = oWQY  + (long)Cv*3*Cv;
constexpr long oWGC  = oWGS  + (long)Cv*Cv;
constexpr long oWP   = oWGC  + (long)Cv*Cv;
constexpr long oQKVX = oWP   + (long)Cv*Cv;
constexpr long oQKVY = oQKVX + (long)BBv*Tv*3*Cv;
constexpr long oQXG  = oQKVY + (long)BBv*Mv*3*Cv;
constexpr long oGT   = oQXG  + (long)BHv*Tv*Dv;
constexpr long oSV   = oGT   + (long)BHv*Dv*Dv;
constexpr long oCV   = oSV   + (long)BBv*Tv*Cv;
constexpr long oT3   = oCV   + (long)BBv*Tv*Cv;
constexpr long NBF   = oT3   + (long)BBv*Tv*Cv;
// ---------- fp32 pool ----------
constexpr long nTCe = (long)BBv*Tv*Cv;
constexpr long fSV = 0;
constexpr long fCV = fSV + nTCe;
constexpr long fT1 = fCV + nTCe;      // also G partial scratch early
constexpr long fT2 = fT1 + nTCe;
constexpr long NF_ = fT2 + nTCe;

__device__ bf    g_h[NBF];
__device__ bf    g_l[NBF];
__device__ float g_f[NF_];

// ---------- helpers ----------
__device__ __forceinline__ uint32_t smem_u32(const void* p) {
    uint32_t a;
    asm("{ .reg .u64 t; cvta.to.shared.u64 t, %1; cvt.u32.u64 %0, t; }" : "=r"(a) : "l"(p));
    return a;
}
#define LDM4(r, addr) asm volatile( \
    "ldmatrix.sync.aligned.m8n8.x4.shared.b16 {%0,%1,%2,%3}, [%4];" \
    : "=r"((r)[0]), "=r"((r)[1]), "=r"((r)[2]), "=r"((r)[3]) : "r"(addr))
#define LDM4T(r, addr) asm volatile( \
    "ldmatrix.sync.aligned.m8n8.x4.trans.shared.b16 {%0,%1,%2,%3}, [%4];" \
    : "=r"((r)[0]), "=r"((r)[1]), "=r"((r)[2]), "=r"((r)[3]) : "r"(addr))
#define MMA(c, a, b) asm volatile( \
    "mma.sync.aligned.m16n8k16.row.col.f32.bf16.bf16.f32 " \
    "{%0,%1,%2,%3}, {%4,%5,%6,%7}, {%8,%9}, {%0,%1,%2,%3};" \
    : "+f"((c)[0]), "+f"((c)[1]), "+f"((c)[2]), "+f"((c)[3]) \
    : "r"((a)[0]), "r"((a)[1]), "r"((a)[2]), "r"((a)[3]), "r"((b)[0]), "r"((b)[1]))
#define CPA(sa, ga) asm volatile("cp.async.cg.shared.global [%0], [%1], 16;" :: "r"(sa), "l"(ga))
#define CPA_COMMIT() asm volatile("cp.async.commit_group;")

__device__ __forceinline__ uint32_t packbf(float a, float b) {
    __nv_bfloat162 t; t.x = __float2bfloat16(a); t.y = __float2bfloat16(b);
    return *reinterpret_cast<uint32_t*>(&t);
}

// ---------- pipelined HMMA split-bf16 GEMM: C = alpha*(A@B^T) (+bias) ---------
// A:[M,K] pair, B:[N,K] pair; cp.async double-buffered stages of 32 K.
// Stage layout (elems): Ah@0(5120), Al@5120, Bh@10240(TN*40), Bl@10240+TN*40.
template<int TN, bool F32O, bool PO, bool BIAS>
__global__ void __launch_bounds__(256) hg(
    const bf* __restrict__ Ah, const bf* __restrict__ Al, int lda, long sAb, long sAh_,
    const bf* __restrict__ Bh, const bf* __restrict__ Bl, int ldb, long sBb, long sBh_,
    float* __restrict__ C, bf* __restrict__ Ch, bf* __restrict__ Cl, int ldc, long sCb, long sCh_,
    const float* __restrict__ bias, int K, int Hn, float alpha)
{
    constexpr int NFRAG = TN / 16;
    constexpr uint32_t STG = (10240 + 2 * TN * 40) * 2;   // stage bytes
    extern __shared__ __align__(16) bf dsm[];
    uint32_t sbase = smem_u32(dsm);

    int m0 = blockIdx.y * 128, n0 = blockIdx.x * TN;
    int z = blockIdx.z, bb = z / Hn, hh = z - bb * Hn;
    const bf* pAh = Ah + bb * sAb + hh * sAh_;
    const bf* pAl = Al + bb * sAb + hh * sAh_;
    const bf* pBh = Bh + bb * sBb + hh * sBh_;
    const bf* pBl = Bl + bb * sBb + hh * sBh_;
    long co = bb * sCb + hh * sCh_;

    int tid = threadIdx.x, lane = tid & 31, wid = tid >> 5;
    int wm = (wid & 3) * 32, wn = (wid >> 2) * (TN / 2);

    float acc[2][NFRAG][4];
    #pragma unroll
    for (int i = 0; i < 2; ++i)
        #pragma unroll
        for (int j = 0; j < NFRAG; ++j)
            #pragma unroll
            for (int q = 0; q < 4; ++q) acc[i][j][q] = 0.f;

    int kst = K >> 5;
    int aRow = (lane & 15), aK = (lane >> 4) * 8;
    int bRow = (lane & 7) + ((lane >> 4) & 1) * 8, bK = ((lane >> 3) & 1) * 8;

    // prefetch lane mapping: idx over 512 chunks (A) resp TN*4 chunks (B)
    auto prefetch = [&](int s) {
        uint32_t st = sbase + (uint32_t)(s & 1) * STG;
        int k0 = s << 5;
        #pragma unroll
        for (int i = 0; i < 2; ++i) {
            int idx = tid + i * 256;          // 0..511
            int r = idx >> 2, c = idx & 3;
            long go = (long)(m0 + r) * lda + k0 + c * 8;
            uint32_t so = (uint32_t)(r * 40 + c * 8) * 2;
            CPA(st + so,            pAh + go);
            CPA(st + 5120*2 + so,   pAl + go);
        }
        #pragma unroll
        for (int i = 0; i < TN / 64; ++i) {
            int idx = tid + i * 256;
            int r = idx >> 2, c = idx & 3;
            long go = (long)(n0 + r) * ldb + k0 + c * 8;
            uint32_t so = (uint32_t)(r * 40 + c * 8) * 2;
            CPA(st + 10240*2 + so,             pBh + go);
            CPA(st + (10240 + TN*40)*2 + so,   pBl + go);
        }
        CPA_COMMIT();
    };

    prefetch(0);

    for (int s = 0; s < kst; ++s) {
        if (s + 1 < kst) {
            prefetch(s + 1);
            asm volatile("cp.async.wait_group 1;");
        } else {
            asm volatile("cp.async.wait_group 0;");
        }
        __syncthreads();
        uint32_t st = sbase + (uint32_t)(s & 1) * STG;

        #pragma unroll
        for (int kk = 0; kk < 2; ++kk) {
            uint32_t ah[2][4], al[2][4];
            #pragma unroll
            for (int mf = 0; mf < 2; ++mf) {
                uint32_t off = (uint32_t)((wm + mf * 16 + aRow) * 40 + kk * 16 + aK) * 2;
                LDM4(ah[mf], st + off);
                LDM4(al[mf], st + 5120*2 + off);
            }
            uint32_t bh[NFRAG][2], bl[NFRAG][2];
            #pragma unroll
            for (int np = 0; np < NFRAG / 2; ++np) {
                uint32_t off = (uint32_t)((wn + np * 16 + bRow) * 40 + kk * 16 + bK) * 2;
                uint32_t t[4];
                LDM4(t, st + 10240*2 + off);
                bh[np*2][0] = t[0]; bh[np*2][1] = t[1]; bh[np*2+1][0] = t[2]; bh[np*2+1][1] = t[3];
                LDM4(t, st + (10240 + TN*40)*2 + off);
                bl[np*2][0] = t[0]; bl[np*2][1] = t[1]; bl[np*2+1][0] = t[2]; bl[np*2+1][1] = t[3];
            }
            #pragma unroll
            for (int mf = 0; mf < 2; ++mf)
                #pragma unroll
                for (int nf = 0; nf < NFRAG; ++nf) {
                    MMA(acc[mf][nf], ah[mf], bh[nf]);
                    MMA(acc[mf][nf], ah[mf], bl[nf]);
                    MMA(acc[mf][nf], al[mf], bh[nf]);
                }
        }
        __syncthreads();
    }

    int rb = m0 + wm + (lane >> 2);
    int cb = n0 + wn + (lane & 3) * 2;
    #pragma unroll
    for (int mf = 0; mf < 2; ++mf)
        #pragma unroll
        for (int half = 0; half < 2; ++half) {
            long row = rb + mf * 16 + half * 8;
            #pragma unroll
            for (int nf = 0; nf < NFRAG; ++nf) {
                int cc = cb + nf * 8;
                float v0 = alpha * acc[mf][nf][half * 2 + 0];
                float v1 = alpha * acc[mf][nf][half * 2 + 1];
                if (BIAS) { v0 += bias[cc]; v1 += bias[cc + 1]; }
                long base = co + row * (long)ldc + cc;
                if (F32O) { C[base] = v0; C[base + 1] = v1; }
                if (PO) {
                    bf h0 = __float2bfloat16(v0), h1 = __float2bfloat16(v1);
                    *reinterpret_cast<uint32_t*>(Ch + base) = packbf(__bfloat162float(h0), __bfloat162float(h1));
                    *reinterpret_cast<uint32_t*>(Cl + base) = packbf(v0 - __bfloat162float(h0), v1 - __bfloat162float(h1));
                }
            }
        }
}

// ---------- shared attention tile step (scale pre-folded with log2e) ----------
template<bool CAUSAL>
__device__ __forceinline__ void attn_tile(
    uint32_t sbase, uint32_t bo,
    uint32_t (&qh)[4][4], uint32_t (&ql)[4][4],
    float (&o)[8][4], float& mr0, float& mr1, float& l0, float& l1,
    int c0, int row0, int diagRow, float scale, int lane)
{
    int bRow = (lane & 7) + ((lane >> 4) & 1) * 8, bK = ((lane >> 3) & 1) * 8;
    int vRow = (lane & 7) + ((lane >> 3) & 1) * 8, vN = ((lane >> 4) & 1) * 8;

    float s[8][4];
    #pragma unroll
    for (int i = 0; i < 8; ++i)
        #pragma unroll
        for (int q = 0; q < 4; ++q) s[i][q] = 0.f;

    #pragma unroll
    for (int kk = 0; kk < 4; ++kk) {
        uint32_t kh[8][2], kl[8][2];
        #pragma unroll
        for (int np = 0; np < 4; ++np) {
            uint32_t off = bo + (uint32_t)((np * 16 + bRow) * 72 + kk * 16 + bK) * 2;
            uint32_t t[4];
            LDM4(t, sbase + off);
            kh[np*2][0] = t[0]; kh[np*2][1] = t[1]; kh[np*2+1][0] = t[2]; kh[np*2+1][1] = t[3];
            LDM4(t, sbase + 4608 * 2 + off);
            kl[np*2][0] = t[0]; kl[np*2][1] = t[1]; kl[np*2+1][0] = t[2]; kl[np*2+1][1] = t[3];
        }
        #pragma unroll
        for (int nf = 0; nf < 8; ++nf) {
            MMA(s[nf], qh[kk], kh[nf]);
            MMA(s[nf], qh[kk], kl[nf]);
            MMA(s[nf], ql[kk], kh[nf]);
        }
    }
    #pragma unroll
    for (int nf = 0; nf < 8; ++nf) {
        #pragma unroll
        for (int q = 0; q < 4; ++q) s[nf][q] *= scale;
    }
    if (CAUSAL && (c0 + 63 > diagRow)) {
        #pragma unroll
        for (int nf = 0; nf < 8; ++nf) {
            int col = c0 + nf * 8 + (lane & 3) * 2;
            if (col     > row0)     s[nf][0] = -1e30f;
            if (col + 1 > row0)     s[nf][1] = -1e30f;
            if (col     > row0 + 8) s[nf][2] = -1e30f;
            if (col + 1 > row0 + 8) s[nf][3] = -1e30f;
        }
    }
    float t0 = -INFINITY, t1 = -INFINITY;
    #pragma unroll
    for (int nf = 0; nf < 8; ++nf) {
        t0 = fmaxf(t0, fmaxf(s[nf][0], s[nf][1]));
        t1 = fmaxf(t1, fmaxf(s[nf][2], s[nf][3]));
    }
    t0 = fmaxf(t0, __shfl_xor_sync(0xffffffffu, t0, 1));
    t0 = fmaxf(t0, __shfl_xor_sync(0xffffffffu, t0, 2));
    t1 = fmaxf(t1, __shfl_xor_sync(0xffffffffu, t1, 1));
    t1 = fmaxf(t1, __shfl_xor_sync(0xffffffffu, t1, 2));
    float mn0 = fmaxf(mr0, t0), mn1 = fmaxf(mr1, t1);
    float cr0 = exp2f(mr0 - mn0), cr1 = exp2f(mr1 - mn1);
    float sum0 = 0.f, sum1 = 0.f;
    #pragma unroll
    for (int nf = 0; nf < 8; ++nf) {
        s[nf][0] = exp2f(s[nf][0] - mn0);
        s[nf][1] = exp2f(s[nf][1] - mn0);
        s[nf][2] = exp2f(s[nf][2] - mn1);
        s[nf][3] = exp2f(s[nf][3] - mn1);
        sum0 += s[nf][0] + s[nf][1];
        sum1 += s[nf][2] + s[nf][3];
    }
    sum0 += __shfl_xor_sync(0xffffffffu, sum0, 1);
    sum0 += __shfl_xor_sync(0xffffffffu, sum0, 2);
    sum1 += __shfl_xor_sync(0xffffffffu, sum1, 1);
    sum1 += __shfl_xor_sync(0xffffffffu, sum1, 2);
    l0 = l0 * cr0 + sum0; l1 = l1 * cr1 + sum1;
    mr0 = mn0; mr1 = mn1;
    #pragma unroll
    for (int nf = 0; nf < 8; ++nf) {
        o[nf][0] *= cr0; o[nf][1] *= cr0; o[nf][2] *= cr1; o[nf][3] *= cr1;
    }
    #pragma unroll
    for (int kk2 = 0; kk2 < 4; ++kk2) {
        uint32_t Ph[4], Pl[4];
        {
            float a0 = s[2*kk2][0],   a1 = s[2*kk2][1];
            float a2 = s[2*kk2][2],   a3 = s[2*kk2][3];
            float a4 = s[2*kk2+1][0], a5 = s[2*kk2+1][1];
            float a6 = s[2*kk2+1][2], a7 = s[2*kk2+1][3];
            bf h0 = __float2bfloat16(a0), h1 = __float2bfloat16(a1);
            bf h2 = __float2bfloat16(a2), h3 = __float2bfloat16(a3);
            bf h4 = __float2bfloat16(a4), h5 = __float2bfloat16(a5);
            bf h6 = __float2bfloat16(a6), h7 = __float2bfloat16(a7);
            Ph[0] = packbf(__bfloat162float(h0), __bfloat162float(h1));
            Ph[1] = packbf(__bfloat162float(h2), __bfloat162float(h3));
            Ph[2] = packbf(__bfloat162float(h4), __bfloat162float(h5));
            Ph[3] = packbf(__bfloat162float(h6), __bfloat162float(h7));
            Pl[0] = packbf(a0 - __bfloat162float(h0), a1 - __bfloat162float(h1));
            Pl[1] = packbf(a2 - __bfloat162float(h2), a3 - __bfloat162float(h3));
            Pl[2] = packbf(a4 - __bfloat162float(h4), a5 - __bfloat162float(h5));
            Pl[3] = packbf(a6 - __bfloat162float(h6), a7 - __bfloat162float(h7));
        }
        uint32_t vh[8][2], vl[8][2];
        #pragma unroll
        for (int np = 0; np < 4; ++np) {
            uint32_t off = bo + (uint32_t)((kk2 * 16 + vRow) * 72 + np * 16 + vN) * 2;
            uint32_t t[4];
            LDM4T(t, sbase + 9216 * 2 + off);
            vh[np*2][0] = t[0]; vh[np*2][1] = t[1]; vh[np*2+1][0] = t[2]; vh[np*2+1][1] = t[3];
            LDM4T(t, sbase + 13824 * 2 + off);
            vl[np*2][0] = t[0]; vl[np*2][1] = t[1]; vl[np*2+1][0] = t[2]; vl[np*2+1][1] = t[3];
        }
        #pragma unroll
        for (int nf = 0; nf < 8; ++nf) {
            MMA(o[nf], Ph, vh[nf]);
            MMA(o[nf], Ph, vl[nf]);
            MMA(o[nf], Pl, vh[nf]);
        }
    }
}

// prefetch one K/V tile
__device__ __forceinline__ void kv_prefetch(
    uint32_t sbase, uint32_t bn, int c0,
    const bf* pKh, const bf* pKl, int ldk,
    const bf* pVh, const bf* pVl, int ldv, int tid)
{
    int pr = tid >> 3, pch = tid & 7;
    #pragma unroll
    for (int i = 0; i < 2; ++i) {
        int r = pr + i * 32;
        long gk = (long)(c0 + r) * ldk + pch * 8;
        long gv = (long)(c0 + r) * ldv + pch * 8;
        uint32_t so = bn + (uint32_t)(r * 72 + pch * 8) * 2;
        CPA(sbase + so,             pKh + gk);
        CPA(sbase + 4608*2  + so,   pKl + gk);
        CPA(sbase + 9216*2  + so,   pVh + gv);
        CPA(sbase + 13824*2 + so,   pVl + gv);
    }
    CPA_COMMIT();
}

// ---------- single-Q flash (non-causal; cval1), f32 out -----------------------
__global__ void __launch_bounds__(256) fa_k(
    const bf* __restrict__ Ah, const bf* __restrict__ Al, int lda, long sAb, long sAh_,
    const bf* __restrict__ Kh, const bf* __restrict__ Kl, int ldk, long sKb, long sKh_,
    const bf* __restrict__ Vh, const bf* __restrict__ Vl, int ldv, long sVb, long sVh_,
    int S_, float* __restrict__ O, int ldo, long sOb, long sOh_, float scale)
{
    extern __shared__ __align__(16) bf dsm[];
    uint32_t sbase = smem_u32(dsm);

    int z = blockIdx.y, bb = z >> 3, hh = z & 7;
    int m0 = (int)blockIdx.x * 128;
    const bf* pAh = Ah + bb * sAb + hh * sAh_;
    const bf* pAl = Al + bb * sAb + hh * sAh_;
    const bf* pKh = Kh + bb * sKb + hh * sKh_;
    const bf* pKl = Kl + bb * sKb + hh * sKh_;
    const bf* pVh = Vh + bb * sVb + hh * sVh_;
    const bf* pVl = Vl + bb * sVb + hh * sVh_;
    long co = (long)bb * sOb + (long)hh * sOh_;

    int tid = threadIdx.x, lane = tid & 31, wid = tid >> 5;
    int wrow = wid * 16;

    #pragma unroll
    for (int i = 0; i < 4; ++i) {
        int q = tid + i * 256, r = q >> 3, ch = q & 7;
        long go = (long)(m0 + r) * lda + ch * 8;
        *(uint4*)&dsm[r * 72 + ch * 8]        = *(const uint4*)(pAh + go);
        *(uint4*)&dsm[9216 + r * 72 + ch * 8] = *(const uint4*)(pAl + go);
    }
    __syncthreads();
    int aRow = lane & 15, aK = (lane >> 4) * 8;
    uint32_t qh[4][4], ql[4][4];
    #pragma unroll
    for (int kk = 0; kk < 4; ++kk) {
        uint32_t off = (uint32_t)((wrow + aRow) * 72 + kk * 16 + aK) * 2;
        LDM4(qh[kk], sbase + off);
        LDM4(ql[kk], sbase + 9216 * 2 + off);
    }
    __syncthreads();

    float o[8][4];
    #pragma unroll
    for (int i = 0; i < 8; ++i)
        #pragma unroll
        for (int q = 0; q < 4; ++q) o[i][q] = 0.f;
    float mr0 = -INFINITY, mr1 = -INFINITY, l0 = 0.f, l1 = 0.f;

    int nt = S_ >> 6;
    int row0 = m0 + wrow + (lane >> 2);

    kv_prefetch(sbase, 0, 0, pKh, pKl, ldk, pVh, pVl, ldv, tid);

    for (int ct = 0; ct < nt; ++ct) {
        uint32_t bo = (uint32_t)(ct & 1) * 18432u * 2u;
        if (ct + 1 < nt) {
            kv_prefetch(sbase, (uint32_t)((ct + 1) & 1) * 18432u * 2u, (ct + 1) << 6,
                        pKh, pKl, ldk, pVh, pVl, ldv, tid);
            asm volatile("cp.async.wait_group 1;");
        } else {
            asm volatile("cp.async.wait_group 0;");
        }
        __syncthreads();
        attn_tile<false>(sbase, bo, qh, ql, o, mr0, mr1, l0, l1,
                         ct << 6, row0, 0, scale, lane);
        __syncthreads();
    }

    float inv0 = 1.f / l0, inv1 = 1.f / l1;
    #pragma unroll
    for (int nf = 0; nf < 8; ++nf) {
        int col = nf * 8 + (lane & 3) * 2;
        long b0 = co + (long)row0 * ldo + col;
        long b1 = co + (long)(row0 + 8) * ldo + col;
        O[b0] = o[nf][0] * inv0; O[b0 + 1] = o[nf][1] * inv0;
        O[b1] = o[nf][2] * inv1; O[b1 + 1] = o[nf][3] * inv1;
    }
}

// ---------- dual-Q causal flash: cval (ACC + pair) + sval (f32 + pair) --------
__global__ void __launch_bounds__(256) fa2_k(
    const bf* __restrict__ A1h, const bf* __restrict__ A1l, int lda1, long sA1b, long sA1h,
    const bf* __restrict__ A2h, const bf* __restrict__ A2l, int lda2, long sA2b, long sA2h,
    const bf* __restrict__ Kh, const bf* __restrict__ Kl, int ldk, long sKb, long sKh_,
    const bf* __restrict__ Vh, const bf* __restrict__ Vl, int ldv, long sVb, long sVh_,
    float* __restrict__ O1, bf* __restrict__ O1h, bf* __restrict__ O1l,
    float* __restrict__ O2, bf* __restrict__ O2h, bf* __restrict__ O2l,
    int ldo, long sOb, long sOh_, float scale)
{
    extern __shared__ __align__(16) bf dsm[];
    uint32_t sbase = smem_u32(dsm);

    int z = blockIdx.y, bb = z >> 3, hh = z & 7;
    int m0 = (int)(gridDim.x - 1 - blockIdx.x) * 128;
    const bf* pKh = Kh + bb * sKb + hh * sKh_;
    const bf* pKl = Kl + bb * sKb + hh * sKh_;
    const bf* pVh = Vh + bb * sVb + hh * sVh_;
    const bf* pVl = Vl + bb * sVb + hh * sVh_;
    long co = (long)bb * sOb + (long)hh * sOh_;

    int tid = threadIdx.x, lane = tid & 31, wid = tid >> 5;
    int wrow = wid * 16;
    int aRow = lane & 15, aK = (lane >> 4) * 8;
    uint32_t q1h[4][4], q1l[4][4], q2h[4][4], q2l[4][4];

    {
        const bf* p1h = A1h + bb * sA1b + hh * sA1h;
        const bf* p1l = A1l + bb * sA1b + hh * sA1h;
        #pragma unroll
        for (int i = 0; i < 4; ++i) {
            int q = tid + i * 256, r = q >> 3, ch = q & 7;
            long go = (long)(m0 + r) * lda1 + ch * 8;
            *(uint4*)&dsm[r * 72 + ch * 8]        = *(const uint4*)(p1h + go);
            *(uint4*)&dsm[9216 + r * 72 + ch * 8] = *(const uint4*)(p1l + go);
        }
        __syncthreads();
        #pragma unroll
        for (int kk = 0; kk < 4; ++kk) {
            uint32_t off = (uint32_t)((wrow + aRow) * 72 + kk * 16 + aK) * 2;
            LDM4(q1h[kk], sbase + off);
            LDM4(q1l[kk], sbase + 9216 * 2 + off);
        }
        __syncthreads();
        const bf* p2h = A2h + bb * sA2b + hh * sA2h;
        const bf* p2l = A2l + bb * sA2b + hh * sA2h;
        #pragma unroll
        for (int i = 0; i < 4; ++i) {
            int q = tid + i * 256, r = q >> 3, ch = q & 7;
            long go = (long)(m0 + r) * lda2 + ch * 8;
            *(uint4*)&dsm[r * 72 + ch * 8]        = *(const uint4*)(p2h + go);
            *(uint4*)&dsm[9216 + r * 72 + ch * 8] = *(const uint4*)(p2l + go);
        }
        __syncthreads();
        #pragma unroll
        for (int kk = 0; kk < 4; ++kk) {
            uint32_t off = (uint32_t)((wrow + aRow) * 72 + kk * 16 + aK) * 2;
            LDM4(q2h[kk], sbase + off);
            LDM4(q2l[kk], sbase + 9216 * 2 + off);
        }
        __syncthreads();
    }

    float o1[8][4], o2[8][4];
    #pragma unroll
    for (int i = 0; i < 8; ++i)
        #pragma unroll
        for (int q = 0; q < 4; ++q) { o1[i][q] = 0.f; o2[i][q] = 0.f; }
    float m10 = -INFINITY, m11 = -INFINITY, l10 = 0.f, l11 = 0.f;
    float m20 = -INFINITY, m21 = -INFINITY, l20 = 0.f, l21 = 0.f;

    int nt = (m0 >> 6) + 2;
    int row0 = m0 + wrow + (lane >> 2);
    int diagRow = m0 + wrow;

    kv_prefetch(sbase, 0, 0, pKh, pKl, ldk, pVh, pVl, ldv, tid);

    for (int ct = 0; ct < nt; ++ct) {
        uint32_t bo = (uint32_t)(ct & 1) * 18432u * 2u;
        if (ct + 1 < nt) {
            kv_prefetch(sbase, (uint32_t)((ct + 1) & 1) * 18432u * 2u, (ct + 1) << 6,
                        pKh, pKl, ldk, pVh, pVl, ldv, tid);
            asm volatile("cp.async.wait_group 1;");
        } else {
            asm volatile("cp.async.wait_group 0;");
        }
        __syncthreads();
        int c0 = ct << 6;
        attn_tile<true>(sbase, bo, q1h, q1l, o1, m10, m11, l10, l11, c0, row0, diagRow, scale, lane);
        attn_tile<true>(sbase, bo, q2h, q2l, o2, m20, m21, l20, l21, c0, row0, diagRow, scale, lane);
        __syncthreads();
    }

    float i10 = 1.f / l10, i11 = 1.f / l11, i20 = 1.f / l20, i21 = 1.f / l21;
    #pragma unroll
    for (int nf = 0; nf < 8; ++nf) {
        int col = nf * 8 + (lane & 3) * 2;
        long b0 = co + (long)row0 * ldo + col;
        long b1 = co + (long)(row0 + 8) * ldo + col;
        float v0 = o1[nf][0] * i10 + O1[b0], v1 = o1[nf][1] * i10 + O1[b0 + 1];
        float v2 = o1[nf][2] * i11 + O1[b1], v3 = o1[nf][3] * i11 + O1[b1 + 1];
        O1[b0] = v0; O1[b0 + 1] = v1; O1[b1] = v2; O1[b1 + 1] = v3;
        bf h0 = __float2bfloat16(v0), h1 = __float2bfloat16(v1);
        bf h2 = __float2bfloat16(v2), h3 = __float2bfloat16(v3);
        *reinterpret_cast<uint32_t*>(O1h + b0) = packbf(__bfloat162float(h0), __bfloat162float(h1));
        *reinterpret_cast<uint32_t*>(O1h + b1) = packbf(__bfloat162float(h2), __bfloat162float(h3));
        *reinterpret_cast<uint32_t*>(O1l + b0) = packbf(v0 - __bfloat162float(h0), v1 - __bfloat162float(h1));
        *reinterpret_cast<uint32_t*>(O1l + b1) = packbf(v2 - __bfloat162float(h2), v3 - __bfloat162float(h3));
        float w0 = o2[nf][0] * i20, w1 = o2[nf][1] * i20;
        float w2 = o2[nf][2] * i21, w3 = o2[nf][3] * i21;
        O2[b0] = w0; O2[b0 + 1] = w1; O2[b1] = w2; O2[b1 + 1] = w3;
        bf g0 = __float2bfloat16(w0), g1 = __float2bfloat16(w1);
        bf g2 = __float2bfloat16(w2), g3 = __float2bfloat16(w3);
        *reinterpret_cast<uint32_t*>(O2h + b0) = packbf(__bfloat162float(g0), __bfloat162float(g1));
        *reinterpret_cast<uint32_t*>(O2h + b1) = packbf(__bfloat162float(g2), __bfloat162float(g3));
        *reinterpret_cast<uint32_t*>(O2l + b0) = packbf(w0 - __bfloat162float(g0), w1 - __bfloat162float(g1));
        *reinterpret_cast<uint32_t*>(O2l + b1) = packbf(w2 - __bfloat162float(g2), w3 - __bfloat162float(g3));
    }
}

// ---------- G partials + reduce ----------
__global__ void __launch_bounds__(256) g1_k(const bf* __restrict__ qh, const bf* __restrict__ ql,
                                            float* __restrict__ part)
{
    int z = blockIdx.x, ck = blockIdx.y;
    int b = z >> 3, h = z & 7;
    int m0 = ck * 64;
    long kyo = (long)b * Mv * 3 * Cv + (long)h * Dv + Cv;
    long qyo = (long)b * Mv * 3 * Cv + (long)h * Dv;
    __shared__ float sky[64][65], sqy[64][65];
    int tid = threadIdx.x;
    int d2 = tid & 63, gg = tid >> 6;
    float acc[16];
    #pragma unroll
    for (int i = 0; i < 16; ++i) acc[i] = 0.f;
    #pragma unroll
    for (int i = 0; i < 16; ++i) {
        int q = tid + i * 256;
        int mm = q >> 6, dd = q & 63;
        long ik = kyo + (long)(m0 + mm) * 3 * Cv + dd;
        long iq = qyo + (long)(m0 + mm) * 3 * Cv + dd;
        sky[mm][dd] = __bfloat162float(qh[ik]) + __bfloat162float(ql[ik]);
        sqy[mm][dd] = __bfloat162float(qh[iq]) + __bfloat162float(ql[iq]);
    }
    __syncthreads();
    for (int mm = 0; mm < 64; ++mm) {
        float qv = sqy[mm][d2];
        #pragma unroll
        for (int i = 0; i < 16; ++i)
            acc[i] += sky[mm][gg * 16 + i] * qv;
    }
    long base = ((long)z * 8 + ck) * 4096 + (long)d2 * 64 + gg * 16;
    #pragma unroll
    for (int i = 0; i < 16; ++i) part[base + i] = acc[i];
}
__global__ void __launch_bounds__(256) g2_k(const float* __restrict__ part,
                                            bf* __restrict__ goh, bf* __restrict__ gol)
{
    int z = blockIdx.x, tid = threadIdx.x;
    #pragma unroll
    for (int i = 0; i < 16; ++i) {
        int idx = tid + i * 256;
        float s = 0.f;
        #pragma unroll
        for (int ck = 0; ck < 8; ++ck)
            s += part[((long)z * 8 + ck) * 4096 + idx];
        float v = s * (SCL * SCL);
        bf hh = __float2bfloat16(v);
        long o = (long)z * 4096 + idx;
        goh[o] = hh;
        gol[o] = __float2bfloat16(v - __bfloat162float(hh));
    }
}

// ---------- splits ----------
__global__ void __launch_bounds__(256) split_k(const float* __restrict__ in, bf* __restrict__ oh,
                                               bf* __restrict__ ol, long n) {
    long i = (long)blockIdx.x * 256 + threadIdx.x;
    if (i < n) {
        float v = in[i]; bf h = __float2bfloat16(v);
        oh[i] = h; ol[i] = __float2bfloat16(v - __bfloat162float(h));
    }
}
__global__ void __launch_bounds__(256) splitW_k(
    const float* __restrict__ w0, const float* __restrict__ w1,
    const float* __restrict__ w2, const float* __restrict__ w3,
    const float* __restrict__ w4, bf* __restrict__ oh, bf* __restrict__ ol)
{
    int job = blockIdx.y;
    const float* src; long off; int Nd;
    switch (job) {
        case 0:  src = w0; off = oWQX; Nd = 3 * Cv; break;
        case 1:  src = w1; off = oWQY; Nd = 3 * Cv; break;
        case 2:  src = w2; off = oWGS; Nd = Cv; break;
        case 3:  src = w3; off = oWGC; Nd = Cv; break;
        default: src = w4; off = oWP;  Nd = Cv; break;
    }
    long n = (long)Cv * Nd;
    long i = (long)blockIdx.x * 256 + threadIdx.x;
    if (i >= n) return;
    int nn = (int)(i / Cv), k = (int)(i % Cv);
    float v = src[(long)k * Nd + nn];
    bf h = __float2bfloat16(v);
    oh[off + i] = h;
    ol[off + i] = __float2bfloat16(v - __bfloat162float(h));
}

// ---------- gate combine (pair out) ----------
__global__ void __launch_bounds__(256) gate_k(
    const float* __restrict__ t1, const float* __restrict__ t2,
    const float* __restrict__ bgs, const float* __restrict__ bgc,
    const float* __restrict__ cv, const float* __restrict__ sv,
    bf* __restrict__ oh, bf* __restrict__ ol, long n)
{
    long i = (long)blockIdx.x * 256 + threadIdx.x;
    if (i < n) {
        int c = (int)(i & (Cv - 1));
        float g1 = 1.f / (1.f + __expf(-(t1[i] + bgs[c])));
        float g2 = 1.f / (1.f + __expf(-(t2[i] + bgc[c])));
        float v = g1 * cv[i] + g2 * sv[i];
        bf h = __float2bfloat16(v);
        oh[i] = h; ol[i] = __float2bfloat16(v - __bfloat162float(h));
    }
}

// ------------------------------------------------------------------------------
extern "C" void kernel_launch(void* const* d_in, const int* in_sizes, int n_in,
                              void* d_out, int out_size)
{
    const float* x      = (const float*)d_in[0];
    const float* y      = (const float*)d_in[1];
    const float* Wqkv_x = (const float*)d_in[3];
    const float* bqkv_x = (const float*)d_in[4];
    const float* Wqkv_y = (const float*)d_in[5];
    const float* bqkv_y = (const float*)d_in[6];
    const float* Wgs    = (const float*)d_in[7];
    const float* bgs    = (const float*)d_in[8];
    const float* Wgc    = (const float*)d_in[9];
    const float* bgc    = (const float*)d_in[10];
    const float* Wp     = (const float*)d_in[11];
    const float* bp     = (const float*)d_in[12];
    float* out = (float*)d_out;

    bf *gh, *gl; float* gf;
    cudaGetSymbolAddress((void**)&gh, g_h);
    cudaGetSymbolAddress((void**)&gl, g_l);
    cudaGetSymbolAddress((void**)&gf, g_f);

    const int FASM   = 2 * 18432 * 2;                 // 73728 B (flash)
    const int HGSM128 = 2 * (10240 + 2 * 128 * 40) * 2;  // 81920 B
    const int HGSM64  = 2 * (10240 + 2 * 64 * 40) * 2;   // 61440 B
    cudaFuncSetAttribute((const void*)fa_k,  cudaFuncAttributeMaxDynamicSharedMemorySize, FASM);
    cudaFuncSetAttribute((const void*)fa2_k, cudaFuncAttributeMaxDynamicSharedMemorySize, FASM);
    cudaFuncSetAttribute((const void*)hg<128,false,true,true>,  cudaFuncAttributeMaxDynamicSharedMemorySize, HGSM128);
    cudaFuncSetAttribute((const void*)hg<128,true,false,false>, cudaFuncAttributeMaxDynamicSharedMemorySize, HGSM128);
    cudaFuncSetAttribute((const void*)hg<128,true,false,true>,  cudaFuncAttributeMaxDynamicSharedMemorySize, HGSM128);
    cudaFuncSetAttribute((const void*)hg<64,false,true,false>,  cudaFuncAttributeMaxDynamicSharedMemorySize, HGSM64);

    dim3 blk(256);
    long nTC = nTCe;

    // splits
    splitW_k<<<dim3(3072, 5), blk>>>(Wqkv_x, Wqkv_y, Wgs, Wgc, Wp, gh, gl);
    split_k<<<(unsigned)((nTC + 255) / 256), blk>>>(x, gh + oXB, gl + oXB, nTC);
    split_k<<<(unsigned)((BBv*Mv*Cv + 255) / 256), blk>>>(y, gh + oYB, gl + oYB, (long)BBv*Mv*Cv);

    // qkv projections (pipelined hg, pair out)
    hg<128,false,true,true><<<dim3(12,32,1), blk, HGSM128>>>(
        gh+oXB, gl+oXB, Cv, 0,0, gh+oWQX, gl+oWQX, Cv, 0,0,
        nullptr, gh+oQKVX, gl+oQKVX, 3*Cv, 0,0, bqkv_x, Cv, 1, 1.0f);
    hg<128,false,true,true><<<dim3(12,8,1), blk, HGSM128>>>(
        gh+oYB, gl+oYB, Cv, 0,0, gh+oWQY, gl+oWQY, Cv, 0,0,
        nullptr, gh+oQKVY, gl+oQKVY, 3*Cv, 0,0, bqkv_y, Cv, 1, 1.0f);

    // G (split-K) then qxG
    g1_k<<<dim3(BHv, 8), blk>>>(gh+oQKVY, gl+oQKVY, gf+fT1);
    g2_k<<<BHv, blk>>>(gf+fT1, gh+oGT, gl+oGT);
    hg<64,false,true,false><<<dim3(1,16,16), blk, HGSM64>>>(
        gh+oQKVX, gl+oQKVX, 3*Cv, (long)Tv*3*Cv, (long)Dv,
        gh+oGT, gl+oGT, 64, (long)Hv*Dv*Dv, (long)Dv*Dv,
        nullptr, gh+oQXG, gl+oQXG, Dv, (long)Hv*Tv*Dv, (long)Tv*Dv, nullptr, Dv, Hv, 1.0f);

    // cval1 (fused, non-causal); scale folded with log2e
    fa_k<<<dim3(16,16), blk, FASM>>>(
        gh+oQKVX, gl+oQKVX, 3*Cv, (long)Tv*3*Cv, (long)Dv,
        gh+oQKVY+Cv, gl+oQKVY+Cv, 3*Cv, (long)Mv*3*Cv, (long)Dv,
        gh+oQKVY+2*Cv, gl+oQKVY+2*Cv, 3*Cv, (long)Mv*3*Cv, (long)Dv,
        Mv, gf+fCV, Cv, (long)Tv*Cv, (long)Dv, SCL * LOG2E);

    // dual-Q causal: cval (+pair) and sval (+pair)
    fa2_k<<<dim3(16,16), blk, FASM>>>(
        gh+oQXG, gl+oQXG, Dv, (long)Hv*Tv*Dv, (long)Tv*Dv,
        gh+oQKVX, gl+oQKVX, 3*Cv, (long)Tv*3*Cv, (long)Dv,
        gh+oQKVX+Cv, gl+oQKVX+Cv, 3*Cv, (long)Tv*3*Cv, (long)Dv,
        gh+oQKVX+2*Cv, gl+oQKVX+2*Cv, 3*Cv, (long)Tv*3*Cv, (long)Dv,
        gf+fCV, gh+oCV, gl+oCV,
        gf+fSV, gh+oSV, gl+oSV,
        Cv, (long)Tv*Cv, (long)Dv, SCL * LOG2E);

    // gates batched z=2: t1 = sval@Wgs, t2 = cval@Wgc (pair A, pipelined)
    hg<128,true,false,false><<<dim3(4,32,2), blk, HGSM128>>>(
        gh+oSV, gl+oSV, Cv, 0, nTC,
        gh+oWGS, gl+oWGS, Cv, 0, (long)Cv*Cv,
        gf+fT1, nullptr, nullptr, Cv, 0, nTC, nullptr, Cv, 2, 1.0f);

    gate_k<<<(unsigned)((nTC + 255) / 256), blk>>>(
        gf+fT1, gf+fT2, bgs, bgc, gf+fCV, gf+fSV, gh+oT3, gl+oT3, nTC);

    // out = t3 @ Wp + bp
    hg<128,true,false,true><<<dim3(4,32,1), blk, HGSM128>>>(
        gh+oT3, gl+oT3, Cv, 0,0, gh+oWP, gl+oWP, Cv, 0,0,
        out, nullptr, nullptr, Cv, 0,0, bp, Cv, 1, 1.0f);
}

// round 14
// speedup vs baseline: 1.1876x; 1.0410x over previous
#include <cuda_runtime.h>
#include <cuda_bf16.h>
#include <cstdint>
#include <math.h>

#define BBv 2
#define Tv 2048
#define Mv 512
#define Cv 512
#define Hv 8
#define Dv 64
#define BHv 16
#define SCL 0.125f
#define LOG2E 1.4426950408889634f
typedef __nv_bfloat16 bf;

// ---------- bf16 pair pool offsets ----------
constexpr long oXB   = 0;
constexpr long oYB   = oXB   + (long)BBv*Tv*Cv;
constexpr long oWQX  = oYB   + (long)BBv*Mv*Cv;
constexpr long oWQY  = oWQX  + (long)Cv*3*Cv;
constexpr long oWGS  = oWQY  + (long)Cv*3*Cv;
constexpr long oWGC  = oWGS  + (long)Cv*Cv;
constexpr long oWP   = oWGC  + (long)Cv*Cv;
constexpr long oQKVX = oWP   + (long)Cv*Cv;
constexpr long oQKVY = oQKVX + (long)BBv*Tv*3*Cv;
constexpr long oQXG  = oQKVY + (long)BBv*Mv*3*Cv;
constexpr long oGT   = oQXG  + (long)BHv*Tv*Dv;
constexpr long oSV   = oGT   + (long)BHv*Dv*Dv;
constexpr long oCV   = oSV   + (long)BBv*Tv*Cv;
constexpr long oT3   = oCV   + (long)BBv*Tv*Cv;
constexpr long NBF   = oT3   + (long)BBv*Tv*Cv;
// ---------- fp32 pool ----------
constexpr long nTCe = (long)BBv*Tv*Cv;
constexpr long fSV = 0;
constexpr long fCV = fSV + nTCe;
constexpr long fT1 = fCV + nTCe;      // also G partial scratch early
constexpr long fT2 = fT1 + nTCe;
constexpr long NF_ = fT2 + nTCe;

__device__ bf    g_h[NBF];
__device__ bf    g_l[NBF];
__device__ float g_f[NF_];

// ---------- helpers ----------
__device__ __forceinline__ uint32_t smem_u32(const void* p) {
    uint32_t a;
    asm("{ .reg .u64 t; cvta.to.shared.u64 t, %1; cvt.u32.u64 %0, t; }" : "=r"(a) : "l"(p));
    return a;
}
#define LDM4(r, addr) asm volatile( \
    "ldmatrix.sync.aligned.m8n8.x4.shared.b16 {%0,%1,%2,%3}, [%4];" \
    : "=r"((r)[0]), "=r"((r)[1]), "=r"((r)[2]), "=r"((r)[3]) : "r"(addr))
#define LDM4T(r, addr) asm volatile( \
    "ldmatrix.sync.aligned.m8n8.x4.trans.shared.b16 {%0,%1,%2,%3}, [%4];" \
    : "=r"((r)[0]), "=r"((r)[1]), "=r"((r)[2]), "=r"((r)[3]) : "r"(addr))
#define MMA(c, a, b) asm volatile( \
    "mma.sync.aligned.m16n8k16.row.col.f32.bf16.bf16.f32 " \
    "{%0,%1,%2,%3}, {%4,%5,%6,%7}, {%8,%9}, {%0,%1,%2,%3};" \
    : "+f"((c)[0]), "+f"((c)[1]), "+f"((c)[2]), "+f"((c)[3]) \
    : "r"((a)[0]), "r"((a)[1]), "r"((a)[2]), "r"((a)[3]), "r"((b)[0]), "r"((b)[1]))
#define CPA(sa, ga) asm volatile("cp.async.cg.shared.global [%0], [%1], 16;" :: "r"(sa), "l"(ga))
#define CPA_COMMIT() asm volatile("cp.async.commit_group;")

__device__ __forceinline__ uint32_t packbf(float a, float b) {
    __nv_bfloat162 t; t.x = __float2bfloat16(a); t.y = __float2bfloat16(b);
    return *reinterpret_cast<uint32_t*>(&t);
}

// ---------- pipelined HMMA split-bf16 GEMM: C = alpha*(A@B^T) (+bias) ---------
// 2 CTAs/SM (launch_bounds) so co-resident CTAs hide each other's sync bubbles.
template<int TN, bool F32O, bool PO, bool BIAS>
__global__ void __launch_bounds__(256, 2) hg(
    const bf* __restrict__ Ah, const bf* __restrict__ Al, int lda, long sAb, long sAh_,
    const bf* __restrict__ Bh, const bf* __restrict__ Bl, int ldb, long sBb, long sBh_,
    float* __restrict__ C, bf* __restrict__ Ch, bf* __restrict__ Cl, int ldc, long sCb, long sCh_,
    const float* __restrict__ bias, int K, int Hn, float alpha)
{
    constexpr int NFRAG = TN / 16;
    constexpr uint32_t STG = (10240 + 2 * TN * 40) * 2;   // stage bytes
    extern __shared__ __align__(16) bf dsm[];
    uint32_t sbase = smem_u32(dsm);

    int m0 = blockIdx.y * 128, n0 = blockIdx.x * TN;
    int z = blockIdx.z, bb = z / Hn, hh = z - bb * Hn;
    const bf* pAh = Ah + bb * sAb + hh * sAh_;
    const bf* pAl = Al + bb * sAb + hh * sAh_;
    const bf* pBh = Bh + bb * sBb + hh * sBh_;
    const bf* pBl = Bl + bb * sBb + hh * sBh_;
    long co = bb * sCb + hh * sCh_;

    int tid = threadIdx.x, lane = tid & 31, wid = tid >> 5;
    int wm = (wid & 3) * 32, wn = (wid >> 2) * (TN / 2);

    float acc[2][NFRAG][4];
    #pragma unroll
    for (int i = 0; i < 2; ++i)
        #pragma unroll
        for (int j = 0; j < NFRAG; ++j)
            #pragma unroll
            for (int q = 0; q < 4; ++q) acc[i][j][q] = 0.f;

    int kst = K >> 5;
    int aRow = (lane & 15), aK = (lane >> 4) * 8;
    int bRow = (lane & 7) + ((lane >> 4) & 1) * 8, bK = ((lane >> 3) & 1) * 8;

    auto prefetch = [&](int s) {
        uint32_t st = sbase + (uint32_t)(s & 1) * STG;
        int k0 = s << 5;
        #pragma unroll
        for (int i = 0; i < 2; ++i) {
            int idx = tid + i * 256;
            int r = idx >> 2, c = idx & 3;
            long go = (long)(m0 + r) * lda + k0 + c * 8;
            uint32_t so = (uint32_t)(r * 40 + c * 8) * 2;
            CPA(st + so,            pAh + go);
            CPA(st + 5120*2 + so,   pAl + go);
        }
        #pragma unroll
        for (int i = 0; i < TN / 64; ++i) {
            int idx = tid + i * 256;
            int r = idx >> 2, c = idx & 3;
            long go = (long)(n0 + r) * ldb + k0 + c * 8;
            uint32_t so = (uint32_t)(r * 40 + c * 8) * 2;
            CPA(st + 10240*2 + so,             pBh + go);
            CPA(st + (10240 + TN*40)*2 + so,   pBl + go);
        }
        CPA_COMMIT();
    };

    prefetch(0);

    for (int s = 0; s < kst; ++s) {
        if (s + 1 < kst) {
            prefetch(s + 1);
            asm volatile("cp.async.wait_group 1;");
        } else {
            asm volatile("cp.async.wait_group 0;");
        }
        __syncthreads();
        uint32_t st = sbase + (uint32_t)(s & 1) * STG;

        #pragma unroll
        for (int kk = 0; kk < 2; ++kk) {
            uint32_t ah[2][4], al[2][4];
            #pragma unroll
            for (int mf = 0; mf < 2; ++mf) {
                uint32_t off = (uint32_t)((wm + mf * 16 + aRow) * 40 + kk * 16 + aK) * 2;
                LDM4(ah[mf], st + off);
                LDM4(al[mf], st + 5120*2 + off);
            }
            uint32_t bh[NFRAG][2], bl[NFRAG][2];
            #pragma unroll
            for (int np = 0; np < NFRAG / 2; ++np) {
                uint32_t off = (uint32_t)((wn + np * 16 + bRow) * 40 + kk * 16 + bK) * 2;
                uint32_t t[4];
                LDM4(t, st + 10240*2 + off);
                bh[np*2][0] = t[0]; bh[np*2][1] = t[1]; bh[np*2+1][0] = t[2]; bh[np*2+1][1] = t[3];
                LDM4(t, st + (10240 + TN*40)*2 + off);
                bl[np*2][0] = t[0]; bl[np*2][1] = t[1]; bl[np*2+1][0] = t[2]; bl[np*2+1][1] = t[3];
            }
            #pragma unroll
            for (int mf = 0; mf < 2; ++mf)
                #pragma unroll
                for (int nf = 0; nf < NFRAG; ++nf) {
                    MMA(acc[mf][nf], ah[mf], bh[nf]);
                    MMA(acc[mf][nf], ah[mf], bl[nf]);
                    MMA(acc[mf][nf], al[mf], bh[nf]);
                }
        }
        __syncthreads();
    }

    int rb = m0 + wm + (lane >> 2);
    int cb = n0 + wn + (lane & 3) * 2;
    #pragma unroll
    for (int mf = 0; mf < 2; ++mf)
        #pragma unroll
        for (int half = 0; half < 2; ++half) {
            long row = rb + mf * 16 + half * 8;
            #pragma unroll
            for (int nf = 0; nf < NFRAG; ++nf) {
                int cc = cb + nf * 8;
                float v0 = alpha * acc[mf][nf][half * 2 + 0];
                float v1 = alpha * acc[mf][nf][half * 2 + 1];
                if (BIAS) { v0 += bias[cc]; v1 += bias[cc + 1]; }
                long base = co + row * (long)ldc + cc;
                if (F32O) { C[base] = v0; C[base + 1] = v1; }
                if (PO) {
                    bf h0 = __float2bfloat16(v0), h1 = __float2bfloat16(v1);
                    *reinterpret_cast<uint32_t*>(Ch + base) = packbf(__bfloat162float(h0), __bfloat162float(h1));
                    *reinterpret_cast<uint32_t*>(Cl + base) = packbf(v0 - __bfloat162float(h0), v1 - __bfloat162float(h1));
                }
            }
        }
}

// ---------- shared attention tile step (scale pre-folded with log2e) ----------
template<bool CAUSAL>
__device__ __forceinline__ void attn_tile(
    uint32_t sbase, uint32_t bo,
    uint32_t (&qh)[4][4], uint32_t (&ql)[4][4],
    float (&o)[8][4], float& mr0, float& mr1, float& l0, float& l1,
    int c0, int row0, int diagRow, float scale, int lane)
{
    int bRow = (lane & 7) + ((lane >> 4) & 1) * 8, bK = ((lane >> 3) & 1) * 8;
    int vRow = (lane & 7) + ((lane >> 3) & 1) * 8, vN = ((lane >> 4) & 1) * 8;

    float s[8][4];
    #pragma unroll
    for (int i = 0; i < 8; ++i)
        #pragma unroll
        for (int q = 0; q < 4; ++q) s[i][q] = 0.f;

    #pragma unroll
    for (int kk = 0; kk < 4; ++kk) {
        uint32_t kh[8][2], kl[8][2];
        #pragma unroll
        for (int np = 0; np < 4; ++np) {
            uint32_t off = bo + (uint32_t)((np * 16 + bRow) * 72 + kk * 16 + bK) * 2;
            uint32_t t[4];
            LDM4(t, sbase + off);
            kh[np*2][0] = t[0]; kh[np*2][1] = t[1]; kh[np*2+1][0] = t[2]; kh[np*2+1][1] = t[3];
            LDM4(t, sbase + 4608 * 2 + off);
            kl[np*2][0] = t[0]; kl[np*2][1] = t[1]; kl[np*2+1][0] = t[2]; kl[np*2+1][1] = t[3];
        }
        #pragma unroll
        for (int nf = 0; nf < 8; ++nf) {
            MMA(s[nf], qh[kk], kh[nf]);
            MMA(s[nf], qh[kk], kl[nf]);
            MMA(s[nf], ql[kk], kh[nf]);
        }
    }
    #pragma unroll
    for (int nf = 0; nf < 8; ++nf) {
        #pragma unroll
        for (int q = 0; q < 4; ++q) s[nf][q] *= scale;
    }
    if (CAUSAL && (c0 + 63 > diagRow)) {
        #pragma unroll
        for (int nf = 0; nf < 8; ++nf) {
            int col = c0 + nf * 8 + (lane & 3) * 2;
            if (col     > row0)     s[nf][0] = -1e30f;
            if (col + 1 > row0)     s[nf][1] = -1e30f;
            if (col     > row0 + 8) s[nf][2] = -1e30f;
            if (col + 1 > row0 + 8) s[nf][3] = -1e30f;
        }
    }
    float t0 = -INFINITY, t1 = -INFINITY;
    #pragma unroll
    for (int nf = 0; nf < 8; ++nf) {
        t0 = fmaxf(t0, fmaxf(s[nf][0], s[nf][1]));
        t1 = fmaxf(t1, fmaxf(s[nf][2], s[nf][3]));
    }
    t0 = fmaxf(t0, __shfl_xor_sync(0xffffffffu, t0, 1));
    t0 = fmaxf(t0, __shfl_xor_sync(0xffffffffu, t0, 2));
    t1 = fmaxf(t1, __shfl_xor_sync(0xffffffffu, t1, 1));
    t1 = fmaxf(t1, __shfl_xor_sync(0xffffffffu, t1, 2));
    float mn0 = fmaxf(mr0, t0), mn1 = fmaxf(mr1, t1);
    float cr0 = exp2f(mr0 - mn0), cr1 = exp2f(mr1 - mn1);
    float sum0 = 0.f, sum1 = 0.f;
    #pragma unroll
    for (int nf = 0; nf < 8; ++nf) {
        s[nf][0] = exp2f(s[nf][0] - mn0);
        s[nf][1] = exp2f(s[nf][1] - mn0);
        s[nf][2] = exp2f(s[nf][2] - mn1);
        s[nf][3] = exp2f(s[nf][3] - mn1);
        sum0 += s[nf][0] + s[nf][1];
        sum1 += s[nf][2] + s[nf][3];
    }
    sum0 += __shfl_xor_sync(0xffffffffu, sum0, 1);
    sum0 += __shfl_xor_sync(0xffffffffu, sum0, 2);
    sum1 += __shfl_xor_sync(0xffffffffu, sum1, 1);
    sum1 += __shfl_xor_sync(0xffffffffu, sum1, 2);
    l0 = l0 * cr0 + sum0; l1 = l1 * cr1 + sum1;
    mr0 = mn0; mr1 = mn1;
    #pragma unroll
    for (int nf = 0; nf < 8; ++nf) {
        o[nf][0] *= cr0; o[nf][1] *= cr0; o[nf][2] *= cr1; o[nf][3] *= cr1;
    }
    #pragma unroll
    for (int kk2 = 0; kk2 < 4; ++kk2) {
        uint32_t Ph[4], Pl[4];
        {
            float a0 = s[2*kk2][0],   a1 = s[2*kk2][1];
            float a2 = s[2*kk2][2],   a3 = s[2*kk2][3];
            float a4 = s[2*kk2+1][0], a5 = s[2*kk2+1][1];
            float a6 = s[2*kk2+1][2], a7 = s[2*kk2+1][3];
            bf h0 = __float2bfloat16(a0), h1 = __float2bfloat16(a1);
            bf h2 = __float2bfloat16(a2), h3 = __float2bfloat16(a3);
            bf h4 = __float2bfloat16(a4), h5 = __float2bfloat16(a5);
            bf h6 = __float2bfloat16(a6), h7 = __float2bfloat16(a7);
            Ph[0] = packbf(__bfloat162float(h0), __bfloat162float(h1));
            Ph[1] = packbf(__bfloat162float(h2), __bfloat162float(h3));
            Ph[2] = packbf(__bfloat162float(h4), __bfloat162float(h5));
            Ph[3] = packbf(__bfloat162float(h6), __bfloat162float(h7));
            Pl[0] = packbf(a0 - __bfloat162float(h0), a1 - __bfloat162float(h1));
            Pl[1] = packbf(a2 - __bfloat162float(h2), a3 - __bfloat162float(h3));
            Pl[2] = packbf(a4 - __bfloat162float(h4), a5 - __bfloat162float(h5));
            Pl[3] = packbf(a6 - __bfloat162float(h6), a7 - __bfloat162float(h7));
        }
        uint32_t vh[8][2], vl[8][2];
        #pragma unroll
        for (int np = 0; np < 4; ++np) {
            uint32_t off = bo + (uint32_t)((kk2 * 16 + vRow) * 72 + np * 16 + vN) * 2;
            uint32_t t[4];
            LDM4T(t, sbase + 9216 * 2 + off);
            vh[np*2][0] = t[0]; vh[np*2][1] = t[1]; vh[np*2+1][0] = t[2]; vh[np*2+1][1] = t[3];
            LDM4T(t, sbase + 13824 * 2 + off);
            vl[np*2][0] = t[0]; vl[np*2][1] = t[1]; vl[np*2+1][0] = t[2]; vl[np*2+1][1] = t[3];
        }
        #pragma unroll
        for (int nf = 0; nf < 8; ++nf) {
            MMA(o[nf], Ph, vh[nf]);
            MMA(o[nf], Ph, vl[nf]);
            MMA(o[nf], Pl, vh[nf]);
        }
    }
}

// prefetch one K/V tile
__device__ __forceinline__ void kv_prefetch(
    uint32_t sbase, uint32_t bn, int c0,
    const bf* pKh, const bf* pKl, int ldk,
    const bf* pVh, const bf* pVl, int ldv, int tid)
{
    int pr = tid >> 3, pch = tid & 7;
    #pragma unroll
    for (int i = 0; i < 2; ++i) {
        int r = pr + i * 32;
        long gk = (long)(c0 + r) * ldk + pch * 8;
        long gv = (long)(c0 + r) * ldv + pch * 8;
        uint32_t so = bn + (uint32_t)(r * 72 + pch * 8) * 2;
        CPA(sbase + so,             pKh + gk);
        CPA(sbase + 4608*2  + so,   pKl + gk);
        CPA(sbase + 9216*2  + so,   pVh + gv);
        CPA(sbase + 13824*2 + so,   pVl + gv);
    }
    CPA_COMMIT();
}

// ---------- single-Q flash (non-causal; cval1), f32 out -----------------------
__global__ void __launch_bounds__(256) fa_k(
    const bf* __restrict__ Ah, const bf* __restrict__ Al, int lda, long sAb, long sAh_,
    const bf* __restrict__ Kh, const bf* __restrict__ Kl, int ldk, long sKb, long sKh_,
    const bf* __restrict__ Vh, const bf* __restrict__ Vl, int ldv, long sVb, long sVh_,
    int S_, float* __restrict__ O, int ldo, long sOb, long sOh_, float scale)
{
    extern __shared__ __align__(16) bf dsm[];
    uint32_t sbase = smem_u32(dsm);

    int z = blockIdx.y, bb = z >> 3, hh = z & 7;
    int m0 = (int)blockIdx.x * 128;
    const bf* pAh = Ah + bb * sAb + hh * sAh_;
    const bf* pAl = Al + bb * sAb + hh * sAh_;
    const bf* pKh = Kh + bb * sKb + hh * sKh_;
    const bf* pKl = Kl + bb * sKb + hh * sKh_;
    const bf* pVh = Vh + bb * sVb + hh * sVh_;
    const bf* pVl = Vl + bb * sVb + hh * sVh_;
    long co = (long)bb * sOb + (long)hh * sOh_;

    int tid = threadIdx.x, lane = tid & 31, wid = tid >> 5;
    int wrow = wid * 16;

    #pragma unroll
    for (int i = 0; i < 4; ++i) {
        int q = tid + i * 256, r = q >> 3, ch = q & 7;
        long go = (long)(m0 + r) * lda + ch * 8;
        *(uint4*)&dsm[r * 72 + ch * 8]        = *(const uint4*)(pAh + go);
        *(uint4*)&dsm[9216 + r * 72 + ch * 8] = *(const uint4*)(pAl + go);
    }
    __syncthreads();
    int aRow = lane & 15, aK = (lane >> 4) * 8;
    uint32_t qh[4][4], ql[4][4];
    #pragma unroll
    for (int kk = 0; kk < 4; ++kk) {
        uint32_t off = (uint32_t)((wrow + aRow) * 72 + kk * 16 + aK) * 2;
        LDM4(qh[kk], sbase + off);
        LDM4(ql[kk], sbase + 9216 * 2 + off);
    }
    __syncthreads();

    float o[8][4];
    #pragma unroll
    for (int i = 0; i < 8; ++i)
        #pragma unroll
        for (int q = 0; q < 4; ++q) o[i][q] = 0.f;
    float mr0 = -INFINITY, mr1 = -INFINITY, l0 = 0.f, l1 = 0.f;

    int nt = S_ >> 6;
    int row0 = m0 + wrow + (lane >> 2);

    kv_prefetch(sbase, 0, 0, pKh, pKl, ldk, pVh, pVl, ldv, tid);

    for (int ct = 0; ct < nt; ++ct) {
        uint32_t bo = (uint32_t)(ct & 1) * 18432u * 2u;
        if (ct + 1 < nt) {
            kv_prefetch(sbase, (uint32_t)((ct + 1) & 1) * 18432u * 2u, (ct + 1) << 6,
                        pKh, pKl, ldk, pVh, pVl, ldv, tid);
            asm volatile("cp.async.wait_group 1;");
        } else {
            asm volatile("cp.async.wait_group 0;");
        }
        __syncthreads();
        attn_tile<false>(sbase, bo, qh, ql, o, mr0, mr1, l0, l1,
                         ct << 6, row0, 0, scale, lane);
        __syncthreads();
    }

    float inv0 = 1.f / l0, inv1 = 1.f / l1;
    #pragma unroll
    for (int nf = 0; nf < 8; ++nf) {
        int col = nf * 8 + (lane & 3) * 2;
        long b0 = co + (long)row0 * ldo + col;
        long b1 = co + (long)(row0 + 8) * ldo + col;
        O[b0] = o[nf][0] * inv0; O[b0 + 1] = o[nf][1] * inv0;
        O[b1] = o[nf][2] * inv1; O[b1 + 1] = o[nf][3] * inv1;
    }
}

// ---------- dual-Q causal flash: cval (ACC + pair) + sval (f32 + pair) --------
__global__ void __launch_bounds__(256) fa2_k(
    const bf* __restrict__ A1h, const bf* __restrict__ A1l, int lda1, long sA1b, long sA1h,
    const bf* __restrict__ A2h, const bf* __restrict__ A2l, int lda2, long sA2b, long sA2h,
    const bf* __restrict__ Kh, const bf* __restrict__ Kl, int ldk, long sKb, long sKh_,
    const bf* __restrict__ Vh, const bf* __restrict__ Vl, int ldv, long sVb, long sVh_,
    float* __restrict__ O1, bf* __restrict__ O1h, bf* __restrict__ O1l,
    float* __restrict__ O2, bf* __restrict__ O2h, bf* __restrict__ O2l,
    int ldo, long sOb, long sOh_, float scale)
{
    extern __shared__ __align__(16) bf dsm[];
    uint32_t sbase = smem_u32(dsm);

    int z = blockIdx.y, bb = z >> 3, hh = z & 7;
    int m0 = (int)(gridDim.x - 1 - blockIdx.x) * 128;
    const bf* pKh = Kh + bb * sKb + hh * sKh_;
    const bf* pKl = Kl + bb * sKb + hh * sKh_;
    const bf* pVh = Vh + bb * sVb + hh * sVh_;
    const bf* pVl = Vl + bb * sVb + hh * sVh_;
    long co = (long)bb * sOb + (long)hh * sOh_;

    int tid = threadIdx.x, lane = tid & 31, wid = tid >> 5;
    int wrow = wid * 16;
    int aRow = lane & 15, aK = (lane >> 4) * 8;
    uint32_t q1h[4][4], q1l[4][4], q2h[4][4], q2l[4][4];

    {
        const bf* p1h = A1h + bb * sA1b + hh * sA1h;
        const bf* p1l = A1l + bb * sA1b + hh * sA1h;
        #pragma unroll
        for (int i = 0; i < 4; ++i) {
            int q = tid + i * 256, r = q >> 3, ch = q & 7;
            long go = (long)(m0 + r) * lda1 + ch * 8;
            *(uint4*)&dsm[r * 72 + ch * 8]        = *(const uint4*)(p1h + go);
            *(uint4*)&dsm[9216 + r * 72 + ch * 8] = *(const uint4*)(p1l + go);
        }
        __syncthreads();
        #pragma unroll
        for (int kk = 0; kk < 4; ++kk) {
            uint32_t off = (uint32_t)((wrow + aRow) * 72 + kk * 16 + aK) * 2;
            LDM4(q1h[kk], sbase + off);
            LDM4(q1l[kk], sbase + 9216 * 2 + off);
        }
        __syncthreads();
        const bf* p2h = A2h + bb * sA2b + hh * sA2h;
        const bf* p2l = A2l + bb * sA2b + hh * sA2h;
        #pragma unroll
        for (int i = 0; i < 4; ++i) {
            int q = tid + i * 256, r = q >> 3, ch = q & 7;
            long go = (long)(m0 + r) * lda2 + ch * 8;
            *(uint4*)&dsm[r * 72 + ch * 8]        = *(const uint4*)(p2h + go);
            *(uint4*)&dsm[9216 + r * 72 + ch * 8] = *(const uint4*)(p2l + go);
        }
        __syncthreads();
        #pragma unroll
        for (int kk = 0; kk < 4; ++kk) {
            uint32_t off = (uint32_t)((wrow + aRow) * 72 + kk * 16 + aK) * 2;
            LDM4(q2h[kk], sbase + off);
            LDM4(q2l[kk], sbase + 9216 * 2 + off);
        }
        __syncthreads();
    }

    float o1[8][4], o2[8][4];
    #pragma unroll
    for (int i = 0; i < 8; ++i)
        #pragma unroll
        for (int q = 0; q < 4; ++q) { o1[i][q] = 0.f; o2[i][q] = 0.f; }
    float m10 = -INFINITY, m11 = -INFINITY, l10 = 0.f, l11 = 0.f;
    float m20 = -INFINITY, m21 = -INFINITY, l20 = 0.f, l21 = 0.f;

    int nt = (m0 >> 6) + 2;
    int row0 = m0 + wrow + (lane >> 2);
    int diagRow = m0 + wrow;

    kv_prefetch(sbase, 0, 0, pKh, pKl, ldk, pVh, pVl, ldv, tid);

    for (int ct = 0; ct < nt; ++ct) {
        uint32_t bo = (uint32_t)(ct & 1) * 18432u * 2u;
        if (ct + 1 < nt) {
            kv_prefetch(sbase, (uint32_t)((ct + 1) & 1) * 18432u * 2u, (ct + 1) << 6,
                        pKh, pKl, ldk, pVh, pVl, ldv, tid);
            asm volatile("cp.async.wait_group 1;");
        } else {
            asm volatile("cp.async.wait_group 0;");
        }
        __syncthreads();
        int c0 = ct << 6;
        attn_tile<true>(sbase, bo, q1h, q1l, o1, m10, m11, l10, l11, c0, row0, diagRow, scale, lane);
        attn_tile<true>(sbase, bo, q2h, q2l, o2, m20, m21, l20, l21, c0, row0, diagRow, scale, lane);
        __syncthreads();
    }

    float i10 = 1.f / l10, i11 = 1.f / l11, i20 = 1.f / l20, i21 = 1.f / l21;
    #pragma unroll
    for (int nf = 0; nf < 8; ++nf) {
        int col = nf * 8 + (lane & 3) * 2;
        long b0 = co + (long)row0 * ldo + col;
        long b1 = co + (long)(row0 + 8) * ldo + col;
        float v0 = o1[nf][0] * i10 + O1[b0], v1 = o1[nf][1] * i10 + O1[b0 + 1];
        float v2 = o1[nf][2] * i11 + O1[b1], v3 = o1[nf][3] * i11 + O1[b1 + 1];
        O1[b0] = v0; O1[b0 + 1] = v1; O1[b1] = v2; O1[b1 + 1] = v3;
        bf h0 = __float2bfloat16(v0), h1 = __float2bfloat16(v1);
        bf h2 = __float2bfloat16(v2), h3 = __float2bfloat16(v3);
        *reinterpret_cast<uint32_t*>(O1h + b0) = packbf(__bfloat162float(h0), __bfloat162float(h1));
        *reinterpret_cast<uint32_t*>(O1h + b1) = packbf(__bfloat162float(h2), __bfloat162float(h3));
        *reinterpret_cast<uint32_t*>(O1l + b0) = packbf(v0 - __bfloat162float(h0), v1 - __bfloat162float(h1));
        *reinterpret_cast<uint32_t*>(O1l + b1) = packbf(v2 - __bfloat162float(h2), v3 - __bfloat162float(h3));
        float w0 = o2[nf][0] * i20, w1 = o2[nf][1] * i20;
        float w2 = o2[nf][2] * i21, w3 = o2[nf][3] * i21;
        O2[b0] = w0; O2[b0 + 1] = w1; O2[b1] = w2; O2[b1 + 1] = w3;
        bf g0 = __float2bfloat16(w0), g1 = __float2bfloat16(w1);
        bf g2 = __float2bfloat16(w2), g3 = __float2bfloat16(w3);
        *reinterpret_cast<uint32_t*>(O2h + b0) = packbf(__bfloat162float(g0), __bfloat162float(g1));
        *reinterpret_cast<uint32_t*>(O2h + b1) = packbf(__bfloat162float(g2), __bfloat162float(g3));
        *reinterpret_cast<uint32_t*>(O2l + b0) = packbf(w0 - __bfloat162float(g0), w1 - __bfloat162float(g1));
        *reinterpret_cast<uint32_t*>(O2l + b1) = packbf(w2 - __bfloat162float(g2), w3 - __bfloat162float(g3));
    }
}

// ---------- G partials + reduce ----------
__global__ void __launch_bounds__(256) g1_k(const bf* __restrict__ qh, const bf* __restrict__ ql,
                                            float* __restrict__ part)
{
    int z = blockIdx.x, ck = blockIdx.y;
    int b = z >> 3, h = z & 7;
    int m0 = ck * 64;
    long kyo = (long)b * Mv * 3 * Cv + (long)h * Dv + Cv;
    long qyo = (long)b * Mv * 3 * Cv + (long)h * Dv;
    __shared__ float sky[64][65], sqy[64][65];
    int tid = threadIdx.x;
    int d2 = tid & 63, gg = tid >> 6;
    float acc[16];
    #pragma unroll
    for (int i = 0; i < 16; ++i) acc[i] = 0.f;
    #pragma unroll
    for (int i = 0; i < 16; ++i) {
        int q = tid + i * 256;
        int mm = q >> 6, dd = q & 63;
        long ik = kyo + (long)(m0 + mm) * 3 * Cv + dd;
        long iq = qyo + (long)(m0 + mm) * 3 * Cv + dd;
        sky[mm][dd] = __bfloat162float(qh[ik]) + __bfloat162float(ql[ik]);
        sqy[mm][dd] = __bfloat162float(qh[iq]) + __bfloat162float(ql[iq]);
    }
    __syncthreads();
    for (int mm = 0; mm < 64; ++mm) {
        float qv = sqy[mm][d2];
        #pragma unroll
        for (int i = 0; i < 16; ++i)
            acc[i] += sky[mm][gg * 16 + i] * qv;
    }
    long base = ((long)z * 8 + ck) * 4096 + (long)d2 * 64 + gg * 16;
    #pragma unroll
    for (int i = 0; i < 16; ++i) part[base + i] = acc[i];
}
__global__ void __launch_bounds__(256) g2_k(const float* __restrict__ part,
                                            bf* __restrict__ goh, bf* __restrict__ gol)
{
    int z = blockIdx.x, tid = threadIdx.x;
    #pragma unroll
    for (int i = 0; i < 16; ++i) {
        int idx = tid + i * 256;
        float s = 0.f;
        #pragma unroll
        for (int ck = 0; ck < 8; ++ck)
            s += part[((long)z * 8 + ck) * 4096 + idx];
        float v = s * (SCL * SCL);
        bf hh = __float2bfloat16(v);
        long o = (long)z * 4096 + idx;
        goh[o] = hh;
        gol[o] = __float2bfloat16(v - __bfloat162float(hh));
    }
}

// ---------- splits ----------
__global__ void __launch_bounds__(256) split_k(const float* __restrict__ in, bf* __restrict__ oh,
                                               bf* __restrict__ ol, long n) {
    long i = (long)blockIdx.x * 256 + threadIdx.x;
    if (i < n) {
        float v = in[i]; bf h = __float2bfloat16(v);
        oh[i] = h; ol[i] = __float2bfloat16(v - __bfloat162float(h));
    }
}
__global__ void __launch_bounds__(256) splitW_k(
    const float* __restrict__ w0, const float* __restrict__ w1,
    const float* __restrict__ w2, const float* __restrict__ w3,
    const float* __restrict__ w4, bf* __restrict__ oh, bf* __restrict__ ol)
{
    int job = blockIdx.y;
    const float* src; long off; int Nd;
    switch (job) {
        case 0:  src = w0; off = oWQX; Nd = 3 * Cv; break;
        case 1:  src = w1; off = oWQY; Nd = 3 * Cv; break;
        case 2:  src = w2; off = oWGS; Nd = Cv; break;
        case 3:  src = w3; off = oWGC; Nd = Cv; break;
        default: src = w4; off = oWP;  Nd = Cv; break;
    }
    long n = (long)Cv * Nd;
    long i = (long)blockIdx.x * 256 + threadIdx.x;
    if (i >= n) return;
    int nn = (int)(i / Cv), k = (int)(i % Cv);
    float v = src[(long)k * Nd + nn];
    bf h = __float2bfloat16(v);
    oh[off + i] = h;
    ol[off + i] = __float2bfloat16(v - __bfloat162float(h));
}

// ---------- gate combine (pair out) ----------
__global__ void __launch_bounds__(256) gate_k(
    const float* __restrict__ t1, const float* __restrict__ t2,
    const float* __restrict__ bgs, const float* __restrict__ bgc,
    const float* __restrict__ cv, const float* __restrict__ sv,
    bf* __restrict__ oh, bf* __restrict__ ol, long n)
{
    long i = (long)blockIdx.x * 256 + threadIdx.x;
    if (i < n) {
        int c = (int)(i & (Cv - 1));
        float g1 = 1.f / (1.f + __expf(-(t1[i] + bgs[c])));
        float g2 = 1.f / (1.f + __expf(-(t2[i] + bgc[c])));
        float v = g1 * cv[i] + g2 * sv[i];
        bf h = __float2bfloat16(v);
        oh[i] = h; ol[i] = __float2bfloat16(v - __bfloat162float(h));
    }
}

// ------------------------------------------------------------------------------
extern "C" void kernel_launch(void* const* d_in, const int* in_sizes, int n_in,
                              void* d_out, int out_size)
{
    const float* x      = (const float*)d_in[0];
    const float* y      = (const float*)d_in[1];
    const float* Wqkv_x = (const float*)d_in[3];
    const float* bqkv_x = (const float*)d_in[4];
    const float* Wqkv_y = (const float*)d_in[5];
    const float* bqkv_y = (const float*)d_in[6];
    const float* Wgs    = (const float*)d_in[7];
    const float* bgs    = (const float*)d_in[8];
    const float* Wgc    = (const float*)d_in[9];
    const float* bgc    = (const float*)d_in[10];
    const float* Wp     = (const float*)d_in[11];
    const float* bp     = (const float*)d_in[12];
    float* out = (float*)d_out;

    bf *gh, *gl; float* gf;
    cudaGetSymbolAddress((void**)&gh, g_h);
    cudaGetSymbolAddress((void**)&gl, g_l);
    cudaGetSymbolAddress((void**)&gf, g_f);

    const int FASM   = 2 * 18432 * 2;
    const int HGSM128 = 2 * (10240 + 2 * 128 * 40) * 2;
    const int HGSM64  = 2 * (10240 + 2 * 64 * 40) * 2;
    cudaFuncSetAttribute((const void*)fa_k,  cudaFuncAttributeMaxDynamicSharedMemorySize, FASM);
    cudaFuncSetAttribute((const void*)fa2_k, cudaFuncAttributeMaxDynamicSharedMemorySize, FASM);
    cudaFuncSetAttribute((const void*)hg<128,false,true,true>,  cudaFuncAttributeMaxDynamicSharedMemorySize, HGSM128);
    cudaFuncSetAttribute((const void*)hg<128,true,false,false>, cudaFuncAttributeMaxDynamicSharedMemorySize, HGSM128);
    cudaFuncSetAttribute((const void*)hg<128,true,false,true>,  cudaFuncAttributeMaxDynamicSharedMemorySize, HGSM128);
    cudaFuncSetAttribute((const void*)hg<64,false,true,false>,  cudaFuncAttributeMaxDynamicSharedMemorySize, HGSM64);

    dim3 blk(256);
    long nTC = nTCe;

    // splits
    splitW_k<<<dim3(3072, 5), blk>>>(Wqkv_x, Wqkv_y, Wgs, Wgc, Wp, gh, gl);
    split_k<<<(unsigned)((nTC + 255) / 256), blk>>>(x, gh + oXB, gl + oXB, nTC);
    split_k<<<(unsigned)((BBv*Mv*Cv + 255) / 256), blk>>>(y, gh + oYB, gl + oYB, (long)BBv*Mv*Cv);

    // qkv projections (pipelined hg, 2 CTAs/SM, pair out)
    hg<128,false,true,true><<<dim3(12,32,1), blk, HGSM128>>>(
        gh+oXB, gl+oXB, Cv, 0,0, gh+oWQX, gl+oWQX, Cv, 0,0,
        nullptr, gh+oQKVX, gl+oQKVX, 3*Cv, 0,0, bqkv_x, Cv, 1, 1.0f);
    hg<128,false,true,true><<<dim3(12,8,1), blk, HGSM128>>>(
        gh+oYB, gl+oYB, Cv, 0,0, gh+oWQY, gl+oWQY, Cv, 0,0,
        nullptr, gh+oQKVY, gl+oQKVY, 3*Cv, 0,0, bqkv_y, Cv, 1, 1.0f);

    // G (split-K) then qxG
    g1_k<<<dim3(BHv, 8), blk>>>(gh+oQKVY, gl+oQKVY, gf+fT1);
    g2_k<<<BHv, blk>>>(gf+fT1, gh+oGT, gl+oGT);
    hg<64,false,true,false><<<dim3(1,16,16), blk, HGSM64>>>(
        gh+oQKVX, gl+oQKVX, 3*Cv, (long)Tv*3*Cv, (long)Dv,
        gh+oGT, gl+oGT, 64, (long)Hv*Dv*Dv, (long)Dv*Dv,
        nullptr, gh+oQXG, gl+oQXG, Dv, (long)Hv*Tv*Dv, (long)Tv*Dv, nullptr, Dv, Hv, 1.0f);

    // cval1 (fused, non-causal); scale folded with log2e
    fa_k<<<dim3(16,16), blk, FASM>>>(
        gh+oQKVX, gl+oQKVX, 3*Cv, (long)Tv*3*Cv, (long)Dv,
        gh+oQKVY+Cv, gl+oQKVY+Cv, 3*Cv, (long)Mv*3*Cv, (long)Dv,
        gh+oQKVY+2*Cv, gl+oQKVY+2*Cv, 3*Cv, (long)Mv*3*Cv, (long)Dv,
        Mv, gf+fCV, Cv, (long)Tv*Cv, (long)Dv, SCL * LOG2E);

    // dual-Q causal: cval (+pair) and sval (+pair)
    fa2_k<<<dim3(16,16), blk, FASM>>>(
        gh+oQXG, gl+oQXG, Dv, (long)Hv*Tv*Dv, (long)Tv*Dv,
        gh+oQKVX, gl+oQKVX, 3*Cv, (long)Tv*3*Cv, (long)Dv,
        gh+oQKVX+Cv, gl+oQKVX+Cv, 3*Cv, (long)Tv*3*Cv, (long)Dv,
        gh+oQKVX+2*Cv, gl+oQKVX+2*Cv, 3*Cv, (long)Tv*3*Cv, (long)Dv,
        gf+fCV, gh+oCV, gl+oCV,
        gf+fSV, gh+oSV, gl+oSV,
        Cv, (long)Tv*Cv, (long)Dv, SCL * LOG2E);

    // gates batched z=2: t1 = sval@Wgs, t2 = cval@Wgc
    hg<128,true,false,false><<<dim3(4,32,2), blk, HGSM128>>>(
        gh+oSV, gl+oSV, Cv, 0, nTC,
        gh+oWGS, gl+oWGS, Cv, 0, (long)Cv*Cv,
        gf+fT1, nullptr, nullptr, Cv, 0, nTC, nullptr, Cv, 2, 1.0f);

    gate_k<<<(unsigned)((nTC + 255) / 256), blk>>>(
        gf+fT1, gf+fT2, bgs, bgc, gf+fCV, gf+fSV, gh+oT3, gl+oT3, nTC);

    // out = t3 @ Wp + bp
    hg<128,true,false,true><<<dim3(4,32,1), blk, HGSM128>>>(
        gh+oT3, gl+oT3, Cv, 0,0, gh+oWP, gl+oWP, Cv, 0,0,
        out, nullptr, nullptr, Cv, 0,0, bp, Cv, 1, 1.0f);
}

// round 15
// speedup vs baseline: 1.1961x; 1.0072x over previous
#include <cuda_runtime.h>
#include <cuda_bf16.h>
#include <cstdint>
#include <math.h>

#define BBv 2
#define Tv 2048
#define Mv 512
#define Cv 512
#define Hv 8
#define Dv 64
#define BHv 16
#define SCL 0.125f
#define LOG2E 1.4426950408889634f
typedef __nv_bfloat16 bf;

// ---------- bf16 pair pool offsets ----------
constexpr long oXB   = 0;
constexpr long oYB   = oXB   + (long)BBv*Tv*Cv;
constexpr long oWQX  = oYB   + (long)BBv*Mv*Cv;
constexpr long oWQY  = oWQX  + (long)Cv*3*Cv;
constexpr long oWGS  = oWQY  + (long)Cv*3*Cv;
constexpr long oWGC  = oWGS  + (long)Cv*Cv;
constexpr long oWP   = oWGC  + (long)Cv*Cv;
constexpr long oQKVX = oWP   + (long)Cv*Cv;
constexpr long oQKVY = oQKVX + (long)BBv*Tv*3*Cv;
constexpr long oGT   = oQKVY + (long)BBv*Mv*3*Cv;
constexpr long oSV   = oGT   + (long)BHv*Dv*Dv;
constexpr long oCV   = oSV   + (long)BBv*Tv*Cv;
constexpr long oT3   = oCV   + (long)BBv*Tv*Cv;
constexpr long NBF   = oT3   + (long)BBv*Tv*Cv;
// ---------- fp32 pool ----------
constexpr long nTCe = (long)BBv*Tv*Cv;
constexpr long fSV = 0;
constexpr long fCV = fSV + nTCe;
constexpr long fT1 = fCV + nTCe;      // also G partial scratch early
constexpr long fT2 = fT1 + nTCe;
constexpr long NF_ = fT2 + nTCe;

__device__ bf    g_h[NBF];
__device__ bf    g_l[NBF];
__device__ float g_f[NF_];

// ---------- helpers ----------
__device__ __forceinline__ uint32_t smem_u32(const void* p) {
    uint32_t a;
    asm("{ .reg .u64 t; cvta.to.shared.u64 t, %1; cvt.u32.u64 %0, t; }" : "=r"(a) : "l"(p));
    return a;
}
#define LDM4(r, addr) asm volatile( \
    "ldmatrix.sync.aligned.m8n8.x4.shared.b16 {%0,%1,%2,%3}, [%4];" \
    : "=r"((r)[0]), "=r"((r)[1]), "=r"((r)[2]), "=r"((r)[3]) : "r"(addr))
#define LDM4T(r, addr) asm volatile( \
    "ldmatrix.sync.aligned.m8n8.x4.trans.shared.b16 {%0,%1,%2,%3}, [%4];" \
    : "=r"((r)[0]), "=r"((r)[1]), "=r"((r)[2]), "=r"((r)[3]) : "r"(addr))
#define MMA(c, a, b) asm volatile( \
    "mma.sync.aligned.m16n8k16.row.col.f32.bf16.bf16.f32 " \
    "{%0,%1,%2,%3}, {%4,%5,%6,%7}, {%8,%9}, {%0,%1,%2,%3};" \
    : "+f"((c)[0]), "+f"((c)[1]), "+f"((c)[2]), "+f"((c)[3]) \
    : "r"((a)[0]), "r"((a)[1]), "r"((a)[2]), "r"((a)[3]), "r"((b)[0]), "r"((b)[1]))
#define CPA(sa, ga) asm volatile("cp.async.cg.shared.global [%0], [%1], 16;" :: "r"(sa), "l"(ga))
#define CPA_COMMIT() asm volatile("cp.async.commit_group;")

__device__ __forceinline__ uint32_t packbf(float a, float b) {
    __nv_bfloat162 t; t.x = __float2bfloat16(a); t.y = __float2bfloat16(b);
    return *reinterpret_cast<uint32_t*>(&t);
}

// ---------- pipelined HMMA split-bf16 GEMM: C = alpha*(A@B^T) (+bias) ---------
template<int TN, bool F32O, bool PO, bool BIAS>
__global__ void __launch_bounds__(256, 2) hg(
    const bf* __restrict__ Ah, const bf* __restrict__ Al, int lda, long sAb, long sAh_,
    const bf* __restrict__ Bh, const bf* __restrict__ Bl, int ldb, long sBb, long sBh_,
    float* __restrict__ C, bf* __restrict__ Ch, bf* __restrict__ Cl, int ldc, long sCb, long sCh_,
    const float* __restrict__ bias, int K, int Hn, float alpha)
{
    constexpr int NFRAG = TN / 16;
    constexpr uint32_t STG = (10240 + 2 * TN * 40) * 2;
    extern __shared__ __align__(16) bf dsm[];
    uint32_t sbase = smem_u32(dsm);

    int m0 = blockIdx.y * 128, n0 = blockIdx.x * TN;
    int z = blockIdx.z, bb = z / Hn, hh = z - bb * Hn;
    const bf* pAh = Ah + bb * sAb + hh * sAh_;
    const bf* pAl = Al + bb * sAb + hh * sAh_;
    const bf* pBh = Bh + bb * sBb + hh * sBh_;
    const bf* pBl = Bl + bb * sBb + hh * sBh_;
    long co = bb * sCb + hh * sCh_;

    int tid = threadIdx.x, lane = tid & 31, wid = tid >> 5;
    int wm = (wid & 3) * 32, wn = (wid >> 2) * (TN / 2);

    float acc[2][NFRAG][4];
    #pragma unroll
    for (int i = 0; i < 2; ++i)
        #pragma unroll
        for (int j = 0; j < NFRAG; ++j)
            #pragma unroll
            for (int q = 0; q < 4; ++q) acc[i][j][q] = 0.f;

    int kst = K >> 5;
    int aRow = (lane & 15), aK = (lane >> 4) * 8;
    int bRow = (lane & 7) + ((lane >> 4) & 1) * 8, bK = ((lane >> 3) & 1) * 8;

    auto prefetch = [&](int s) {
        uint32_t st = sbase + (uint32_t)(s & 1) * STG;
        int k0 = s << 5;
        #pragma unroll
        for (int i = 0; i < 2; ++i) {
            int idx = tid + i * 256;
            int r = idx >> 2, c = idx & 3;
            long go = (long)(m0 + r) * lda + k0 + c * 8;
            uint32_t so = (uint32_t)(r * 40 + c * 8) * 2;
            CPA(st + so,            pAh + go);
            CPA(st + 5120*2 + so,   pAl + go);
        }
        #pragma unroll
        for (int i = 0; i < TN / 64; ++i) {
            int idx = tid + i * 256;
            int r = idx >> 2, c = idx & 3;
            long go = (long)(n0 + r) * ldb + k0 + c * 8;
            uint32_t so = (uint32_t)(r * 40 + c * 8) * 2;
            CPA(st + 10240*2 + so,             pBh + go);
            CPA(st + (10240 + TN*40)*2 + so,   pBl + go);
        }
        CPA_COMMIT();
    };

    prefetch(0);

    for (int s = 0; s < kst; ++s) {
        if (s + 1 < kst) {
            prefetch(s + 1);
            asm volatile("cp.async.wait_group 1;");
        } else {
            asm volatile("cp.async.wait_group 0;");
        }
        __syncthreads();
        uint32_t st = sbase + (uint32_t)(s & 1) * STG;

        #pragma unroll
        for (int kk = 0; kk < 2; ++kk) {
            uint32_t ah[2][4], al[2][4];
            #pragma unroll
            for (int mf = 0; mf < 2; ++mf) {
                uint32_t off = (uint32_t)((wm + mf * 16 + aRow) * 40 + kk * 16 + aK) * 2;
                LDM4(ah[mf], st + off);
                LDM4(al[mf], st + 5120*2 + off);
            }
            uint32_t bh[NFRAG][2], bl[NFRAG][2];
            #pragma unroll
            for (int np = 0; np < NFRAG / 2; ++np) {
                uint32_t off = (uint32_t)((wn + np * 16 + bRow) * 40 + kk * 16 + bK) * 2;
                uint32_t t[4];
                LDM4(t, st + 10240*2 + off);
                bh[np*2][0] = t[0]; bh[np*2][1] = t[1]; bh[np*2+1][0] = t[2]; bh[np*2+1][1] = t[3];
                LDM4(t, st + (10240 + TN*40)*2 + off);
                bl[np*2][0] = t[0]; bl[np*2][1] = t[1]; bl[np*2+1][0] = t[2]; bl[np*2+1][1] = t[3];
            }
            #pragma unroll
            for (int mf = 0; mf < 2; ++mf)
                #pragma unroll
                for (int nf = 0; nf < NFRAG; ++nf) {
                    MMA(acc[mf][nf], ah[mf], bh[nf]);
                    MMA(acc[mf][nf], ah[mf], bl[nf]);
                    MMA(acc[mf][nf], al[mf], bh[nf]);
                }
        }
        __syncthreads();
    }

    int rb = m0 + wm + (lane >> 2);
    int cb = n0 + wn + (lane & 3) * 2;
    #pragma unroll
    for (int mf = 0; mf < 2; ++mf)
        #pragma unroll
        for (int half = 0; half < 2; ++half) {
            long row = rb + mf * 16 + half * 8;
            #pragma unroll
            for (int nf = 0; nf < NFRAG; ++nf) {
                int cc = cb + nf * 8;
                float v0 = alpha * acc[mf][nf][half * 2 + 0];
                float v1 = alpha * acc[mf][nf][half * 2 + 1];
                if (BIAS) { v0 += bias[cc]; v1 += bias[cc + 1]; }
                long base = co + row * (long)ldc + cc;
                if (F32O) { C[base] = v0; C[base + 1] = v1; }
                if (PO) {
                    bf h0 = __float2bfloat16(v0), h1 = __float2bfloat16(v1);
                    *reinterpret_cast<uint32_t*>(Ch + base) = packbf(__bfloat162float(h0), __bfloat162float(h1));
                    *reinterpret_cast<uint32_t*>(Cl + base) = packbf(v0 - __bfloat162float(h0), v1 - __bfloat162float(h1));
                }
            }
        }
}

// ---------- shared attention tile step (scale pre-folded with log2e) ----------
template<bool CAUSAL>
__device__ __forceinline__ void attn_tile(
    uint32_t sbase, uint32_t bo,
    uint32_t (&qh)[4][4], uint32_t (&ql)[4][4],
    float (&o)[8][4], float& mr0, float& mr1, float& l0, float& l1,
    int c0, int row0, int diagRow, float scale, int lane)
{
    int bRow = (lane & 7) + ((lane >> 4) & 1) * 8, bK = ((lane >> 3) & 1) * 8;
    int vRow = (lane & 7) + ((lane >> 3) & 1) * 8, vN = ((lane >> 4) & 1) * 8;

    float s[8][4];
    #pragma unroll
    for (int i = 0; i < 8; ++i)
        #pragma unroll
        for (int q = 0; q < 4; ++q) s[i][q] = 0.f;

    #pragma unroll
    for (int kk = 0; kk < 4; ++kk) {
        uint32_t kh[8][2], kl[8][2];
        #pragma unroll
        for (int np = 0; np < 4; ++np) {
            uint32_t off = bo + (uint32_t)((np * 16 + bRow) * 72 + kk * 16 + bK) * 2;
            uint32_t t[4];
            LDM4(t, sbase + off);
            kh[np*2][0] = t[0]; kh[np*2][1] = t[1]; kh[np*2+1][0] = t[2]; kh[np*2+1][1] = t[3];
            LDM4(t, sbase + 4608 * 2 + off);
            kl[np*2][0] = t[0]; kl[np*2][1] = t[1]; kl[np*2+1][0] = t[2]; kl[np*2+1][1] = t[3];
        }
        #pragma unroll
        for (int nf = 0; nf < 8; ++nf) {
            MMA(s[nf], qh[kk], kh[nf]);
            MMA(s[nf], qh[kk], kl[nf]);
            MMA(s[nf], ql[kk], kh[nf]);
        }
    }
    #pragma unroll
    for (int nf = 0; nf < 8; ++nf) {
        #pragma unroll
        for (int q = 0; q < 4; ++q) s[nf][q] *= scale;
    }
    if (CAUSAL && (c0 + 63 > diagRow)) {
        #pragma unroll
        for (int nf = 0; nf < 8; ++nf) {
            int col = c0 + nf * 8 + (lane & 3) * 2;
            if (col     > row0)     s[nf][0] = -1e30f;
            if (col + 1 > row0)     s[nf][1] = -1e30f;
            if (col     > row0 + 8) s[nf][2] = -1e30f;
            if (col + 1 > row0 + 8) s[nf][3] = -1e30f;
        }
    }
    float t0 = -INFINITY, t1 = -INFINITY;
    #pragma unroll
    for (int nf = 0; nf < 8; ++nf) {
        t0 = fmaxf(t0, fmaxf(s[nf][0], s[nf][1]));
        t1 = fmaxf(t1, fmaxf(s[nf][2], s[nf][3]));
    }
    t0 = fmaxf(t0, __shfl_xor_sync(0xffffffffu, t0, 1));
    t0 = fmaxf(t0, __shfl_xor_sync(0xffffffffu, t0, 2));
    t1 = fmaxf(t1, __shfl_xor_sync(0xffffffffu, t1, 1));
    t1 = fmaxf(t1, __shfl_xor_sync(0xffffffffu, t1, 2));
    float mn0 = fmaxf(mr0, t0), mn1 = fmaxf(mr1, t1);
    float cr0 = exp2f(mr0 - mn0), cr1 = exp2f(mr1 - mn1);
    float sum0 = 0.f, sum1 = 0.f;
    #pragma unroll
    for (int nf = 0; nf < 8; ++nf) {
        s[nf][0] = exp2f(s[nf][0] - mn0);
        s[nf][1] = exp2f(s[nf][1] - mn0);
        s[nf][2] = exp2f(s[nf][2] - mn1);
        s[nf][3] = exp2f(s[nf][3] - mn1);
        sum0 += s[nf][0] + s[nf][1];
        sum1 += s[nf][2] + s[nf][3];
    }
    sum0 += __shfl_xor_sync(0xffffffffu, sum0, 1);
    sum0 += __shfl_xor_sync(0xffffffffu, sum0, 2);
    sum1 += __shfl_xor_sync(0xffffffffu, sum1, 1);
    sum1 += __shfl_xor_sync(0xffffffffu, sum1, 2);
    l0 = l0 * cr0 + sum0; l1 = l1 * cr1 + sum1;
    mr0 = mn0; mr1 = mn1;
    #pragma unroll
    for (int nf = 0; nf < 8; ++nf) {
        o[nf][0] *= cr0; o[nf][1] *= cr0; o[nf][2] *= cr1; o[nf][3] *= cr1;
    }
    #pragma unroll
    for (int kk2 = 0; kk2 < 4; ++kk2) {
        uint32_t Ph[4], Pl[4];
        {
            float a0 = s[2*kk2][0],   a1 = s[2*kk2][1];
            float a2 = s[2*kk2][2],   a3 = s[2*kk2][3];
            float a4 = s[2*kk2+1][0], a5 = s[2*kk2+1][1];
            float a6 = s[2*kk2+1][2], a7 = s[2*kk2+1][3];
            bf h0 = __float2bfloat16(a0), h1 = __float2bfloat16(a1);
            bf h2 = __float2bfloat16(a2), h3 = __float2bfloat16(a3);
            bf h4 = __float2bfloat16(a4), h5 = __float2bfloat16(a5);
            bf h6 = __float2bfloat16(a6), h7 = __float2bfloat16(a7);
            Ph[0] = packbf(__bfloat162float(h0), __bfloat162float(h1));
            Ph[1] = packbf(__bfloat162float(h2), __bfloat162float(h3));
            Ph[2] = packbf(__bfloat162float(h4), __bfloat162float(h5));
            Ph[3] = packbf(__bfloat162float(h6), __bfloat162float(h7));
            Pl[0] = packbf(a0 - __bfloat162float(h0), a1 - __bfloat162float(h1));
            Pl[1] = packbf(a2 - __bfloat162float(h2), a3 - __bfloat162float(h3));
            Pl[2] = packbf(a4 - __bfloat162float(h4), a5 - __bfloat162float(h5));
            Pl[3] = packbf(a6 - __bfloat162float(h6), a7 - __bfloat162float(h7));
        }
        uint32_t vh[8][2], vl[8][2];
        #pragma unroll
        for (int np = 0; np < 4; ++np) {
            uint32_t off = bo + (uint32_t)((kk2 * 16 + vRow) * 72 + np * 16 + vN) * 2;
            uint32_t t[4];
            LDM4T(t, sbase + 9216 * 2 + off);
            vh[np*2][0] = t[0]; vh[np*2][1] = t[1]; vh[np*2+1][0] = t[2]; vh[np*2+1][1] = t[3];
            LDM4T(t, sbase + 13824 * 2 + off);
            vl[np*2][0] = t[0]; vl[np*2][1] = t[1]; vl[np*2+1][0] = t[2]; vl[np*2+1][1] = t[3];
        }
        #pragma unroll
        for (int nf = 0; nf < 8; ++nf) {
            MMA(o[nf], Ph, vh[nf]);
            MMA(o[nf], Ph, vl[nf]);
            MMA(o[nf], Pl, vh[nf]);
        }
    }
}

// prefetch one K/V tile
__device__ __forceinline__ void kv_prefetch(
    uint32_t sbase, uint32_t bn, int c0,
    const bf* pKh, const bf* pKl, int ldk,
    const bf* pVh, const bf* pVl, int ldv, int tid)
{
    int pr = tid >> 3, pch = tid & 7;
    #pragma unroll
    for (int i = 0; i < 2; ++i) {
        int r = pr + i * 32;
        long gk = (long)(c0 + r) * ldk + pch * 8;
        long gv = (long)(c0 + r) * ldv + pch * 8;
        uint32_t so = bn + (uint32_t)(r * 72 + pch * 8) * 2;
        CPA(sbase + so,             pKh + gk);
        CPA(sbase + 4608*2  + so,   pKl + gk);
        CPA(sbase + 9216*2  + so,   pVh + gv);
        CPA(sbase + 13824*2 + so,   pVl + gv);
    }
    CPA_COMMIT();
}

// ---------- single-Q flash (non-causal; cval1), f32 out -----------------------
__global__ void __launch_bounds__(256) fa_k(
    const bf* __restrict__ Ah, const bf* __restrict__ Al, int lda, long sAb, long sAh_,
    const bf* __restrict__ Kh, const bf* __restrict__ Kl, int ldk, long sKb, long sKh_,
    const bf* __restrict__ Vh, const bf* __restrict__ Vl, int ldv, long sVb, long sVh_,
    int S_, float* __restrict__ O, int ldo, long sOb, long sOh_, float scale)
{
    extern __shared__ __align__(16) bf dsm[];
    uint32_t sbase = smem_u32(dsm);

    int z = blockIdx.y, bb = z >> 3, hh = z & 7;
    int m0 = (int)blockIdx.x * 128;
    const bf* pAh = Ah + bb * sAb + hh * sAh_;
    const bf* pAl = Al + bb * sAb + hh * sAh_;
    const bf* pKh = Kh + bb * sKb + hh * sKh_;
    const bf* pKl = Kl + bb * sKb + hh * sKh_;
    const bf* pVh = Vh + bb * sVb + hh * sVh_;
    const bf* pVl = Vl + bb * sVb + hh * sVh_;
    long co = (long)bb * sOb + (long)hh * sOh_;

    int tid = threadIdx.x, lane = tid & 31, wid = tid >> 5;
    int wrow = wid * 16;

    #pragma unroll
    for (int i = 0; i < 4; ++i) {
        int q = tid + i * 256, r = q >> 3, ch = q & 7;
        long go = (long)(m0 + r) * lda + ch * 8;
        *(uint4*)&dsm[r * 72 + ch * 8]        = *(const uint4*)(pAh + go);
        *(uint4*)&dsm[9216 + r * 72 + ch * 8] = *(const uint4*)(pAl + go);
    }
    __syncthreads();
    int aRow = lane & 15, aK = (lane >> 4) * 8;
    uint32_t qh[4][4], ql[4][4];
    #pragma unroll
    for (int kk = 0; kk < 4; ++kk) {
        uint32_t off = (uint32_t)((wrow + aRow) * 72 + kk * 16 + aK) * 2;
        LDM4(qh[kk], sbase + off);
        LDM4(ql[kk], sbase + 9216 * 2 + off);
    }
    __syncthreads();

    float o[8][4];
    #pragma unroll
    for (int i = 0; i < 8; ++i)
        #pragma unroll
        for (int q = 0; q < 4; ++q) o[i][q] = 0.f;
    float mr0 = -INFINITY, mr1 = -INFINITY, l0 = 0.f, l1 = 0.f;

    int nt = S_ >> 6;
    int row0 = m0 + wrow + (lane >> 2);

    kv_prefetch(sbase, 0, 0, pKh, pKl, ldk, pVh, pVl, ldv, tid);

    for (int ct = 0; ct < nt; ++ct) {
        uint32_t bo = (uint32_t)(ct & 1) * 18432u * 2u;
        if (ct + 1 < nt) {
            kv_prefetch(sbase, (uint32_t)((ct + 1) & 1) * 18432u * 2u, (ct + 1) << 6,
                        pKh, pKl, ldk, pVh, pVl, ldv, tid);
            asm volatile("cp.async.wait_group 1;");
        } else {
            asm volatile("cp.async.wait_group 0;");
        }
        __syncthreads();
        attn_tile<false>(sbase, bo, qh, ql, o, mr0, mr1, l0, l1,
                         ct << 6, row0, 0, scale, lane);
        __syncthreads();
    }

    float inv0 = 1.f / l0, inv1 = 1.f / l1;
    #pragma unroll
    for (int nf = 0; nf < 8; ++nf) {
        int col = nf * 8 + (lane & 3) * 2;
        long b0 = co + (long)row0 * ldo + col;
        long b1 = co + (long)(row0 + 8) * ldo + col;
        O[b0] = o[nf][0] * inv0; O[b0 + 1] = o[nf][1] * inv0;
        O[b1] = o[nf][2] * inv1; O[b1 + 1] = o[nf][3] * inv1;
    }
}

// ---------- dual-Q causal flash with FUSED qxG (in-register G-multiply) -------
// Q1 = (q_x @ G) computed in the prologue via the C-frag->A-frag identity;
// numerics identical to the former separate hg<64> pass (same K order, same
// 3-term MMA order, same hi/lo split formula).
__global__ void __launch_bounds__(256) fa2_k(
    const bf* __restrict__ Gh, const bf* __restrict__ Gl,
    const bf* __restrict__ A2h, const bf* __restrict__ A2l, int lda2, long sA2b, long sA2h,
    const bf* __restrict__ Kh, const bf* __restrict__ Kl, int ldk, long sKb, long sKh_,
    const bf* __restrict__ Vh, const bf* __restrict__ Vl, int ldv, long sVb, long sVh_,
    float* __restrict__ O1, bf* __restrict__ O1h, bf* __restrict__ O1l,
    float* __restrict__ O2, bf* __restrict__ O2h, bf* __restrict__ O2l,
    int ldo, long sOb, long sOh_, float scale)
{
    extern __shared__ __align__(16) bf dsm[];
    uint32_t sbase = smem_u32(dsm);

    int z = blockIdx.y, bb = z >> 3, hh = z & 7;
    int m0 = (int)(gridDim.x - 1 - blockIdx.x) * 128;
    const bf* pKh = Kh + bb * sKb + hh * sKh_;
    const bf* pKl = Kl + bb * sKb + hh * sKh_;
    const bf* pVh = Vh + bb * sVb + hh * sVh_;
    const bf* pVl = Vl + bb * sVb + hh * sVh_;
    const bf* pGh = Gh + (long)z * 4096;
    const bf* pGl = Gl + (long)z * 4096;
    long co = (long)bb * sOb + (long)hh * sOh_;

    int tid = threadIdx.x, lane = tid & 31, wid = tid >> 5;
    int wrow = wid * 16;
    int aRow = lane & 15, aK = (lane >> 4) * 8;
    int bRow = (lane & 7) + ((lane >> 4) & 1) * 8, bK = ((lane >> 3) & 1) * 8;
    uint32_t q1h[4][4], q1l[4][4], q2h[4][4], q2l[4][4];

    // stage q_x block -> q2 frags
    {
        const bf* p2h = A2h + bb * sA2b + hh * sA2h;
        const bf* p2l = A2l + bb * sA2b + hh * sA2h;
        #pragma unroll
        for (int i = 0; i < 4; ++i) {
            int q = tid + i * 256, r = q >> 3, ch = q & 7;
            long go = (long)(m0 + r) * lda2 + ch * 8;
            *(uint4*)&dsm[r * 72 + ch * 8]        = *(const uint4*)(p2h + go);
            *(uint4*)&dsm[9216 + r * 72 + ch * 8] = *(const uint4*)(p2l + go);
        }
        __syncthreads();
        #pragma unroll
        for (int kk = 0; kk < 4; ++kk) {
            uint32_t off = (uint32_t)((wrow + aRow) * 72 + kk * 16 + aK) * 2;
            LDM4(q2h[kk], sbase + off);
            LDM4(q2l[kk], sbase + 9216 * 2 + off);
        }
        __syncthreads();
    }

    // stage G^T (64x64 pair, K-tile layout: hi@0, lo@4608 elems)
    {
        #pragma unroll
        for (int i = 0; i < 2; ++i) {
            int idx = tid + i * 256;
            int r = idx >> 3, ch = idx & 7;
            *(uint4*)&dsm[r * 72 + ch * 8]        = *(const uint4*)(pGh + r * 64 + ch * 8);
            *(uint4*)&dsm[4608 + r * 72 + ch * 8] = *(const uint4*)(pGl + r * 64 + ch * 8);
        }
        __syncthreads();

        // q1 = q_x @ G  (score-pass shape, no scale/softmax)
        float sq[8][4];
        #pragma unroll
        for (int i = 0; i < 8; ++i)
            #pragma unroll
            for (int q = 0; q < 4; ++q) sq[i][q] = 0.f;
        #pragma unroll
        for (int kk = 0; kk < 4; ++kk) {
            uint32_t gB[8][2], gBl[8][2];
            #pragma unroll
            for (int np = 0; np < 4; ++np) {
                uint32_t off = (uint32_t)((np * 16 + bRow) * 72 + kk * 16 + bK) * 2;
                uint32_t t[4];
                LDM4(t, sbase + off);
                gB[np*2][0] = t[0]; gB[np*2][1] = t[1]; gB[np*2+1][0] = t[2]; gB[np*2+1][1] = t[3];
                LDM4(t, sbase + 4608 * 2 + off);
                gBl[np*2][0] = t[0]; gBl[np*2][1] = t[1]; gBl[np*2+1][0] = t[2]; gBl[np*2+1][1] = t[3];
            }
            #pragma unroll
            for (int nf = 0; nf < 8; ++nf) {
                MMA(sq[nf], q2h[kk], gB[nf]);
                MMA(sq[nf], q2h[kk], gBl[nf]);
                MMA(sq[nf], q2l[kk], gB[nf]);
            }
        }
        // pack C-frags -> A-frags (hi/lo), same split formula as the old epilogue
        #pragma unroll
        for (int kk = 0; kk < 4; ++kk) {
            float a0 = sq[2*kk][0],   a1 = sq[2*kk][1];
            float a2 = sq[2*kk][2],   a3 = sq[2*kk][3];
            float a4 = sq[2*kk+1][0], a5 = sq[2*kk+1][1];
            float a6 = sq[2*kk+1][2], a7 = sq[2*kk+1][3];
            bf h0 = __float2bfloat16(a0), h1 = __float2bfloat16(a1);
            bf h2 = __float2bfloat16(a2), h3 = __float2bfloat16(a3);
            bf h4 = __float2bfloat16(a4), h5 = __float2bfloat16(a5);
            bf h6 = __float2bfloat16(a6), h7 = __float2bfloat16(a7);
            q1h[kk][0] = packbf(__bfloat162float(h0), __bfloat162float(h1));
            q1h[kk][1] = packbf(__bfloat162float(h2), __bfloat162float(h3));
            q1h[kk][2] = packbf(__bfloat162float(h4), __bfloat162float(h5));
            q1h[kk][3] = packbf(__bfloat162float(h6), __bfloat162float(h7));
            q1l[kk][0] = packbf(a0 - __bfloat162float(h0), a1 - __bfloat162float(h1));
            q1l[kk][1] = packbf(a2 - __bfloat162float(h2), a3 - __bfloat162float(h3));
            q1l[kk][2] = packbf(a4 - __bfloat162float(h4), a5 - __bfloat162float(h5));
            q1l[kk][3] = packbf(a6 - __bfloat162float(h6), a7 - __bfloat162float(h7));
        }
        __syncthreads();
    }

    float o1[8][4], o2[8][4];
    #pragma unroll
    for (int i = 0; i < 8; ++i)
        #pragma unroll
        for (int q = 0; q < 4; ++q) { o1[i][q] = 0.f; o2[i][q] = 0.f; }
    float m10 = -INFINITY, m11 = -INFINITY, l10 = 0.f, l11 = 0.f;
    float m20 = -INFINITY, m21 = -INFINITY, l20 = 0.f, l21 = 0.f;

    int nt = (m0 >> 6) + 2;
    int row0 = m0 + wrow + (lane >> 2);
    int diagRow = m0 + wrow;

    kv_prefetch(sbase, 0, 0, pKh, pKl, ldk, pVh, pVl, ldv, tid);

    for (int ct = 0; ct < nt; ++ct) {
        uint32_t bo = (uint32_t)(ct & 1) * 18432u * 2u;
        if (ct + 1 < nt) {
            kv_prefetch(sbase, (uint32_t)((ct + 1) & 1) * 18432u * 2u, (ct + 1) << 6,
                        pKh, pKl, ldk, pVh, pVl, ldv, tid);
            asm volatile("cp.async.wait_group 1;");
        } else {
            asm volatile("cp.async.wait_group 0;");
        }
        __syncthreads();
        int c0 = ct << 6;
        attn_tile<true>(sbase, bo, q1h, q1l, o1, m10, m11, l10, l11, c0, row0, diagRow, scale, lane);
        attn_tile<true>(sbase, bo, q2h, q2l, o2, m20, m21, l20, l21, c0, row0, diagRow, scale, lane);
        __syncthreads();
    }

    float i10 = 1.f / l10, i11 = 1.f / l11, i20 = 1.f / l20, i21 = 1.f / l21;
    #pragma unroll
    for (int nf = 0; nf < 8; ++nf) {
        int col = nf * 8 + (lane & 3) * 2;
        long b0 = co + (long)row0 * ldo + col;
        long b1 = co + (long)(row0 + 8) * ldo + col;
        float v0 = o1[nf][0] * i10 + O1[b0], v1 = o1[nf][1] * i10 + O1[b0 + 1];
        float v2 = o1[nf][2] * i11 + O1[b1], v3 = o1[nf][3] * i11 + O1[b1 + 1];
        O1[b0] = v0; O1[b0 + 1] = v1; O1[b1] = v2; O1[b1 + 1] = v3;
        bf h0 = __float2bfloat16(v0), h1 = __float2bfloat16(v1);
        bf h2 = __float2bfloat16(v2), h3 = __float2bfloat16(v3);
        *reinterpret_cast<uint32_t*>(O1h + b0) = packbf(__bfloat162float(h0), __bfloat162float(h1));
        *reinterpret_cast<uint32_t*>(O1h + b1) = packbf(__bfloat162float(h2), __bfloat162float(h3));
        *reinterpret_cast<uint32_t*>(O1l + b0) = packbf(v0 - __bfloat162float(h0), v1 - __bfloat162float(h1));
        *reinterpret_cast<uint32_t*>(O1l + b1) = packbf(v2 - __bfloat162float(h2), v3 - __bfloat162float(h3));
        float w0 = o2[nf][0] * i20, w1 = o2[nf][1] * i20;
        float w2 = o2[nf][2] * i21, w3 = o2[nf][3] * i21;
        O2[b0] = w0; O2[b0 + 1] = w1; O2[b1] = w2; O2[b1 + 1] = w3;
        bf g0 = __float2bfloat16(w0), g1 = __float2bfloat16(w1);
        bf g2 = __float2bfloat16(w2), g3 = __float2bfloat16(w3);
        *reinterpret_cast<uint32_t*>(O2h + b0) = packbf(__bfloat162float(g0), __bfloat162float(g1));
        *reinterpret_cast<uint32_t*>(O2h + b1) = packbf(__bfloat162float(g2), __bfloat162float(g3));
        *reinterpret_cast<uint32_t*>(O2l + b0) = packbf(w0 - __bfloat162float(g0), w1 - __bfloat162float(g1));
        *reinterpret_cast<uint32_t*>(O2l + b1) = packbf(w2 - __bfloat162float(g2), w3 - __bfloat162float(g3));
    }
}

// ---------- G partials + reduce ----------
__global__ void __launch_bounds__(256) g1_k(const bf* __restrict__ qh, const bf* __restrict__ ql,
                                            float* __restrict__ part)
{
    int z = blockIdx.x, ck = blockIdx.y;
    int b = z >> 3, h = z & 7;
    int m0 = ck * 64;
    long kyo = (long)b * Mv * 3 * Cv + (long)h * Dv + Cv;
    long qyo = (long)b * Mv * 3 * Cv + (long)h * Dv;
    __shared__ float sky[64][65], sqy[64][65];
    int tid = threadIdx.x;
    int d2 = tid & 63, gg = tid >> 6;
    float acc[16];
    #pragma unroll
    for (int i = 0; i < 16; ++i) acc[i] = 0.f;
    #pragma unroll
    for (int i = 0; i < 16; ++i) {
        int q = tid + i * 256;
        int mm = q >> 6, dd = q & 63;
        long ik = kyo + (long)(m0 + mm) * 3 * Cv + dd;
        long iq = qyo + (long)(m0 + mm) * 3 * Cv + dd;
        sky[mm][dd] = __bfloat162float(qh[ik]) + __bfloat162float(ql[ik]);
        sqy[mm][dd] = __bfloat162float(qh[iq]) + __bfloat162float(ql[iq]);
    }
    __syncthreads();
    for (int mm = 0; mm < 64; ++mm) {
        float qv = sqy[mm][d2];
        #pragma unroll
        for (int i = 0; i < 16; ++i)
            acc[i] += sky[mm][gg * 16 + i] * qv;
    }
    long base = ((long)z * 8 + ck) * 4096 + (long)d2 * 64 + gg * 16;
    #pragma unroll
    for (int i = 0; i < 16; ++i) part[base + i] = acc[i];
}
__global__ void __launch_bounds__(256) g2_k(const float* __restrict__ part,
                                            bf* __restrict__ goh, bf* __restrict__ gol)
{
    int z = blockIdx.x, tid = threadIdx.x;
    #pragma unroll
    for (int i = 0; i < 16; ++i) {
        int idx = tid + i * 256;
        float s = 0.f;
        #pragma unroll
        for (int ck = 0; ck < 8; ++ck)
            s += part[((long)z * 8 + ck) * 4096 + idx];
        float v = s * (SCL * SCL);
        bf hh = __float2bfloat16(v);
        long o = (long)z * 4096 + idx;
        goh[o] = hh;
        gol[o] = __float2bfloat16(v - __bfloat162float(hh));
    }
}

// ---------- splits ----------
__global__ void __launch_bounds__(256) split_k(const float* __restrict__ in, bf* __restrict__ oh,
                                               bf* __restrict__ ol, long n) {
    long i = (long)blockIdx.x * 256 + threadIdx.x;
    if (i < n) {
        float v = in[i]; bf h = __float2bfloat16(v);
        oh[i] = h; ol[i] = __float2bfloat16(v - __bfloat162float(h));
    }
}
__global__ void __launch_bounds__(256) splitW_k(
    const float* __restrict__ w0, const float* __restrict__ w1,
    const float* __restrict__ w2, const float* __restrict__ w3,
    const float* __restrict__ w4, bf* __restrict__ oh, bf* __restrict__ ol)
{
    int job = blockIdx.y;
    const float* src; long off; int Nd;
    switch (job) {
        case 0:  src = w0; off = oWQX; Nd = 3 * Cv; break;
        case 1:  src = w1; off = oWQY; Nd = 3 * Cv; break;
        case 2:  src = w2; off = oWGS; Nd = Cv; break;
        case 3:  src = w3; off = oWGC; Nd = Cv; break;
        default: src = w4; off = oWP;  Nd = Cv; break;
    }
    long n = (long)Cv * Nd;
    long i = (long)blockIdx.x * 256 + threadIdx.x;
    if (i >= n) return;
    int nn = (int)(i / Cv), k = (int)(i % Cv);
    float v = src[(long)k * Nd + nn];
    bf h = __float2bfloat16(v);
    oh[off + i] = h;
    ol[off + i] = __float2bfloat16(v - __bfloat162float(h));
}

// ---------- gate combine (pair out) ----------
__global__ void __launch_bounds__(256) gate_k(
    const float* __restrict__ t1, const float* __restrict__ t2,
    const float* __restrict__ bgs, const float* __restrict__ bgc,
    const float* __restrict__ cv, const float* __restrict__ sv,
    bf* __restrict__ oh, bf* __restrict__ ol, long n)
{
    long i = (long)blockIdx.x * 256 + threadIdx.x;
    if (i < n) {
        int c = (int)(i & (Cv - 1));
        float g1 = 1.f / (1.f + __expf(-(t1[i] + bgs[c])));
        float g2 = 1.f / (1.f + __expf(-(t2[i] + bgc[c])));
        float v = g1 * cv[i] + g2 * sv[i];
        bf h = __float2bfloat16(v);
        oh[i] = h; ol[i] = __float2bfloat16(v - __bfloat162float(h));
    }
}

// ------------------------------------------------------------------------------
extern "C" void kernel_launch(void* const* d_in, const int* in_sizes, int n_in,
                              void* d_out, int out_size)
{
    const float* x      = (const float*)d_in[0];
    const float* y      = (const float*)d_in[1];
    const float* Wqkv_x = (const float*)d_in[3];
    const float* bqkv_x = (const float*)d_in[4];
    const float* Wqkv_y = (const float*)d_in[5];
    const float* bqkv_y = (const float*)d_in[6];
    const float* Wgs    = (const float*)d_in[7];
    const float* bgs    = (const float*)d_in[8];
    const float* Wgc    = (const float*)d_in[9];
    const float* bgc    = (const float*)d_in[10];
    const float* Wp     = (const float*)d_in[11];
    const float* bp     = (const float*)d_in[12];
    float* out = (float*)d_out;

    bf *gh, *gl; float* gf;
    cudaGetSymbolAddress((void**)&gh, g_h);
    cudaGetSymbolAddress((void**)&gl, g_l);
    cudaGetSymbolAddress((void**)&gf, g_f);

    const int FASM   = 2 * 18432 * 2;
    const int HGSM128 = 2 * (10240 + 2 * 128 * 40) * 2;
    cudaFuncSetAttribute((const void*)fa_k,  cudaFuncAttributeMaxDynamicSharedMemorySize, FASM);
    cudaFuncSetAttribute((const void*)fa2_k, cudaFuncAttributeMaxDynamicSharedMemorySize, FASM);
    cudaFuncSetAttribute((const void*)hg<128,false,true,true>,  cudaFuncAttributeMaxDynamicSharedMemorySize, HGSM128);
    cudaFuncSetAttribute((const void*)hg<128,true,false,false>, cudaFuncAttributeMaxDynamicSharedMemorySize, HGSM128);
    cudaFuncSetAttribute((const void*)hg<128,true,false,true>,  cudaFuncAttributeMaxDynamicSharedMemorySize, HGSM128);

    dim3 blk(256);
    long nTC = nTCe;

    // splits
    splitW_k<<<dim3(3072, 5), blk>>>(Wqkv_x, Wqkv_y, Wgs, Wgc, Wp, gh, gl);
    split_k<<<(unsigned)((nTC + 255) / 256), blk>>>(x, gh + oXB, gl + oXB, nTC);
    split_k<<<(unsigned)((BBv*Mv*Cv + 255) / 256), blk>>>(y, gh + oYB, gl + oYB, (long)BBv*Mv*Cv);

    // qkv projections (pipelined hg, 2 CTAs/SM, pair out)
    hg<128,false,true,true><<<dim3(12,32,1), blk, HGSM128>>>(
        gh+oXB, gl+oXB, Cv, 0,0, gh+oWQX, gl+oWQX, Cv, 0,0,
        nullptr, gh+oQKVX, gl+oQKVX, 3*Cv, 0,0, bqkv_x, Cv, 1, 1.0f);
    hg<128,false,true,true><<<dim3(12,8,1), blk, HGSM128>>>(
        gh+oYB, gl+oYB, Cv, 0,0, gh+oWQY, gl+oWQY, Cv, 0,0,
        nullptr, gh+oQKVY, gl+oQKVY, 3*Cv, 0,0, bqkv_y, Cv, 1, 1.0f);

    // G (split-K)
    g1_k<<<dim3(BHv, 8), blk>>>(gh+oQKVY, gl+oQKVY, gf+fT1);
    g2_k<<<BHv, blk>>>(gf+fT1, gh+oGT, gl+oGT);

    // cval1 (fused, non-causal); scale folded with log2e
    fa_k<<<dim3(16,16), blk, FASM>>>(
        gh+oQKVX, gl+oQKVX, 3*Cv, (long)Tv*3*Cv, (long)Dv,
        gh+oQKVY+Cv, gl+oQKVY+Cv, 3*Cv, (long)Mv*3*Cv, (long)Dv,
        gh+oQKVY+2*Cv, gl+oQKVY+2*Cv, 3*Cv, (long)Mv*3*Cv, (long)Dv,
        Mv, gf+fCV, Cv, (long)Tv*Cv, (long)Dv, SCL * LOG2E);

    // dual-Q causal with fused qxG: cval (+pair) and sval (+pair)
    fa2_k<<<dim3(16,16), blk, FASM>>>(
        gh+oGT, gl+oGT,
        gh+oQKVX, gl+oQKVX, 3*Cv, (long)Tv*3*Cv, (long)Dv,
        gh+oQKVX+Cv, gl+oQKVX+Cv, 3*Cv, (long)Tv*3*Cv, (long)Dv,
        gh+oQKVX+2*Cv, gl+oQKVX+2*Cv, 3*Cv, (long)Tv*3*Cv, (long)Dv,
        gf+fCV, gh+oCV, gl+oCV,
        gf+fSV, gh+oSV, gl+oSV,
        Cv, (long)Tv*Cv, (long)Dv, SCL * LOG2E);

    // gates batched z=2: t1 = sval@Wgs, t2 = cval@Wgc
    hg<128,true,false,false><<<dim3(4,32,2), blk, HGSM128>>>(
        gh+oSV, gl+oSV, Cv, 0, nTC,
        gh+oWGS, gl+oWGS, Cv, 0, (long)Cv*Cv,
        gf+fT1, nullptr, nullptr, Cv, 0, nTC, nullptr, Cv, 2, 1.0f);

    gate_k<<<(unsigned)((nTC + 255) / 256), blk>>>(
        gf+fT1, gf+fT2, bgs, bgc, gf+fCV, gf+fSV, gh+oT3, gl+oT3, nTC);

    // out = t3 @ Wp + bp
    hg<128,true,false,true><<<dim3(4,32,1), blk, HGSM128>>>(
        gh+oT3, gl+oT3, Cv, 0,0, gh+oWP, gl+oWP, Cv, 0,0,
        out, nullptr, nullptr, Cv, 0,0, bp, Cv, 1, 1.0f);
}

// round 16
// speedup vs baseline: 1.3794x; 1.1532x over previous
#include <cuda_runtime.h>
#include <cuda_bf16.h>
#include <cstdint>
#include <math.h>

#define BBv 2
#define Tv 2048
#define Mv 512
#define Cv 512
#define Hv 8
#define Dv 64
#define BHv 16
#define SCL 0.125f
#define LOG2E 1.4426950408889634f
typedef __nv_bfloat16 bf;

// ---------- bf16 pair pool offsets ----------
constexpr long oXB   = 0;
constexpr long oYB   = oXB   + (long)BBv*Tv*Cv;
constexpr long oWQX  = oYB   + (long)BBv*Mv*Cv;
constexpr long oWQY  = oWQX  + (long)Cv*3*Cv;
constexpr long oWGS  = oWQY  + (long)Cv*3*Cv;
constexpr long oWGC  = oWGS  + (long)Cv*Cv;
constexpr long oWP   = oWGC  + (long)Cv*Cv;
constexpr long oQKVX = oWP   + (long)Cv*Cv;
constexpr long oQKVY = oQKVX + (long)BBv*Tv*3*Cv;
constexpr long oGT   = oQKVY + (long)BBv*Mv*3*Cv;
constexpr long oSV   = oGT   + (long)BHv*Dv*Dv;
constexpr long oCV   = oSV   + (long)BBv*Tv*Cv;
constexpr long oT3   = oCV   + (long)BBv*Tv*Cv;
constexpr long NBF   = oT3   + (long)BBv*Tv*Cv;
// ---------- fp32 pool ----------
constexpr long nTCe = (long)BBv*Tv*Cv;
constexpr long fSV = 0;
constexpr long fCV = fSV + nTCe;
constexpr long fC2 = fCV + nTCe;
constexpr long fT1 = fC2 + nTCe;      // also G partial scratch early
constexpr long fT2 = fT1 + nTCe;
constexpr long NF_ = fT2 + nTCe;

__device__ bf    g_h[NBF];
__device__ bf    g_l[NBF];
__device__ float g_f[NF_];

// ---------- helpers ----------
__device__ __forceinline__ uint32_t smem_u32(const void* p) {
    uint32_t a;
    asm("{ .reg .u64 t; cvta.to.shared.u64 t, %1; cvt.u32.u64 %0, t; }" : "=r"(a) : "l"(p));
    return a;
}
#define LDM4(r, addr) asm volatile( \
    "ldmatrix.sync.aligned.m8n8.x4.shared.b16 {%0,%1,%2,%3}, [%4];" \
    : "=r"((r)[0]), "=r"((r)[1]), "=r"((r)[2]), "=r"((r)[3]) : "r"(addr))
#define LDM4T(r, addr) asm volatile( \
    "ldmatrix.sync.aligned.m8n8.x4.trans.shared.b16 {%0,%1,%2,%3}, [%4];" \
    : "=r"((r)[0]), "=r"((r)[1]), "=r"((r)[2]), "=r"((r)[3]) : "r"(addr))
#define MMA(c, a, b) asm volatile( \
    "mma.sync.aligned.m16n8k16.row.col.f32.bf16.bf16.f32 " \
    "{%0,%1,%2,%3}, {%4,%5,%6,%7}, {%8,%9}, {%0,%1,%2,%3};" \
    : "+f"((c)[0]), "+f"((c)[1]), "+f"((c)[2]), "+f"((c)[3]) \
    : "r"((a)[0]), "r"((a)[1]), "r"((a)[2]), "r"((a)[3]), "r"((b)[0]), "r"((b)[1]))
#define CPA(sa, ga) asm volatile("cp.async.cg.shared.global [%0], [%1], 16;" :: "r"(sa), "l"(ga))
#define CPA_COMMIT() asm volatile("cp.async.commit_group;")

__device__ __forceinline__ uint32_t packbf(float a, float b) {
    __nv_bfloat162 t; t.x = __float2bfloat16(a); t.y = __float2bfloat16(b);
    return *reinterpret_cast<uint32_t*>(&t);
}
__device__ __forceinline__ void split4(float4 v, uint2& hi, uint2& lo) {
    bf h0 = __float2bfloat16(v.x), h1 = __float2bfloat16(v.y);
    bf h2 = __float2bfloat16(v.z), h3 = __float2bfloat16(v.w);
    hi.x = packbf(__bfloat162float(h0), __bfloat162float(h1));
    hi.y = packbf(__bfloat162float(h2), __bfloat162float(h3));
    lo.x = packbf(v.x - __bfloat162float(h0), v.y - __bfloat162float(h1));
    lo.y = packbf(v.z - __bfloat162float(h2), v.w - __bfloat162float(h3));
}

// ---------- pipelined HMMA split-bf16 GEMM: C = alpha*(A@B^T) (+bias) ---------
template<int TN, bool F32O, bool PO, bool BIAS>
__global__ void __launch_bounds__(256, 2) hg(
    const bf* __restrict__ Ah, const bf* __restrict__ Al, int lda, long sAb, long sAh_,
    const bf* __restrict__ Bh, const bf* __restrict__ Bl, int ldb, long sBb, long sBh_,
    float* __restrict__ C, bf* __restrict__ Ch, bf* __restrict__ Cl, int ldc, long sCb, long sCh_,
    const float* __restrict__ bias, int K, int Hn, float alpha)
{
    constexpr int NFRAG = TN / 16;
    constexpr uint32_t STG = (10240 + 2 * TN * 40) * 2;
    extern __shared__ __align__(16) bf dsm[];
    uint32_t sbase = smem_u32(dsm);

    int m0 = blockIdx.y * 128, n0 = blockIdx.x * TN;
    int z = blockIdx.z, bb = z / Hn, hh = z - bb * Hn;
    const bf* pAh = Ah + bb * sAb + hh * sAh_;
    const bf* pAl = Al + bb * sAb + hh * sAh_;
    const bf* pBh = Bh + bb * sBb + hh * sBh_;
    const bf* pBl = Bl + bb * sBb + hh * sBh_;
    long co = bb * sCb + hh * sCh_;

    int tid = threadIdx.x, lane = tid & 31, wid = tid >> 5;
    int wm = (wid & 3) * 32, wn = (wid >> 2) * (TN / 2);

    float acc[2][NFRAG][4];
    #pragma unroll
    for (int i = 0; i < 2; ++i)
        #pragma unroll
        for (int j = 0; j < NFRAG; ++j)
            #pragma unroll
            for (int q = 0; q < 4; ++q) acc[i][j][q] = 0.f;

    int kst = K >> 5;
    int aRow = (lane & 15), aK = (lane >> 4) * 8;
    int bRow = (lane & 7) + ((lane >> 4) & 1) * 8, bK = ((lane >> 3) & 1) * 8;

    auto prefetch = [&](int s) {
        uint32_t st = sbase + (uint32_t)(s & 1) * STG;
        int k0 = s << 5;
        #pragma unroll
        for (int i = 0; i < 2; ++i) {
            int idx = tid + i * 256;
            int r = idx >> 2, c = idx & 3;
            long go = (long)(m0 + r) * lda + k0 + c * 8;
            uint32_t so = (uint32_t)(r * 40 + c * 8) * 2;
            CPA(st + so,            pAh + go);
            CPA(st + 5120*2 + so,   pAl + go);
        }
        #pragma unroll
        for (int i = 0; i < TN / 64; ++i) {
            int idx = tid + i * 256;
            int r = idx >> 2, c = idx & 3;
            long go = (long)(n0 + r) * ldb + k0 + c * 8;
            uint32_t so = (uint32_t)(r * 40 + c * 8) * 2;
            CPA(st + 10240*2 + so,             pBh + go);
            CPA(st + (10240 + TN*40)*2 + so,   pBl + go);
        }
        CPA_COMMIT();
    };

    prefetch(0);

    for (int s = 0; s < kst; ++s) {
        if (s + 1 < kst) {
            prefetch(s + 1);
            asm volatile("cp.async.wait_group 1;");
        } else {
            asm volatile("cp.async.wait_group 0;");
        }
        __syncthreads();
        uint32_t st = sbase + (uint32_t)(s & 1) * STG;

        #pragma unroll
        for (int kk = 0; kk < 2; ++kk) {
            uint32_t ah[2][4], al[2][4];
            #pragma unroll
            for (int mf = 0; mf < 2; ++mf) {
                uint32_t off = (uint32_t)((wm + mf * 16 + aRow) * 40 + kk * 16 + aK) * 2;
                LDM4(ah[mf], st + off);
                LDM4(al[mf], st + 5120*2 + off);
            }
            uint32_t bh[NFRAG][2], bl[NFRAG][2];
            #pragma unroll
            for (int np = 0; np < NFRAG / 2; ++np) {
                uint32_t off = (uint32_t)((wn + np * 16 + bRow) * 40 + kk * 16 + bK) * 2;
                uint32_t t[4];
                LDM4(t, st + 10240*2 + off);
                bh[np*2][0] = t[0]; bh[np*2][1] = t[1]; bh[np*2+1][0] = t[2]; bh[np*2+1][1] = t[3];
                LDM4(t, st + (10240 + TN*40)*2 + off);
                bl[np*2][0] = t[0]; bl[np*2][1] = t[1]; bl[np*2+1][0] = t[2]; bl[np*2+1][1] = t[3];
            }
            #pragma unroll
            for (int mf = 0; mf < 2; ++mf)
                #pragma unroll
                for (int nf = 0; nf < NFRAG; ++nf) {
                    MMA(acc[mf][nf], ah[mf], bh[nf]);
                    MMA(acc[mf][nf], ah[mf], bl[nf]);
                    MMA(acc[mf][nf], al[mf], bh[nf]);
                }
        }
        __syncthreads();
    }

    int rb = m0 + wm + (lane >> 2);
    int cb = n0 + wn + (lane & 3) * 2;
    #pragma unroll
    for (int mf = 0; mf < 2; ++mf)
        #pragma unroll
        for (int half = 0; half < 2; ++half) {
            long row = rb + mf * 16 + half * 8;
            #pragma unroll
            for (int nf = 0; nf < NFRAG; ++nf) {
                int cc = cb + nf * 8;
                float v0 = alpha * acc[mf][nf][half * 2 + 0];
                float v1 = alpha * acc[mf][nf][half * 2 + 1];
                if (BIAS) { v0 += bias[cc]; v1 += bias[cc + 1]; }
                long base = co + row * (long)ldc + cc;
                if (F32O) { C[base] = v0; C[base + 1] = v1; }
                if (PO) {
                    bf h0 = __float2bfloat16(v0), h1 = __float2bfloat16(v1);
                    *reinterpret_cast<uint32_t*>(Ch + base) = packbf(__bfloat162float(h0), __bfloat162float(h1));
                    *reinterpret_cast<uint32_t*>(Cl + base) = packbf(v0 - __bfloat162float(h0), v1 - __bfloat162float(h1));
                }
            }
        }
}

// ---------- shared attention tile step ----------
template<bool CAUSAL>
__device__ __forceinline__ void attn_tile(
    uint32_t sbase, uint32_t bo,
    uint32_t (&qh)[4][4], uint32_t (&ql)[4][4],
    float (&o)[8][4], float& mr0, float& mr1, float& l0, float& l1,
    int c0, int row0, int diagRow, float scale, int lane)
{
    int bRow = (lane & 7) + ((lane >> 4) & 1) * 8, bK = ((lane >> 3) & 1) * 8;
    int vRow = (lane & 7) + ((lane >> 3) & 1) * 8, vN = ((lane >> 4) & 1) * 8;

    float s[8][4];
    #pragma unroll
    for (int i = 0; i < 8; ++i)
        #pragma unroll
        for (int q = 0; q < 4; ++q) s[i][q] = 0.f;

    #pragma unroll
    for (int kk = 0; kk < 4; ++kk) {
        uint32_t kh[8][2], kl[8][2];
        #pragma unroll
        for (int np = 0; np < 4; ++np) {
            uint32_t off = bo + (uint32_t)((np * 16 + bRow) * 72 + kk * 16 + bK) * 2;
            uint32_t t[4];
            LDM4(t, sbase + off);
            kh[np*2][0] = t[0]; kh[np*2][1] = t[1]; kh[np*2+1][0] = t[2]; kh[np*2+1][1] = t[3];
            LDM4(t, sbase + 4608 * 2 + off);
            kl[np*2][0] = t[0]; kl[np*2][1] = t[1]; kl[np*2+1][0] = t[2]; kl[np*2+1][1] = t[3];
        }
        #pragma unroll
        for (int nf = 0; nf < 8; ++nf) {
            MMA(s[nf], qh[kk], kh[nf]);
            MMA(s[nf], qh[kk], kl[nf]);
            MMA(s[nf], ql[kk], kh[nf]);
        }
    }
    #pragma unroll
    for (int nf = 0; nf < 8; ++nf) {
        #pragma unroll
        for (int q = 0; q < 4; ++q) s[nf][q] *= scale;
    }
    if (CAUSAL && (c0 + 63 > diagRow)) {
        #pragma unroll
        for (int nf = 0; nf < 8; ++nf) {
            int col = c0 + nf * 8 + (lane & 3) * 2;
            if (col     > row0)     s[nf][0] = -1e30f;
            if (col + 1 > row0)     s[nf][1] = -1e30f;
            if (col     > row0 + 8) s[nf][2] = -1e30f;
            if (col + 1 > row0 + 8) s[nf][3] = -1e30f;
        }
    }
    float t0 = -INFINITY, t1 = -INFINITY;
    #pragma unroll
    for (int nf = 0; nf < 8; ++nf) {
        t0 = fmaxf(t0, fmaxf(s[nf][0], s[nf][1]));
        t1 = fmaxf(t1, fmaxf(s[nf][2], s[nf][3]));
    }
    t0 = fmaxf(t0, __shfl_xor_sync(0xffffffffu, t0, 1));
    t0 = fmaxf(t0, __shfl_xor_sync(0xffffffffu, t0, 2));
    t1 = fmaxf(t1, __shfl_xor_sync(0xffffffffu, t1, 1));
    t1 = fmaxf(t1, __shfl_xor_sync(0xffffffffu, t1, 2));
    float mn0 = fmaxf(mr0, t0), mn1 = fmaxf(mr1, t1);
    float cr0 = exp2f(mr0 - mn0), cr1 = exp2f(mr1 - mn1);
    float sum0 = 0.f, sum1 = 0.f;
    #pragma unroll
    for (int nf = 0; nf < 8; ++nf) {
        s[nf][0] = exp2f(s[nf][0] - mn0);
        s[nf][1] = exp2f(s[nf][1] - mn0);
        s[nf][2] = exp2f(s[nf][2] - mn1);
        s[nf][3] = exp2f(s[nf][3] - mn1);
        sum0 += s[nf][0] + s[nf][1];
        sum1 += s[nf][2] + s[nf][3];
    }
    sum0 += __shfl_xor_sync(0xffffffffu, sum0, 1);
    sum0 += __shfl_xor_sync(0xffffffffu, sum0, 2);
    sum1 += __shfl_xor_sync(0xffffffffu, sum1, 1);
    sum1 += __shfl_xor_sync(0xffffffffu, sum1, 2);
    l0 = l0 * cr0 + sum0; l1 = l1 * cr1 + sum1;
    mr0 = mn0; mr1 = mn1;
    #pragma unroll
    for (int nf = 0; nf < 8; ++nf) {
        o[nf][0] *= cr0; o[nf][1] *= cr0; o[nf][2] *= cr1; o[nf][3] *= cr1;
    }
    #pragma unroll
    for (int kk2 = 0; kk2 < 4; ++kk2) {
        uint32_t Ph[4], Pl[4];
        {
            float a0 = s[2*kk2][0],   a1 = s[2*kk2][1];
            float a2 = s[2*kk2][2],   a3 = s[2*kk2][3];
            float a4 = s[2*kk2+1][0], a5 = s[2*kk2+1][1];
            float a6 = s[2*kk2+1][2], a7 = s[2*kk2+1][3];
            bf h0 = __float2bfloat16(a0), h1 = __float2bfloat16(a1);
            bf h2 = __float2bfloat16(a2), h3 = __float2bfloat16(a3);
            bf h4 = __float2bfloat16(a4), h5 = __float2bfloat16(a5);
            bf h6 = __float2bfloat16(a6), h7 = __float2bfloat16(a7);
            Ph[0] = packbf(__bfloat162float(h0), __bfloat162float(h1));
            Ph[1] = packbf(__bfloat162float(h2), __bfloat162float(h3));
            Ph[2] = packbf(__bfloat162float(h4), __bfloat162float(h5));
            Ph[3] = packbf(__bfloat162float(h6), __bfloat162float(h7));
            Pl[0] = packbf(a0 - __bfloat162float(h0), a1 - __bfloat162float(h1));
            Pl[1] = packbf(a2 - __bfloat162float(h2), a3 - __bfloat162float(h3));
            Pl[2] = packbf(a4 - __bfloat162float(h4), a5 - __bfloat162float(h5));
            Pl[3] = packbf(a6 - __bfloat162float(h6), a7 - __bfloat162float(h7));
        }
        uint32_t vh[8][2], vl[8][2];
        #pragma unroll
        for (int np = 0; np < 4; ++np) {
            uint32_t off = bo + (uint32_t)((kk2 * 16 + vRow) * 72 + np * 16 + vN) * 2;
            uint32_t t[4];
            LDM4T(t, sbase + 9216 * 2 + off);
            vh[np*2][0] = t[0]; vh[np*2][1] = t[1]; vh[np*2+1][0] = t[2]; vh[np*2+1][1] = t[3];
            LDM4T(t, sbase + 13824 * 2 + off);
            vl[np*2][0] = t[0]; vl[np*2][1] = t[1]; vl[np*2+1][0] = t[2]; vl[np*2+1][1] = t[3];
        }
        #pragma unroll
        for (int nf = 0; nf < 8; ++nf) {
            MMA(o[nf], Ph, vh[nf]);
            MMA(o[nf], Ph, vl[nf]);
            MMA(o[nf], Pl, vh[nf]);
        }
    }
}

// prefetch one K/V tile
__device__ __forceinline__ void kv_prefetch(
    uint32_t sbase, uint32_t bn, int c0,
    const bf* pKh, const bf* pKl, int ldk,
    const bf* pVh, const bf* pVl, int ldv, int tid)
{
    int pr = tid >> 3, pch = tid & 7;
    #pragma unroll
    for (int i = 0; i < 2; ++i) {
        int r = pr + i * 32;
        long gk = (long)(c0 + r) * ldk + pch * 8;
        long gv = (long)(c0 + r) * ldv + pch * 8;
        uint32_t so = bn + (uint32_t)(r * 72 + pch * 8) * 2;
        CPA(sbase + so,             pKh + gk);
        CPA(sbase + 4608*2  + so,   pKl + gk);
        CPA(sbase + 9216*2  + so,   pVh + gv);
        CPA(sbase + 13824*2 + so,   pVl + gv);
    }
    CPA_COMMIT();
}

// ---------- unified flash kernel: y<16 => dual-Q causal (cval2->fC2, sval);
//                                  y>=16 => non-causal cval1 -> fCV -----------
__global__ void __launch_bounds__(256) fa_u(
    const bf* __restrict__ gh_, const bf* __restrict__ gl_, float* __restrict__ gf_,
    float scale)
{
    extern __shared__ __align__(16) bf dsm[];
    uint32_t sbase = smem_u32(dsm);
    int tid = threadIdx.x, lane = tid & 31, wid = tid >> 5;
    int wrow = wid * 16;
    int aRow = lane & 15, aK = (lane >> 4) * 8;

    if (blockIdx.y < 16) {
        // ===== dual-Q causal role =====
        int z = blockIdx.y, bb = z >> 3, hh = z & 7;
        int m0 = (int)(gridDim.x - 1 - blockIdx.x) * 128;
        const bf* pKh = gh_ + oQKVX + Cv + (long)bb * Tv * 3 * Cv + (long)hh * Dv;
        const bf* pKl = gl_ + oQKVX + Cv + (long)bb * Tv * 3 * Cv + (long)hh * Dv;
        const bf* pVh = gh_ + oQKVX + 2*Cv + (long)bb * Tv * 3 * Cv + (long)hh * Dv;
        const bf* pVl = gl_ + oQKVX + 2*Cv + (long)bb * Tv * 3 * Cv + (long)hh * Dv;
        const bf* pGh = gh_ + oGT + (long)z * 4096;
        const bf* pGl = gl_ + oGT + (long)z * 4096;
        long co = (long)bb * Tv * Cv + (long)hh * Dv;
        int bRow = (lane & 7) + ((lane >> 4) & 1) * 8, bK = ((lane >> 3) & 1) * 8;
        uint32_t q1h[4][4], q1l[4][4], q2h[4][4], q2l[4][4];

        {
            const bf* p2h = gh_ + oQKVX + (long)bb * Tv * 3 * Cv + (long)hh * Dv;
            const bf* p2l = gl_ + oQKVX + (long)bb * Tv * 3 * Cv + (long)hh * Dv;
            #pragma unroll
            for (int i = 0; i < 4; ++i) {
                int q = tid + i * 256, r = q >> 3, ch = q & 7;
                long go = (long)(m0 + r) * 3 * Cv + ch * 8;
                *(uint4*)&dsm[r * 72 + ch * 8]        = *(const uint4*)(p2h + go);
                *(uint4*)&dsm[9216 + r * 72 + ch * 8] = *(const uint4*)(p2l + go);
            }
            __syncthreads();
            #pragma unroll
            for (int kk = 0; kk < 4; ++kk) {
                uint32_t off = (uint32_t)((wrow + aRow) * 72 + kk * 16 + aK) * 2;
                LDM4(q2h[kk], sbase + off);
                LDM4(q2l[kk], sbase + 9216 * 2 + off);
            }
            __syncthreads();
        }
        {
            #pragma unroll
            for (int i = 0; i < 2; ++i) {
                int idx = tid + i * 256;
                int r = idx >> 3, ch = idx & 7;
                *(uint4*)&dsm[r * 72 + ch * 8]        = *(const uint4*)(pGh + r * 64 + ch * 8);
                *(uint4*)&dsm[4608 + r * 72 + ch * 8] = *(const uint4*)(pGl + r * 64 + ch * 8);
            }
            __syncthreads();
            float sq[8][4];
            #pragma unroll
            for (int i = 0; i < 8; ++i)
                #pragma unroll
                for (int q = 0; q < 4; ++q) sq[i][q] = 0.f;
            #pragma unroll
            for (int kk = 0; kk < 4; ++kk) {
                uint32_t gB[8][2], gBl[8][2];
                #pragma unroll
                for (int np = 0; np < 4; ++np) {
                    uint32_t off = (uint32_t)((np * 16 + bRow) * 72 + kk * 16 + bK) * 2;
                    uint32_t t[4];
                    LDM4(t, sbase + off);
                    gB[np*2][0] = t[0]; gB[np*2][1] = t[1]; gB[np*2+1][0] = t[2]; gB[np*2+1][1] = t[3];
                    LDM4(t, sbase + 4608 * 2 + off);
                    gBl[np*2][0] = t[0]; gBl[np*2][1] = t[1]; gBl[np*2+1][0] = t[2]; gBl[np*2+1][1] = t[3];
                }
                #pragma unroll
                for (int nf = 0; nf < 8; ++nf) {
                    MMA(sq[nf], q2h[kk], gB[nf]);
                    MMA(sq[nf], q2h[kk], gBl[nf]);
                    MMA(sq[nf], q2l[kk], gB[nf]);
                }
            }
            #pragma unroll
            for (int kk = 0; kk < 4; ++kk) {
                float a0 = sq[2*kk][0],   a1 = sq[2*kk][1];
                float a2 = sq[2*kk][2],   a3 = sq[2*kk][3];
                float a4 = sq[2*kk+1][0], a5 = sq[2*kk+1][1];
                float a6 = sq[2*kk+1][2], a7 = sq[2*kk+1][3];
                bf h0 = __float2bfloat16(a0), h1 = __float2bfloat16(a1);
                bf h2 = __float2bfloat16(a2), h3 = __float2bfloat16(a3);
                bf h4 = __float2bfloat16(a4), h5 = __float2bfloat16(a5);
                bf h6 = __float2bfloat16(a6), h7 = __float2bfloat16(a7);
                q1h[kk][0] = packbf(__bfloat162float(h0), __bfloat162float(h1));
                q1h[kk][1] = packbf(__bfloat162float(h2), __bfloat162float(h3));
                q1h[kk][2] = packbf(__bfloat162float(h4), __bfloat162float(h5));
                q1h[kk][3] = packbf(__bfloat162float(h6), __bfloat162float(h7));
                q1l[kk][0] = packbf(a0 - __bfloat162float(h0), a1 - __bfloat162float(h1));
                q1l[kk][1] = packbf(a2 - __bfloat162float(h2), a3 - __bfloat162float(h3));
                q1l[kk][2] = packbf(a4 - __bfloat162float(h4), a5 - __bfloat162float(h5));
                q1l[kk][3] = packbf(a6 - __bfloat162float(h6), a7 - __bfloat162float(h7));
            }
            __syncthreads();
        }

        float o1[8][4], o2[8][4];
        #pragma unroll
        for (int i = 0; i < 8; ++i)
            #pragma unroll
            for (int q = 0; q < 4; ++q) { o1[i][q] = 0.f; o2[i][q] = 0.f; }
        float m10 = -INFINITY, m11 = -INFINITY, l10 = 0.f, l11 = 0.f;
        float m20 = -INFINITY, m21 = -INFINITY, l20 = 0.f, l21 = 0.f;

        int nt = (m0 >> 6) + 2;
        int row0 = m0 + wrow + (lane >> 2);
        int diagRow = m0 + wrow;

        kv_prefetch(sbase, 0, 0, pKh, pKl, 3*Cv, pVh, pVl, 3*Cv, tid);
        for (int ct = 0; ct < nt; ++ct) {
            uint32_t bo = (uint32_t)(ct & 1) * 18432u * 2u;
            if (ct + 1 < nt) {
                kv_prefetch(sbase, (uint32_t)((ct + 1) & 1) * 18432u * 2u, (ct + 1) << 6,
                            pKh, pKl, 3*Cv, pVh, pVl, 3*Cv, tid);
                asm volatile("cp.async.wait_group 1;");
            } else {
                asm volatile("cp.async.wait_group 0;");
            }
            __syncthreads();
            int c0 = ct << 6;
            attn_tile<true>(sbase, bo, q1h, q1l, o1, m10, m11, l10, l11, c0, row0, diagRow, scale, lane);
            attn_tile<true>(sbase, bo, q2h, q2l, o2, m20, m21, l20, l21, c0, row0, diagRow, scale, lane);
            __syncthreads();
        }

        float i10 = 1.f / l10, i11 = 1.f / l11, i20 = 1.f / l20, i21 = 1.f / l21;
        float* O1 = gf_ + fC2;
        float* O2 = gf_ + fSV;
        bf* O2h = (bf*)gh_ + oSV; bf* O2l = (bf*)gl_ + oSV;
        #pragma unroll
        for (int nf = 0; nf < 8; ++nf) {
            int col = nf * 8 + (lane & 3) * 2;
            long b0 = co + (long)row0 * Cv + col;
            long b1 = co + (long)(row0 + 8) * Cv + col;
            O1[b0]     = o1[nf][0] * i10;
            O1[b0 + 1] = o1[nf][1] * i10;
            O1[b1]     = o1[nf][2] * i11;
            O1[b1 + 1] = o1[nf][3] * i11;
            float w0 = o2[nf][0] * i20, w1 = o2[nf][1] * i20;
            float w2 = o2[nf][2] * i21, w3 = o2[nf][3] * i21;
            O2[b0] = w0; O2[b0 + 1] = w1; O2[b1] = w2; O2[b1 + 1] = w3;
            bf g0 = __float2bfloat16(w0), g1 = __float2bfloat16(w1);
            bf g2 = __float2bfloat16(w2), g3 = __float2bfloat16(w3);
            *reinterpret_cast<uint32_t*>(O2h + b0) = packbf(__bfloat162float(g0), __bfloat162float(g1));
            *reinterpret_cast<uint32_t*>(O2h + b1) = packbf(__bfloat162float(g2), __bfloat162float(g3));
            *reinterpret_cast<uint32_t*>(O2l + b0) = packbf(w0 - __bfloat162float(g0), w1 - __bfloat162float(g1));
            *reinterpret_cast<uint32_t*>(O2l + b1) = packbf(w2 - __bfloat162float(g2), w3 - __bfloat162float(g3));
        }
    } else {
        // ===== non-causal cross-attention role (cval1) =====
        int z = blockIdx.y - 16, bb = z >> 3, hh = z & 7;
        int m0 = (int)blockIdx.x * 128;
        const bf* pAh = gh_ + oQKVX + (long)bb * Tv * 3 * Cv + (long)hh * Dv;
        const bf* pAl = gl_ + oQKVX + (long)bb * Tv * 3 * Cv + (long)hh * Dv;
        const bf* pKh = gh_ + oQKVY + Cv + (long)bb * Mv * 3 * Cv + (long)hh * Dv;
        const bf* pKl = gl_ + oQKVY + Cv + (long)bb * Mv * 3 * Cv + (long)hh * Dv;
        const bf* pVh = gh_ + oQKVY + 2*Cv + (long)bb * Mv * 3 * Cv + (long)hh * Dv;
        const bf* pVl = gl_ + oQKVY + 2*Cv + (long)bb * Mv * 3 * Cv + (long)hh * Dv;
        long co = (long)bb * Tv * Cv + (long)hh * Dv;

        #pragma unroll
        for (int i = 0; i < 4; ++i) {
            int q = tid + i * 256, r = q >> 3, ch = q & 7;
            long go = (long)(m0 + r) * 3 * Cv + ch * 8;
            *(uint4*)&dsm[r * 72 + ch * 8]        = *(const uint4*)(pAh + go);
            *(uint4*)&dsm[9216 + r * 72 + ch * 8] = *(const uint4*)(pAl + go);
        }
        __syncthreads();
        uint32_t qh[4][4], ql[4][4];
        #pragma unroll
        for (int kk = 0; kk < 4; ++kk) {
            uint32_t off = (uint32_t)((wrow + aRow) * 72 + kk * 16 + aK) * 2;
            LDM4(qh[kk], sbase + off);
            LDM4(ql[kk], sbase + 9216 * 2 + off);
        }
        __syncthreads();

        float o[8][4];
        #pragma unroll
        for (int i = 0; i < 8; ++i)
            #pragma unroll
            for (int q = 0; q < 4; ++q) o[i][q] = 0.f;
        float mr0 = -INFINITY, mr1 = -INFINITY, l0 = 0.f, l1 = 0.f;
        int nt = Mv >> 6;
        int row0 = m0 + wrow + (lane >> 2);

        kv_prefetch(sbase, 0, 0, pKh, pKl, 3*Cv, pVh, pVl, 3*Cv, tid);
        for (int ct = 0; ct < nt; ++ct) {
            uint32_t bo = (uint32_t)(ct & 1) * 18432u * 2u;
            if (ct + 1 < nt) {
                kv_prefetch(sbase, (uint32_t)((ct + 1) & 1) * 18432u * 2u, (ct + 1) << 6,
                            pKh, pKl, 3*Cv, pVh, pVl, 3*Cv, tid);
                asm volatile("cp.async.wait_group 1;");
            } else {
                asm volatile("cp.async.wait_group 0;");
            }
            __syncthreads();
            attn_tile<false>(sbase, bo, qh, ql, o, mr0, mr1, l0, l1,
                             ct << 6, row0, 0, scale, lane);
            __syncthreads();
        }
        float inv0 = 1.f / l0, inv1 = 1.f / l1;
        float* O = gf_ + fCV;
        #pragma unroll
        for (int nf = 0; nf < 8; ++nf) {
            int col = nf * 8 + (lane & 3) * 2;
            long b0 = co + (long)row0 * Cv + col;
            long b1 = co + (long)(row0 + 8) * Cv + col;
            O[b0] = o[nf][0] * inv0; O[b0 + 1] = o[nf][1] * inv0;
            O[b1] = o[nf][2] * inv1; O[b1 + 1] = o[nf][3] * inv1;
        }
    }
}

// ---------- G partials + reduce ----------
__global__ void __launch_bounds__(256) g1_k(const bf* __restrict__ qh, const bf* __restrict__ ql,
                                            float* __restrict__ part)
{
    int z = blockIdx.x, ck = blockIdx.y;
    int b = z >> 3, h = z & 7;
    int m0 = ck * 64;
    long kyo = (long)b * Mv * 3 * Cv + (long)h * Dv + Cv;
    long qyo = (long)b * Mv * 3 * Cv + (long)h * Dv;
    __shared__ float sky[64][65], sqy[64][65];
    int tid = threadIdx.x;
    int d2 = tid & 63, gg = tid >> 6;
    float acc[16];
    #pragma unroll
    for (int i = 0; i < 16; ++i) acc[i] = 0.f;
    #pragma unroll
    for (int i = 0; i < 16; ++i) {
        int q = tid + i * 256;
        int mm = q >> 6, dd = q & 63;
        long ik = kyo + (long)(m0 + mm) * 3 * Cv + dd;
        long iq = qyo + (long)(m0 + mm) * 3 * Cv + dd;
        sky[mm][dd] = __bfloat162float(qh[ik]) + __bfloat162float(ql[ik]);
        sqy[mm][dd] = __bfloat162float(qh[iq]) + __bfloat162float(ql[iq]);
    }
    __syncthreads();
    for (int mm = 0; mm < 64; ++mm) {
        float qv = sqy[mm][d2];
        #pragma unroll
        for (int i = 0; i < 16; ++i)
            acc[i] += sky[mm][gg * 16 + i] * qv;
    }
    long base = ((long)z * 8 + ck) * 4096 + (long)d2 * 64 + gg * 16;
    #pragma unroll
    for (int i = 0; i < 16; ++i) part[base + i] = acc[i];
}
__global__ void __launch_bounds__(256) g2_k(const float* __restrict__ part,
                                            bf* __restrict__ goh, bf* __restrict__ gol)
{
    int z = blockIdx.x, tid = threadIdx.x;
    #pragma unroll
    for (int i = 0; i < 16; ++i) {
        int idx = tid + i * 256;
        float s = 0.f;
        #pragma unroll
        for (int ck = 0; ck < 8; ++ck)
            s += part[((long)z * 8 + ck) * 4096 + idx];
        float v = s * (SCL * SCL);
        bf hh = __float2bfloat16(v);
        long o = (long)z * 4096 + idx;
        goh[o] = hh;
        gol[o] = __float2bfloat16(v - __bfloat162float(hh));
    }
}

// ---------- vectorized split (contiguous) ----------
__global__ void __launch_bounds__(256) split4_k(const float* __restrict__ in, bf* __restrict__ oh,
                                                bf* __restrict__ ol, long n4) {
    long i = (long)blockIdx.x * 256 + threadIdx.x;
    if (i < n4) {
        float4 v = *reinterpret_cast<const float4*>(in + i * 4);
        uint2 hi, lo; split4(v, hi, lo);
        *reinterpret_cast<uint2*>(oh + i * 4) = hi;
        *reinterpret_cast<uint2*>(ol + i * 4) = lo;
    }
}

// ---------- tiled-transpose weight splits (coalesced both sides) --------------
// out[off + nn*Cv + k] = split(in[k*Nd + nn]); tile 32x32.
__global__ void __launch_bounds__(256) splitWt_k(
    const float* __restrict__ w0, const float* __restrict__ w1,
    const float* __restrict__ w2, const float* __restrict__ w3,
    const float* __restrict__ w4, bf* __restrict__ oh, bf* __restrict__ ol)
{
    int job = blockIdx.y;
    const float* src; long off; int Nd;
    switch (job) {
        case 0:  src = w0; off = oWQX; Nd = 3 * Cv; break;
        case 1:  src = w1; off = oWQY; Nd = 3 * Cv; break;
        case 2:  src = w2; off = oWGS; Nd = Cv; break;
        case 3:  src = w3; off = oWGC; Nd = Cv; break;
        default: src = w4; off = oWP;  Nd = Cv; break;
    }
    int ntx = Nd >> 5;                       // tiles along nn
    int ntiles = ntx * (Cv >> 5);
    int tile = blockIdx.x;
    if (tile >= ntiles) return;
    int tn = tile % ntx, tk = tile / ntx;
    int n0 = tn << 5, k0 = tk << 5;

    __shared__ float sm[32][33];
    int c = threadIdx.x & 31, r8 = threadIdx.x >> 5;
    #pragma unroll
    for (int rr = 0; rr < 4; ++rr) {
        int r = r8 + rr * 8;
        sm[r][c] = src[(long)(k0 + r) * Nd + n0 + c];
    }
    __syncthreads();
    #pragma unroll
    for (int rr = 0; rr < 4; ++rr) {
        int a = r8 + rr * 8;
        float v = sm[c][a];
        bf h = __float2bfloat16(v);
        long o = off + (long)(n0 + a) * Cv + k0 + c;
        oh[o] = h;
        ol[o] = __float2bfloat16(v - __bfloat162float(h));
    }
}

// ---------- vectorized add: fCV += fC2, pair out -------------------------------
__global__ void __launch_bounds__(256) add4_k(float* __restrict__ cv, const float* __restrict__ c2,
                                              bf* __restrict__ oh, bf* __restrict__ ol, long n4)
{
    long i = (long)blockIdx.x * 256 + threadIdx.x;
    if (i < n4) {
        float4 a = *reinterpret_cast<const float4*>(cv + i * 4);
        float4 b = *reinterpret_cast<const float4*>(c2 + i * 4);
        float4 v = make_float4(a.x + b.x, a.y + b.y, a.z + b.z, a.w + b.w);
        *reinterpret_cast<float4*>(cv + i * 4) = v;
        uint2 hi, lo; split4(v, hi, lo);
        *reinterpret_cast<uint2*>(oh + i * 4) = hi;
        *reinterpret_cast<uint2*>(ol + i * 4) = lo;
    }
}

// ---------- vectorized gate combine (pair out) ----------
__global__ void __launch_bounds__(256) gate4_k(
    const float* __restrict__ t1, const float* __restrict__ t2,
    const float* __restrict__ bgs, const float* __restrict__ bgc,
    const float* __restrict__ cv, const float* __restrict__ sv,
    bf* __restrict__ oh, bf* __restrict__ ol, long n4)
{
    long i = (long)blockIdx.x * 256 + threadIdx.x;
    if (i < n4) {
        int c = (int)((i * 4) & (Cv - 1));
        float4 a = *reinterpret_cast<const float4*>(t1 + i * 4);
        float4 b = *reinterpret_cast<const float4*>(t2 + i * 4);
        float4 bs = *reinterpret_cast<const float4*>(bgs + c);
        float4 bc = *reinterpret_cast<const float4*>(bgc + c);
        float4 vc = *reinterpret_cast<const float4*>(cv + i * 4);
        float4 vs = *reinterpret_cast<const float4*>(sv + i * 4);
        float4 v;
        v.x = 1.f / (1.f + __expf(-(a.x + bs.x))) * vc.x + 1.f / (1.f + __expf(-(b.x + bc.x))) * vs.x;
        v.y = 1.f / (1.f + __expf(-(a.y + bs.y))) * vc.y + 1.f / (1.f + __expf(-(b.y + bc.y))) * vs.y;
        v.z = 1.f / (1.f + __expf(-(a.z + bs.z))) * vc.z + 1.f / (1.f + __expf(-(b.z + bc.z))) * vs.z;
        v.w = 1.f / (1.f + __expf(-(a.w + bs.w))) * vc.w + 1.f / (1.f + __expf(-(b.w + bc.w))) * vs.w;
        uint2 hi, lo; split4(v, hi, lo);
        *reinterpret_cast<uint2*>(oh + i * 4) = hi;
        *reinterpret_cast<uint2*>(ol + i * 4) = lo;
    }
}

// ------------------------------------------------------------------------------
extern "C" void kernel_launch(void* const* d_in, const int* in_sizes, int n_in,
                              void* d_out, int out_size)
{
    const float* x      = (const float*)d_in[0];
    const float* y      = (const float*)d_in[1];
    const float* Wqkv_x = (const float*)d_in[3];
    const float* bqkv_x = (const float*)d_in[4];
    const float* Wqkv_y = (const float*)d_in[5];
    const float* bqkv_y = (const float*)d_in[6];
    const float* Wgs    = (const float*)d_in[7];
    const float* bgs    = (const float*)d_in[8];
    const float* Wgc    = (const float*)d_in[9];
    const float* bgc    = (const float*)d_in[10];
    const float* Wp     = (const float*)d_in[11];
    const float* bp     = (const float*)d_in[12];
    float* out = (float*)d_out;

    bf *gh, *gl; float* gf;
    cudaGetSymbolAddress((void**)&gh, g_h);
    cudaGetSymbolAddress((void**)&gl, g_l);
    cudaGetSymbolAddress((void**)&gf, g_f);

    const int FASM   = 2 * 18432 * 2;
    const int HGSM128 = 2 * (10240 + 2 * 128 * 40) * 2;
    cudaFuncSetAttribute((const void*)fa_u,  cudaFuncAttributeMaxDynamicSharedMemorySize, FASM);
    cudaFuncSetAttribute((const void*)hg<128,false,true,true>,  cudaFuncAttributeMaxDynamicSharedMemorySize, HGSM128);
    cudaFuncSetAttribute((const void*)hg<128,true,false,false>, cudaFuncAttributeMaxDynamicSharedMemorySize, HGSM128);
    cudaFuncSetAttribute((const void*)hg<128,true,false,true>,  cudaFuncAttributeMaxDynamicSharedMemorySize, HGSM128);

    dim3 blk(256);
    long nTC = nTCe;

    // splits (tiled transpose + vectorized)
    splitWt_k<<<dim3(768, 5), blk>>>(Wqkv_x, Wqkv_y, Wgs, Wgc, Wp, gh, gl);
    split4_k<<<(unsigned)((nTC / 4 + 255) / 256), blk>>>(x, gh + oXB, gl + oXB, nTC / 4);
    split4_k<<<(unsigned)(((long)BBv*Mv*Cv / 4 + 255) / 256), blk>>>(y, gh + oYB, gl + oYB, (long)BBv*Mv*Cv / 4);

    // qkv projections
    hg<128,false,true,true><<<dim3(12,32,1), blk, HGSM128>>>(
        gh+oXB, gl+oXB, Cv, 0,0, gh+oWQX, gl+oWQX, Cv, 0,0,
        nullptr, gh+oQKVX, gl+oQKVX, 3*Cv, 0,0, bqkv_x, Cv, 1, 1.0f);
    hg<128,false,true,true><<<dim3(12,8,1), blk, HGSM128>>>(
        gh+oYB, gl+oYB, Cv, 0,0, gh+oWQY, gl+oWQY, Cv, 0,0,
        nullptr, gh+oQKVY, gl+oQKVY, 3*Cv, 0,0, bqkv_y, Cv, 1, 1.0f);

    // G (split-K)
    g1_k<<<dim3(BHv, 8), blk>>>(gh+oQKVY, gl+oQKVY, gf+fT1);
    g2_k<<<BHv, blk>>>(gf+fT1, gh+oGT, gl+oGT);

    // unified flash: causal dual-Q (cval2->fC2, sval) + non-causal (cval1->fCV)
    fa_u<<<dim3(16,32), blk, FASM>>>(gh, gl, gf, SCL * LOG2E);

    // cval = cval1 + cval2 (in place fCV) + pair
    add4_k<<<(unsigned)((nTC / 4 + 255) / 256), blk>>>(gf+fCV, gf+fC2, gh+oCV, gl+oCV, nTC / 4);

    // gates batched z=2: t1 = sval@Wgs, t2 = cval@Wgc
    hg<128,true,false,false><<<dim3(4,32,2), blk, HGSM128>>>(
        gh+oSV, gl+oSV, Cv, 0, nTC,
        gh+oWGS, gl+oWGS, Cv, 0, (long)Cv*Cv,
        gf+fT1, nullptr, nullptr, Cv, 0, nTC, nullptr, Cv, 2, 1.0f);

    gate4_k<<<(unsigned)((nTC / 4 + 255) / 256), blk>>>(
        gf+fT1, gf+fT2, bgs, bgc, gf+fCV, gf+fSV, gh+oT3, gl+oT3, nTC / 4);

    // out = t3 @ Wp + bp
    hg<128,true,false,true><<<dim3(4,32,1), blk, HGSM128>>>(
        gh+oT3, gl+oT3, Cv, 0,0, gh+oWP, gl+oWP, Cv, 0,0,
        out, nullptr, nullptr, Cv, 0,0, bp, Cv, 1, 1.0f);
}